// round 1
// baseline (speedup 1.0000x reference)
#include <cuda_runtime.h>
#include <cuda_bf16.h>
#include <cstdint>

// Problem constants
#define BB 2
#define NN 2048
#define DIMX 64
#define HH 8
#define DD 512            // per-head dim
#define INNER 4096
#define SCALE 0.125f
#define MASKV -1e9f

// Output layout in d_out (fp32): [out | pre_softmax_attn | attn]
#define OUT_ELEMS   (BB*NN*DIMX)          // 262144
#define PRE_ELEMS   (BB*HH*NN*NN)         // 67108864

// Scratch
__device__ float g_q[BB*HH*NN*DD];
__device__ float g_k[BB*HH*NN*DD];
__device__ float g_v[BB*HH*NN*DD];
__device__ float g_ctx[BB*NN*INNER];
__device__ int   g_mask[BB*NN];

// ---------------------------------------------------------------------------
// Mask prep: detect dtype of the bool mask buffer (int8 / int32 / float32)
// from byte patterns in the first 4096 bytes, then expand to g_mask as int.
// ---------------------------------------------------------------------------
__global__ void prep_mask_kernel(const unsigned char* __restrict__ raw) {
    __shared__ int cnt_f32, cnt_gt1;
    if (threadIdx.x == 0) { cnt_f32 = 0; cnt_gt1 = 0; }
    __syncthreads();
    const unsigned int* u = (const unsigned int*)raw;
    int lf = 0, lg = 0;
    for (int i = threadIdx.x; i < 1024; i += blockDim.x) {  // first 4096 bytes: safe for all dtypes
        unsigned int v = u[i];
        if (v == 0x3f800000u) lf++;
        else if (v > 1u) lg++;
    }
    atomicAdd(&cnt_f32, lf);
    atomicAdd(&cnt_gt1, lg);
    __syncthreads();
    int mode;   // 0 = int32 0/1, 1 = int8 0/1, 2 = float32 0/1
    if (cnt_f32 > 64) mode = 2;
    else if (cnt_gt1 > 64) mode = 1;
    else mode = 0;
    for (int i = threadIdx.x; i < BB*NN; i += blockDim.x) {
        int m;
        if (mode == 2)      m = (((const unsigned int*)raw)[i] != 0u) ? 1 : 0;
        else if (mode == 1) m = raw[i] ? 1 : 0;
        else                m = (((const int*)raw)[i] != 0) ? 1 : 0;
        g_mask[i] = m;
    }
}

// ---------------------------------------------------------------------------
// Projection GEMM: C = x @ W  (M=4096, K=64, Ncols=4096), stored with the
// head split: dst[((b*H + h)*N + n)*D + d]
// Tiles 128x128, BK=16, 256 threads, 8x8 microtile.
// ---------------------------------------------------------------------------
__global__ __launch_bounds__(256) void proj_kernel(
    const float* __restrict__ X, const float* __restrict__ W, float* __restrict__ dst)
{
    __shared__ float As[16][128];
    __shared__ float Bs[16][128];
    const int row0 = blockIdx.y * 128;
    const int col0 = blockIdx.x * 128;
    const int tid = threadIdx.x;
    const int tx = tid & 15, ty = tid >> 4;
    float acc[8][8];
#pragma unroll
    for (int i = 0; i < 8; i++)
#pragma unroll
        for (int j = 0; j < 8; j++) acc[i][j] = 0.f;

    for (int kt = 0; kt < 64; kt += 16) {
        // A: 128 rows x 16 k, lda=64, transpose into As[k][m]
#pragma unroll
        for (int l = 0; l < 2; l++) {
            int f = tid + l * 256;
            int r = f >> 2;
            int c = (f & 3) * 4;
            float4 v = *(const float4*)(X + (size_t)(row0 + r) * 64 + kt + c);
            As[c+0][r] = v.x; As[c+1][r] = v.y; As[c+2][r] = v.z; As[c+3][r] = v.w;
        }
        // B: 16 rows x 128 cols of W (ldb=4096), direct
#pragma unroll
        for (int l = 0; l < 2; l++) {
            int f = tid + l * 256;
            int r = f >> 5;
            int c = (f & 31) * 4;
            float4 v = *(const float4*)(W + (size_t)(kt + r) * 4096 + col0 + c);
            *(float4*)&Bs[r][c] = v;
        }
        __syncthreads();
#pragma unroll
        for (int k = 0; k < 16; k++) {
            float4 a0 = *(const float4*)&As[k][ty*8];
            float4 a1 = *(const float4*)&As[k][ty*8+4];
            float4 b0 = *(const float4*)&Bs[k][tx*8];
            float4 b1 = *(const float4*)&Bs[k][tx*8+4];
            float ar[8] = {a0.x,a0.y,a0.z,a0.w,a1.x,a1.y,a1.z,a1.w};
            float br[8] = {b0.x,b0.y,b0.z,b0.w,b1.x,b1.y,b1.z,b1.w};
#pragma unroll
            for (int i = 0; i < 8; i++)
#pragma unroll
                for (int j = 0; j < 8; j++) acc[i][j] = fmaf(ar[i], br[j], acc[i][j]);
        }
        __syncthreads();
    }
    // store with head-split layout
    const int col = col0 + tx * 8;
    const int h = col >> 9;
    const int d = col & 511;
#pragma unroll
    for (int i = 0; i < 8; i++) {
        int m = row0 + ty * 8 + i;
        int b = m >> 11;
        int n = m & 2047;
        float* p = dst + (((size_t)(b * HH + h) * NN + n) * DD + d);
        *(float4*)p       = make_float4(acc[i][0], acc[i][1], acc[i][2], acc[i][3]);
        *(float4*)(p + 4) = make_float4(acc[i][4], acc[i][5], acc[i][6], acc[i][7]);
    }
}

// ---------------------------------------------------------------------------
// dots = scale * Q @ K^T with mask fill -> pre_softmax_attn
// per (b,h): 2048x2048x512; A,B both row-major K-major (A @ B^T)
// ---------------------------------------------------------------------------
__global__ __launch_bounds__(256) void dots_kernel(
    const float* __restrict__ Q, const float* __restrict__ Kt, float* __restrict__ pre)
{
    const int z = blockIdx.z;              // b*8 + h
    const int b = z >> 3;
    const float* A  = Q  + (size_t)z * NN * DD;
    const float* Bm = Kt + (size_t)z * NN * DD;
    float* C = pre + (size_t)z * NN * NN;
    const int row0 = blockIdx.y * 128;
    const int col0 = blockIdx.x * 128;
    __shared__ float As[16][128];
    __shared__ float Bs[16][128];
    const int tid = threadIdx.x;
    const int tx = tid & 15, ty = tid >> 4;
    float acc[8][8];
#pragma unroll
    for (int i = 0; i < 8; i++)
#pragma unroll
        for (int j = 0; j < 8; j++) acc[i][j] = 0.f;

    for (int kt = 0; kt < DD; kt += 16) {
#pragma unroll
        for (int l = 0; l < 2; l++) {
            int f = tid + l * 256;
            int r = f >> 2;
            int c = (f & 3) * 4;
            float4 v = *(const float4*)(A  + (size_t)(row0 + r) * DD + kt + c);
            As[c+0][r] = v.x; As[c+1][r] = v.y; As[c+2][r] = v.z; As[c+3][r] = v.w;
            float4 w = *(const float4*)(Bm + (size_t)(col0 + r) * DD + kt + c);
            Bs[c+0][r] = w.x; Bs[c+1][r] = w.y; Bs[c+2][r] = w.z; Bs[c+3][r] = w.w;
        }
        __syncthreads();
#pragma unroll
        for (int k = 0; k < 16; k++) {
            float4 a0 = *(const float4*)&As[k][ty*8];
            float4 a1 = *(const float4*)&As[k][ty*8+4];
            float4 b0 = *(const float4*)&Bs[k][tx*8];
            float4 b1 = *(const float4*)&Bs[k][tx*8+4];
            float ar[8] = {a0.x,a0.y,a0.z,a0.w,a1.x,a1.y,a1.z,a1.w};
            float br[8] = {b0.x,b0.y,b0.z,b0.w,b1.x,b1.y,b1.z,b1.w};
#pragma unroll
            for (int i = 0; i < 8; i++)
#pragma unroll
                for (int j = 0; j < 8; j++) acc[i][j] = fmaf(ar[i], br[j], acc[i][j]);
        }
        __syncthreads();
    }
    const int gi0 = row0 + ty * 8;
    const int gj0 = col0 + tx * 8;
    int mrow[8], mcol[8];
#pragma unroll
    for (int i = 0; i < 8; i++) mrow[i] = g_mask[b * NN + gi0 + i];
#pragma unroll
    for (int j = 0; j < 8; j++) mcol[j] = g_mask[b * NN + gj0 + j];
#pragma unroll
    for (int i = 0; i < 8; i++) {
        float v[8];
#pragma unroll
        for (int j = 0; j < 8; j++) {
            float t = acc[i][j] * SCALE;
            v[j] = (mrow[i] & mcol[j]) ? t : MASKV;
        }
        float* p = C + (size_t)(gi0 + i) * NN + gj0;
        *(float4*)p       = make_float4(v[0], v[1], v[2], v[3]);
        *(float4*)(p + 4) = make_float4(v[4], v[5], v[6], v[7]);
    }
}

// ---------------------------------------------------------------------------
// entmax-1.5 per row via Newton on f(tau) = sum (x-tau)_+^2 - 1 (convex,
// decreasing; Newton from tau0 = max-1 is monotone from the left).
// One block (256 thr) per row of 2048; x kept in registers (8/thread).
// ---------------------------------------------------------------------------
__global__ __launch_bounds__(256) void entmax_kernel(
    const float* __restrict__ pre, float* __restrict__ att)
{
    const size_t row = blockIdx.x;
    const float* p = pre + row * NN;
    float* o = att + row * NN;
    const int t = threadIdx.x;
    const int wid = t >> 5, lane = t & 31;
    __shared__ float r1[8], r2[8], bc;

    float x[8];
    float lmax = -3.0e38f;
#pragma unroll
    for (int i = 0; i < 8; i++) {
        x[i] = 0.5f * p[t + i * 256];
        lmax = fmaxf(lmax, x[i]);
    }
#pragma unroll
    for (int off = 16; off; off >>= 1)
        lmax = fmaxf(lmax, __shfl_xor_sync(0xffffffffu, lmax, off));
    if (lane == 0) r1[wid] = lmax;
    __syncthreads();
    if (t == 0) {
        float m = r1[0];
#pragma unroll
        for (int i = 1; i < 8; i++) m = fmaxf(m, r1[i]);
        bc = m;
    }
    __syncthreads();
    const float mx = bc;
#pragma unroll
    for (int i = 0; i < 8; i++) x[i] -= mx;

    float tau = -1.0f;
    for (int it = 0; it < 32; ++it) {
        float s1 = 0.f, s2 = 0.f;
#pragma unroll
        for (int i = 0; i < 8; i++) {
            float d = fmaxf(x[i] - tau, 0.f);
            s1 += d;
            s2 = fmaf(d, d, s2);
        }
#pragma unroll
        for (int off = 16; off; off >>= 1) {
            s1 += __shfl_xor_sync(0xffffffffu, s1, off);
            s2 += __shfl_xor_sync(0xffffffffu, s2, off);
        }
        if (lane == 0) { r1[wid] = s1; r2[wid] = s2; }
        __syncthreads();
        if (t == 0) {
            float S1 = 0.f, S2 = 0.f;
#pragma unroll
            for (int i = 0; i < 8; i++) { S1 += r1[i]; S2 += r2[i]; }
            float step = (S1 > 1e-20f) ? (S2 - 1.0f) / (2.0f * S1) : 0.f;
            bc = tau + step;
        }
        __syncthreads();
        tau = bc;
        __syncthreads();
    }
#pragma unroll
    for (int i = 0; i < 8; i++) {
        float d = fmaxf(x[i] - tau, 0.f);
        o[t + i * 256] = d * d;
    }
}

// ---------------------------------------------------------------------------
// ctx = attn @ V  per (b,h): (2048x2048) @ (2048x512)
// A row-major MxK, B row-major KxN. Output into interleaved ctx[b][n][h*512+d].
// ---------------------------------------------------------------------------
__global__ __launch_bounds__(256) void av_kernel(
    const float* __restrict__ Att, const float* __restrict__ V, float* __restrict__ ctx)
{
    const int z = blockIdx.z;
    const int b = z >> 3;
    const int h = z & 7;
    const float* A  = Att + (size_t)z * NN * NN;
    const float* Bm = V   + (size_t)z * NN * DD;
    const int row0 = blockIdx.y * 128;
    const int col0 = blockIdx.x * 128;
    __shared__ float As[16][128];
    __shared__ float Bs[16][128];
    const int tid = threadIdx.x;
    const int tx = tid & 15, ty = tid >> 4;
    float acc[8][8];
#pragma unroll
    for (int i = 0; i < 8; i++)
#pragma unroll
        for (int j = 0; j < 8; j++) acc[i][j] = 0.f;

    for (int kt = 0; kt < NN; kt += 16) {
#pragma unroll
        for (int l = 0; l < 2; l++) {
            int f = tid + l * 256;
            { // A transpose-load, lda = 2048
                int r = f >> 2;
                int c = (f & 3) * 4;
                float4 v = *(const float4*)(A + (size_t)(row0 + r) * NN + kt + c);
                As[c+0][r] = v.x; As[c+1][r] = v.y; As[c+2][r] = v.z; As[c+3][r] = v.w;
            }
            { // B direct load, ldb = 512
                int r = f >> 5;
                int c = (f & 31) * 4;
                float4 v = *(const float4*)(Bm + (size_t)(kt + r) * DD + col0 + c);
                *(float4*)&Bs[r][c] = v;
            }
        }
        __syncthreads();
#pragma unroll
        for (int k = 0; k < 16; k++) {
            float4 a0 = *(const float4*)&As[k][ty*8];
            float4 a1 = *(const float4*)&As[k][ty*8+4];
            float4 b0 = *(const float4*)&Bs[k][tx*8];
            float4 b1 = *(const float4*)&Bs[k][tx*8+4];
            float ar[8] = {a0.x,a0.y,a0.z,a0.w,a1.x,a1.y,a1.z,a1.w};
            float br[8] = {b0.x,b0.y,b0.z,b0.w,b1.x,b1.y,b1.z,b1.w};
#pragma unroll
            for (int i = 0; i < 8; i++)
#pragma unroll
                for (int j = 0; j < 8; j++) acc[i][j] = fmaf(ar[i], br[j], acc[i][j]);
        }
        __syncthreads();
    }
    const int gi0 = row0 + ty * 8;
    const int gj0 = col0 + tx * 8;
#pragma unroll
    for (int i = 0; i < 8; i++) {
        float* p = ctx + ((size_t)(b * NN + gi0 + i) * INNER + (size_t)h * DD + gj0);
        *(float4*)p       = make_float4(acc[i][0], acc[i][1], acc[i][2], acc[i][3]);
        *(float4*)(p + 4) = make_float4(acc[i][4], acc[i][5], acc[i][6], acc[i][7]);
    }
}

// ---------------------------------------------------------------------------
// out = ctx @ Wo + bo  (M=4096, K=4096, Ncols=64)
// BM=32, BN=64, BK=32, 256 threads, 2x4 microtile -> 128 blocks.
// ---------------------------------------------------------------------------
__global__ __launch_bounds__(256) void final_kernel(
    const float* __restrict__ C, const float* __restrict__ Wo,
    const float* __restrict__ bo, float* __restrict__ out)
{
    __shared__ float As[32][32];
    __shared__ float Ws[32][64];
    const int row0 = blockIdx.x * 32;
    const int tid = threadIdx.x;
    const int tx = tid & 15, ty = tid >> 4;
    float acc[2][4] = {{0.f,0.f,0.f,0.f},{0.f,0.f,0.f,0.f}};

    for (int kt = 0; kt < INNER; kt += 32) {
        { // A: 32 rows x 32 k, lda=4096, transpose
            int r = tid >> 3;
            int c = (tid & 7) * 4;
            float4 v = *(const float4*)(C + (size_t)(row0 + r) * INNER + kt + c);
            As[c+0][r] = v.x; As[c+1][r] = v.y; As[c+2][r] = v.z; As[c+3][r] = v.w;
        }
#pragma unroll
        for (int l = 0; l < 2; l++) { // Wo: 32 rows x 64 cols, direct
            int f = tid + l * 256;
            int r = f >> 4;
            int c = (f & 15) * 4;
            float4 v = *(const float4*)(Wo + (size_t)(kt + r) * 64 + c);
            *(float4*)&Ws[r][c] = v;
        }
        __syncthreads();
#pragma unroll
        for (int k = 0; k < 32; k++) {
            float a0 = As[k][ty*2 + 0];
            float a1 = As[k][ty*2 + 1];
            float4 w = *(const float4*)&Ws[k][tx*4];
            float wr[4] = {w.x, w.y, w.z, w.w};
#pragma unroll
            for (int j = 0; j < 4; j++) {
                acc[0][j] = fmaf(a0, wr[j], acc[0][j]);
                acc[1][j] = fmaf(a1, wr[j], acc[1][j]);
            }
        }
        __syncthreads();
    }
    float4 bias = *(const float4*)(bo + tx * 4);
    float br[4] = {bias.x, bias.y, bias.z, bias.w};
#pragma unroll
    for (int i = 0; i < 2; i++) {
        int m = row0 + ty * 2 + i;
        float* p = out + (size_t)m * 64 + tx * 4;
        *(float4*)p = make_float4(acc[i][0] + br[0], acc[i][1] + br[1],
                                  acc[i][2] + br[2], acc[i][3] + br[3]);
    }
}

// ---------------------------------------------------------------------------
extern "C" void kernel_launch(void* const* d_in, const int* in_sizes, int n_in,
                              void* d_out, int out_size)
{
    const float* x   = (const float*)d_in[0];
    const unsigned char* mask_raw = (const unsigned char*)d_in[1];
    const float* Wq  = (const float*)d_in[2];
    const float* Wk  = (const float*)d_in[3];
    const float* Wv  = (const float*)d_in[4];
    const float* Wo  = (const float*)d_in[5];
    const float* bo  = (const float*)d_in[6];

    float* out = (float*)d_out;
    float* pre = out + OUT_ELEMS;
    float* att = pre + PRE_ELEMS;

    float *pq, *pk, *pv, *pctx;
    cudaGetSymbolAddress((void**)&pq,  g_q);
    cudaGetSymbolAddress((void**)&pk,  g_k);
    cudaGetSymbolAddress((void**)&pv,  g_v);
    cudaGetSymbolAddress((void**)&pctx, g_ctx);

    prep_mask_kernel<<<1, 256>>>(mask_raw);

    dim3 pg(32, 32);
    proj_kernel<<<pg, 256>>>(x, Wq, pq);
    proj_kernel<<<pg, 256>>>(x, Wk, pk);
    proj_kernel<<<pg, 256>>>(x, Wv, pv);

    dots_kernel<<<dim3(16, 16, 16), 256>>>(pq, pk, pre);

    entmax_kernel<<<BB * HH * NN, 256>>>(pre, att);

    av_kernel<<<dim3(4, 16, 16), 256>>>(att, pv, pctx);

    final_kernel<<<128, 256>>>(pctx, Wo, bo, out);
}

// round 3
// speedup vs baseline: 1.9451x; 1.9451x over previous
#include <cuda_runtime.h>
#include <cuda_bf16.h>
#include <cstdint>

// Problem constants
#define BB 2
#define NN 2048
#define DIMX 64
#define HH 8
#define DD 512            // per-head dim
#define INNER 4096
#define SCALE 0.125f
#define MASKV -1e9f

// Output layout in d_out (fp32): [out | pre_softmax_attn | attn]
#define OUT_ELEMS   (BB*NN*DIMX)          // 262144
#define PRE_ELEMS   (BB*HH*NN*NN)         // 67108864

// Scratch
__device__ float g_q[BB*HH*NN*DD];
__device__ float g_k[BB*HH*NN*DD];
__device__ float g_v[BB*HH*NN*DD];
__device__ float g_vt[BB*HH*DD*NN];
__device__ float g_ctx[BB*NN*INNER];
__device__ int   g_mask[BB*NN];

// ===========================================================================
// Helpers (baseline PTX only: ldmatrix sm_75+, mma.sync bf16 sm_80+)
// ===========================================================================
__device__ __forceinline__ uint32_t smem_u32(const void* p) {
    uint32_t r;
    asm("{ .reg .u64 t; cvta.to.shared.u64 t, %1; cvt.u32.u64 %0, t; }" : "=r"(r) : "l"(p));
    return r;
}

__device__ __forceinline__ void ldsm_x4(uint32_t* r, uint32_t addr) {
    asm volatile("ldmatrix.sync.aligned.m8n8.x4.shared.b16 {%0,%1,%2,%3}, [%4];"
        : "=r"(r[0]), "=r"(r[1]), "=r"(r[2]), "=r"(r[3]) : "r"(addr));
}
__device__ __forceinline__ void ldsm_x2(uint32_t* r, uint32_t addr) {
    asm volatile("ldmatrix.sync.aligned.m8n8.x2.shared.b16 {%0,%1}, [%2];"
        : "=r"(r[0]), "=r"(r[1]) : "r"(addr));
}
__device__ __forceinline__ void mma_bf16(float* c, const uint32_t* a, const uint32_t* b) {
    asm volatile("mma.sync.aligned.m16n8k16.row.col.f32.bf16.bf16.f32 "
        "{%0,%1,%2,%3}, {%4,%5,%6,%7}, {%8,%9}, {%0,%1,%2,%3};"
        : "+f"(c[0]), "+f"(c[1]), "+f"(c[2]), "+f"(c[3])
        : "r"(a[0]), "r"(a[1]), "r"(a[2]), "r"(a[3]), "r"(b[0]), "r"(b[1]));
}

// swizzled byte offset inside a [rows][32] bf16 tile stored as 64B rows
// (two rows per 128B swizzle atom; XOR bits 4-6 with atom row & 7)
__device__ __forceinline__ uint32_t swz(uint32_t r, uint32_t kb) {
    uint32_t off = r * 64u + kb;
    return off ^ ((off >> 3) & 0x70u);
}

// ===========================================================================
// Mask prep (dtype detect)
// ===========================================================================
__global__ void prep_mask_kernel(const unsigned char* __restrict__ raw) {
    __shared__ int cnt_f32, cnt_gt1;
    if (threadIdx.x == 0) { cnt_f32 = 0; cnt_gt1 = 0; }
    __syncthreads();
    const unsigned int* u = (const unsigned int*)raw;
    int lf = 0, lg = 0;
    for (int i = threadIdx.x; i < 1024; i += blockDim.x) {
        unsigned int v = u[i];
        if (v == 0x3f800000u) lf++;
        else if (v > 1u) lg++;
    }
    atomicAdd(&cnt_f32, lf);
    atomicAdd(&cnt_gt1, lg);
    __syncthreads();
    int mode;
    if (cnt_f32 > 64) mode = 2;
    else if (cnt_gt1 > 64) mode = 1;
    else mode = 0;
    for (int i = threadIdx.x; i < BB*NN; i += blockDim.x) {
        int m;
        if (mode == 2)      m = (((const unsigned int*)raw)[i] != 0u) ? 1 : 0;
        else if (mode == 1) m = raw[i] ? 1 : 0;
        else                m = (((const int*)raw)[i] != 0) ? 1 : 0;
        g_mask[i] = m;
    }
}

// ===========================================================================
// Projection GEMM (SIMT fp32): C = x @ W, head-split store
// ===========================================================================
__global__ __launch_bounds__(256) void proj_kernel(
    const float* __restrict__ X, const float* __restrict__ W, float* __restrict__ dst)
{
    __shared__ float As[16][128];
    __shared__ float Bs[16][128];
    const int row0 = blockIdx.y * 128;
    const int col0 = blockIdx.x * 128;
    const int tid = threadIdx.x;
    const int tx = tid & 15, ty = tid >> 4;
    float acc[8][8];
#pragma unroll
    for (int i = 0; i < 8; i++)
#pragma unroll
        for (int j = 0; j < 8; j++) acc[i][j] = 0.f;

    for (int kt = 0; kt < 64; kt += 16) {
#pragma unroll
        for (int l = 0; l < 2; l++) {
            int f = tid + l * 256;
            int r = f >> 2;
            int c = (f & 3) * 4;
            float4 v = *(const float4*)(X + (size_t)(row0 + r) * 64 + kt + c);
            As[c+0][r] = v.x; As[c+1][r] = v.y; As[c+2][r] = v.z; As[c+3][r] = v.w;
        }
#pragma unroll
        for (int l = 0; l < 2; l++) {
            int f = tid + l * 256;
            int r = f >> 5;
            int c = (f & 31) * 4;
            float4 v = *(const float4*)(W + (size_t)(kt + r) * 4096 + col0 + c);
            *(float4*)&Bs[r][c] = v;
        }
        __syncthreads();
#pragma unroll
        for (int k = 0; k < 16; k++) {
            float4 a0 = *(const float4*)&As[k][ty*8];
            float4 a1 = *(const float4*)&As[k][ty*8+4];
            float4 b0 = *(const float4*)&Bs[k][tx*8];
            float4 b1 = *(const float4*)&Bs[k][tx*8+4];
            float ar[8] = {a0.x,a0.y,a0.z,a0.w,a1.x,a1.y,a1.z,a1.w};
            float br[8] = {b0.x,b0.y,b0.z,b0.w,b1.x,b1.y,b1.z,b1.w};
#pragma unroll
            for (int i = 0; i < 8; i++)
#pragma unroll
                for (int j = 0; j < 8; j++) acc[i][j] = fmaf(ar[i], br[j], acc[i][j]);
        }
        __syncthreads();
    }
    const int col = col0 + tx * 8;
    const int h = col >> 9;
    const int d = col & 511;
#pragma unroll
    for (int i = 0; i < 8; i++) {
        int m = row0 + ty * 8 + i;
        int b = m >> 11;
        int n = m & 2047;
        float* p = dst + (((size_t)(b * HH + h) * NN + n) * DD + d);
        *(float4*)p       = make_float4(acc[i][0], acc[i][1], acc[i][2], acc[i][3]);
        *(float4*)(p + 4) = make_float4(acc[i][4], acc[i][5], acc[i][6], acc[i][7]);
    }
}

// ===========================================================================
// V transpose: v[z][n][d] -> vt[z][d][n], 32x32 tiles
// ===========================================================================
__global__ void transpose_v_kernel(const float* __restrict__ v, float* __restrict__ vt) {
    __shared__ float t[32][33];
    const int z = blockIdx.z;
    const int n0 = blockIdx.x * 32, d0 = blockIdx.y * 32;
    const float* src = v + (size_t)z * NN * DD;
    float* dst = vt + (size_t)z * DD * NN;
    const int tx = threadIdx.x, ty = threadIdx.y;
#pragma unroll
    for (int i = 0; i < 4; i++)
        t[ty + i*8][tx] = src[(size_t)(n0 + ty + i*8) * DD + d0 + tx];
    __syncthreads();
#pragma unroll
    for (int i = 0; i < 4; i++)
        dst[(size_t)(d0 + ty + i*8) * NN + n0 + tx] = t[tx][ty + i*8];
}

// ===========================================================================
// hi/lo split of float4 -> two uint2 (4 bf16 each)
// ===========================================================================
__device__ __forceinline__ void split4(float4 v, uint2& hh, uint2& ll) {
    __nv_bfloat162 h01 = __floats2bfloat162_rn(v.x, v.y);
    __nv_bfloat162 h23 = __floats2bfloat162_rn(v.z, v.w);
    float2 f01 = __bfloat1622float2(h01);
    float2 f23 = __bfloat1622float2(h23);
    __nv_bfloat162 l01 = __floats2bfloat162_rn(v.x - f01.x, v.y - f01.y);
    __nv_bfloat162 l23 = __floats2bfloat162_rn(v.z - f23.x, v.w - f23.y);
    hh.x = *(uint32_t*)&h01; hh.y = *(uint32_t*)&h23;
    ll.x = *(uint32_t*)&l01; ll.y = *(uint32_t*)&l23;
}

// ===========================================================================
// mma.sync bf16 split-precision batched GEMM.
// C_tile[128x64] = A[rows 128, KLD] @ B[cols 64 rows of KLD]^T   (both K-major)
// MODE 0: dots epilogue (scale+mask -> pre, per-z N x N)
// MODE 1: av epilogue (-> ctx interleaved [b][n][h*512+d])
// SMEM per buffer: Ahi 8K | Alo 8K | Bhi 4K | Blo 4K = 24K, double buffered.
// ===========================================================================
#define MG_SMEM (49152 + 256)

template<int KLD, int MODE>
__global__ __launch_bounds__(256, 2) void mma_gemm(
    const float* __restrict__ Aall, const float* __restrict__ Ball, float* __restrict__ Out)
{
    extern __shared__ char sm[];
    const uint32_t sbase = smem_u32(sm);
    int* cmask = (int*)(sm + 49152);

    const int tid = threadIdx.x;
    const int wid = tid >> 5, lane = tid & 31;
    const int wm = wid >> 1, wn = wid & 1;        // 4 x 2 warps, 32x32 tiles
    const int z = blockIdx.z, b = z >> 3, h = z & 7;
    const int row0 = blockIdx.y * 128, col0 = blockIdx.x * 64;
    const float* A  = Aall + (size_t)z * NN * KLD;
    const float* Bm = Ball + (size_t)z * (MODE == 0 ? NN : DD) * KLD;

    if (MODE == 0 && tid < 64) cmask[tid] = g_mask[b * NN + col0 + tid];

    // per-thread load coords: A 128x32 floats -> 4 float4/thr; B 64x32 -> 2
    const int ar = tid >> 1;                 // 0..127   (tid*2+i -> r = idx>>3 with idx=tid+i*256? )
    // use idx = tid + i*256: r = idx >> 3, c4 = idx & 7
    float acc[2][4][4];
#pragma unroll
    for (int mf = 0; mf < 2; mf++)
#pragma unroll
        for (int nf = 0; nf < 4; nf++)
#pragma unroll
            for (int r = 0; r < 4; r++) acc[mf][nf][r] = 0.f;

    float4 ra[4], rb[2];
    const int NC = KLD / 32;

    // prologue: chunk 0
#pragma unroll
    for (int i = 0; i < 4; i++) {
        int idx = tid + i * 256;
        ra[i] = *(const float4*)(A + (size_t)(row0 + (idx >> 3)) * KLD + (idx & 7) * 4);
    }
#pragma unroll
    for (int i = 0; i < 2; i++) {
        int idx = tid + i * 256;
        rb[i] = *(const float4*)(Bm + (size_t)(col0 + (idx >> 3)) * KLD + (idx & 7) * 4);
    }
    {
        const uint32_t AH = sbase, AL = sbase + 8192, BH = sbase + 16384, BL = sbase + 20480;
#pragma unroll
        for (int i = 0; i < 4; i++) {
            int idx = tid + i * 256;
            uint32_t off = swz(idx >> 3, (idx & 7) * 8);
            uint2 hh, ll; split4(ra[i], hh, ll);
            *(uint2*)(sm + (AH - sbase) + off) = hh;
            *(uint2*)(sm + (AL - sbase) + off) = ll;
        }
#pragma unroll
        for (int i = 0; i < 2; i++) {
            int idx = tid + i * 256;
            uint32_t off = swz(idx >> 3, (idx & 7) * 8);
            uint2 hh, ll; split4(rb[i], hh, ll);
            *(uint2*)(sm + (BH - sbase) + off) = hh;
            *(uint2*)(sm + (BL - sbase) + off) = ll;
        }
    }
    __syncthreads();

    // ldmatrix lane addressing (within-tile, byte offsets)
    const uint32_t a_row = (uint32_t)(wm * 32) + (lane & 15);
    const uint32_t a_kb  = ((lane >> 4) & 1) * 16;
    const uint32_t b_row = (uint32_t)(wn * 32) + (lane & 7);
    const uint32_t b_kb  = ((lane >> 3) & 1) * 16;

    for (int ch = 0; ch < NC; ++ch) {
        const int nxt = ch + 1;
        if (nxt < NC) {
            const int kt = nxt * 32;
#pragma unroll
            for (int i = 0; i < 4; i++) {
                int idx = tid + i * 256;
                ra[i] = *(const float4*)(A + (size_t)(row0 + (idx >> 3)) * KLD + kt + (idx & 7) * 4);
            }
#pragma unroll
            for (int i = 0; i < 2; i++) {
                int idx = tid + i * 256;
                rb[i] = *(const float4*)(Bm + (size_t)(col0 + (idx >> 3)) * KLD + kt + (idx & 7) * 4);
            }
        }
        // MMA over buffer ch&1
        {
            const uint32_t bufo = (uint32_t)(ch & 1) * 24576u;
            const uint32_t AH = sbase + bufo, AL = AH + 8192;
            const uint32_t BH = sbase + bufo + 16384, BL = BH + 4096;
#pragma unroll
            for (int ks = 0; ks < 2; ks++) {
                const uint32_t kb0 = (uint32_t)ks * 32;
                uint32_t bhf[4][2], blf[4][2];
#pragma unroll
                for (int nf = 0; nf < 4; nf++) {
                    uint32_t o = swz(b_row + nf * 8, kb0 + b_kb);
                    ldsm_x2(bhf[nf], BH + o);
                    ldsm_x2(blf[nf], BL + o);
                }
#pragma unroll
                for (int mf = 0; mf < 2; mf++) {
                    uint32_t o = swz(a_row + mf * 16, kb0 + a_kb);
                    uint32_t ahf[4], alf[4];
                    ldsm_x4(ahf, AH + o);
                    ldsm_x4(alf, AL + o);
#pragma unroll
                    for (int nf = 0; nf < 4; nf++) {
                        mma_bf16(acc[mf][nf], ahf, bhf[nf]);
                        mma_bf16(acc[mf][nf], ahf, blf[nf]);
                        mma_bf16(acc[mf][nf], alf, bhf[nf]);
                    }
                }
            }
        }
        if (nxt < NC) {
            const uint32_t bufo = (uint32_t)(nxt & 1) * 24576u;
            char* base = sm + bufo;
#pragma unroll
            for (int i = 0; i < 4; i++) {
                int idx = tid + i * 256;
                uint32_t off = swz(idx >> 3, (idx & 7) * 8);
                uint2 hh, ll; split4(ra[i], hh, ll);
                *(uint2*)(base + off) = hh;
                *(uint2*)(base + 8192 + off) = ll;
            }
#pragma unroll
            for (int i = 0; i < 2; i++) {
                int idx = tid + i * 256;
                uint32_t off = swz(idx >> 3, (idx & 7) * 8);
                uint2 hh, ll; split4(rb[i], hh, ll);
                *(uint2*)(base + 16384 + off) = hh;
                *(uint2*)(base + 20480 + off) = ll;
            }
        }
        __syncthreads();
    }

    // epilogue
    const int r_lo = row0 + wm * 32 + (lane >> 2);
    const int c_lo = col0 + wn * 32 + (lane & 3) * 2;
    if (MODE == 0) {
        const int rm0 = g_mask[b * NN + (r_lo & (NN - 1))];
        float* outz = Out + (size_t)z * NN * NN;
#pragma unroll
        for (int mf = 0; mf < 2; mf++) {
            int rg0 = r_lo + mf * 16;
            int m0 = g_mask[b * NN + rg0];
            int m1 = g_mask[b * NN + rg0 + 8];
#pragma unroll
            for (int nf = 0; nf < 4; nf++) {
                int cg = c_lo + nf * 8 - col0;   // index into cmask
                int cmA = cmask[cg], cmB = cmask[cg + 1];
                float2 v0, v1;
                v0.x = (m0 && cmA) ? acc[mf][nf][0] * SCALE : MASKV;
                v0.y = (m0 && cmB) ? acc[mf][nf][1] * SCALE : MASKV;
                v1.x = (m1 && cmA) ? acc[mf][nf][2] * SCALE : MASKV;
                v1.y = (m1 && cmB) ? acc[mf][nf][3] * SCALE : MASKV;
                *(float2*)(outz + (size_t)rg0 * NN + col0 + cg)       = v0;
                *(float2*)(outz + (size_t)(rg0 + 8) * NN + col0 + cg) = v1;
            }
        }
        (void)rm0;
    } else {
#pragma unroll
        for (int mf = 0; mf < 2; mf++) {
            int rg0 = r_lo + mf * 16;
            float* p0 = Out + ((size_t)(b * NN + rg0)) * INNER + (size_t)h * DD;
            float* p1 = Out + ((size_t)(b * NN + rg0 + 8)) * INNER + (size_t)h * DD;
#pragma unroll
            for (int nf = 0; nf < 4; nf++) {
                int cg = c_lo + nf * 8;
                *(float2*)(p0 + cg) = make_float2(acc[mf][nf][0], acc[mf][nf][1]);
                *(float2*)(p1 + cg) = make_float2(acc[mf][nf][2], acc[mf][nf][3]);
            }
        }
    }
}

// ===========================================================================
// entmax-1.5 per row via Newton on f(tau) = sum (x-tau)_+^2 - 1
// ===========================================================================
__global__ __launch_bounds__(256) void entmax_kernel(
    const float* __restrict__ pre, float* __restrict__ att)
{
    const size_t row = blockIdx.x;
    const float* p = pre + row * NN;
    float* o = att + row * NN;
    const int t = threadIdx.x;
    const int wid = t >> 5, lane = t & 31;
    __shared__ float r1[8], r2[8], bc;

    float x[8];
    float lmax = -3.0e38f;
#pragma unroll
    for (int i = 0; i < 8; i++) {
        x[i] = 0.5f * p[t + i * 256];
        lmax = fmaxf(lmax, x[i]);
    }
#pragma unroll
    for (int off = 16; off; off >>= 1)
        lmax = fmaxf(lmax, __shfl_xor_sync(0xffffffffu, lmax, off));
    if (lane == 0) r1[wid] = lmax;
    __syncthreads();
    if (t == 0) {
        float m = r1[0];
#pragma unroll
        for (int i = 1; i < 8; i++) m = fmaxf(m, r1[i]);
        bc = m;
    }
    __syncthreads();
    const float mx = bc;
#pragma unroll
    for (int i = 0; i < 8; i++) x[i] -= mx;

    float tau = -1.0f;
    for (int it = 0; it < 32; ++it) {
        float s1 = 0.f, s2 = 0.f;
#pragma unroll
        for (int i = 0; i < 8; i++) {
            float d = fmaxf(x[i] - tau, 0.f);
            s1 += d;
            s2 = fmaf(d, d, s2);
        }
#pragma unroll
        for (int off = 16; off; off >>= 1) {
            s1 += __shfl_xor_sync(0xffffffffu, s1, off);
            s2 += __shfl_xor_sync(0xffffffffu, s2, off);
        }
        if (lane == 0) { r1[wid] = s1; r2[wid] = s2; }
        __syncthreads();
        if (t == 0) {
            float S1 = 0.f, S2 = 0.f;
#pragma unroll
            for (int i = 0; i < 8; i++) { S1 += r1[i]; S2 += r2[i]; }
            float step = (S1 > 1e-20f) ? (S2 - 1.0f) / (2.0f * S1) : 0.f;
            bc = tau + step;
        }
        __syncthreads();
        tau = bc;
        __syncthreads();
    }
#pragma unroll
    for (int i = 0; i < 8; i++) {
        float d = fmaxf(x[i] - tau, 0.f);
        o[t + i * 256] = d * d;
    }
}

// ===========================================================================
// out = ctx @ Wo + bo
// ===========================================================================
__global__ __launch_bounds__(256) void final_kernel(
    const float* __restrict__ C, const float* __restrict__ Wo,
    const float* __restrict__ bo, float* __restrict__ out)
{
    __shared__ float As[32][32];
    __shared__ float Ws[32][64];
    const int row0 = blockIdx.x * 32;
    const int tid = threadIdx.x;
    const int tx = tid & 15, ty = tid >> 4;
    float acc[2][4] = {{0.f,0.f,0.f,0.f},{0.f,0.f,0.f,0.f}};

    for (int kt = 0; kt < INNER; kt += 32) {
        {
            int r = tid >> 3;
            int c = (tid & 7) * 4;
            float4 v = *(const float4*)(C + (size_t)(row0 + r) * INNER + kt + c);
            As[c+0][r] = v.x; As[c+1][r] = v.y; As[c+2][r] = v.z; As[c+3][r] = v.w;
        }
#pragma unroll
        for (int l = 0; l < 2; l++) {
            int f = tid + l * 256;
            int r = f >> 4;
            int c = (f & 15) * 4;
            float4 v = *(const float4*)(Wo + (size_t)(kt + r) * 64 + c);
            *(float4*)&Ws[r][c] = v;
        }
        __syncthreads();
#pragma unroll
        for (int k = 0; k < 32; k++) {
            float a0 = As[k][ty*2 + 0];
            float a1 = As[k][ty*2 + 1];
            float4 w = *(const float4*)&Ws[k][tx*4];
            float wr[4] = {w.x, w.y, w.z, w.w};
#pragma unroll
            for (int j = 0; j < 4; j++) {
                acc[0][j] = fmaf(a0, wr[j], acc[0][j]);
                acc[1][j] = fmaf(a1, wr[j], acc[1][j]);
            }
        }
        __syncthreads();
    }
    float4 bias = *(const float4*)(bo + tx * 4);
    float br[4] = {bias.x, bias.y, bias.z, bias.w};
#pragma unroll
    for (int i = 0; i < 2; i++) {
        int m = row0 + ty * 2 + i;
        float* p = out + (size_t)m * 64 + tx * 4;
        *(float4*)p = make_float4(acc[i][0] + br[0], acc[i][1] + br[1],
                                  acc[i][2] + br[2], acc[i][3] + br[3]);
    }
}

// ===========================================================================
extern "C" void kernel_launch(void* const* d_in, const int* in_sizes, int n_in,
                              void* d_out, int out_size)
{
    const float* x   = (const float*)d_in[0];
    const unsigned char* mask_raw = (const unsigned char*)d_in[1];
    const float* Wq  = (const float*)d_in[2];
    const float* Wk  = (const float*)d_in[3];
    const float* Wv  = (const float*)d_in[4];
    const float* Wo  = (const float*)d_in[5];
    const float* bo  = (const float*)d_in[6];

    float* out = (float*)d_out;
    float* pre = out + OUT_ELEMS;
    float* att = pre + PRE_ELEMS;

    float *pq, *pk, *pv, *pvt, *pctx;
    cudaGetSymbolAddress((void**)&pq,  g_q);
    cudaGetSymbolAddress((void**)&pk,  g_k);
    cudaGetSymbolAddress((void**)&pv,  g_v);
    cudaGetSymbolAddress((void**)&pvt, g_vt);
    cudaGetSymbolAddress((void**)&pctx, g_ctx);

    static int smem_set = 0;
    if (!smem_set) {
        cudaFuncSetAttribute(mma_gemm<512, 0>,
                             cudaFuncAttributeMaxDynamicSharedMemorySize, MG_SMEM);
        cudaFuncSetAttribute(mma_gemm<2048, 1>,
                             cudaFuncAttributeMaxDynamicSharedMemorySize, MG_SMEM);
        smem_set = 1;
    }

    prep_mask_kernel<<<1, 256>>>(mask_raw);

    dim3 pg(32, 32);
    proj_kernel<<<pg, 256>>>(x, Wq, pq);
    proj_kernel<<<pg, 256>>>(x, Wk, pk);
    proj_kernel<<<pg, 256>>>(x, Wv, pv);

    transpose_v_kernel<<<dim3(64, 16, 16), dim3(32, 8)>>>(pv, pvt);

    // dots = scale*Q@K^T (+mask) -> pre
    mma_gemm<512, 0><<<dim3(32, 16, 16), 256, MG_SMEM>>>(pq, pk, pre);

    entmax_kernel<<<BB * HH * NN, 256>>>(pre, att);

    // ctx = attn @ V
    mma_gemm<2048, 1><<<dim3(8, 16, 16), 256, MG_SMEM>>>(att, pvt, pctx);

    final_kernel<<<128, 256>>>(pctx, Wo, bo, out);
}

// round 4
// speedup vs baseline: 2.4157x; 1.2419x over previous
#include <cuda_runtime.h>
#include <cuda_bf16.h>
#include <cstdint>

// Problem constants
#define BB 2
#define NN 2048
#define DIMX 64
#define HH 8
#define DD 512            // per-head dim
#define INNER 4096
#define SCALE 0.125f
#define MASKV -1e9f

// Output layout in d_out (fp32): [out | pre_softmax_attn | attn]
#define OUT_ELEMS   (BB*NN*DIMX)          // 262144
#define PRE_ELEMS   (BB*HH*NN*NN)         // 67108864

// Scratch
__device__ float g_q[BB*HH*NN*DD];
__device__ float g_k[BB*HH*NN*DD];
__device__ float g_v[BB*HH*NN*DD];
__device__ float g_vt[BB*HH*DD*NN];
__device__ float g_ctx[BB*NN*INNER];
__device__ int   g_mask[BB*NN];

// ===========================================================================
// Helpers (baseline PTX only: ldmatrix sm_75+, mma.sync bf16 sm_80+)
// ===========================================================================
__device__ __forceinline__ uint32_t smem_u32(const void* p) {
    uint32_t r;
    asm("{ .reg .u64 t; cvta.to.shared.u64 t, %1; cvt.u32.u64 %0, t; }" : "=r"(r) : "l"(p));
    return r;
}
__device__ __forceinline__ void ldsm_x4(uint32_t* r, uint32_t addr) {
    asm volatile("ldmatrix.sync.aligned.m8n8.x4.shared.b16 {%0,%1,%2,%3}, [%4];"
        : "=r"(r[0]), "=r"(r[1]), "=r"(r[2]), "=r"(r[3]) : "r"(addr));
}
__device__ __forceinline__ void mma_bf16(float* c, const uint32_t* a, const uint32_t* b) {
    asm volatile("mma.sync.aligned.m16n8k16.row.col.f32.bf16.bf16.f32 "
        "{%0,%1,%2,%3}, {%4,%5,%6,%7}, {%8,%9}, {%0,%1,%2,%3};"
        : "+f"(c[0]), "+f"(c[1]), "+f"(c[2]), "+f"(c[3])
        : "r"(a[0]), "r"(a[1]), "r"(a[2]), "r"(a[3]), "r"(b[0]), "r"(b[1]));
}

// swizzled byte offset inside a [rows][32] bf16 tile stored as 64B rows
__device__ __forceinline__ uint32_t swz(uint32_t r, uint32_t kb) {
    uint32_t off = r * 64u + kb;
    return off ^ ((off >> 3) & 0x70u);
}

// ===========================================================================
// Mask prep (dtype detect)
// ===========================================================================
__global__ void prep_mask_kernel(const unsigned char* __restrict__ raw) {
    __shared__ int cnt_f32, cnt_gt1;
    if (threadIdx.x == 0) { cnt_f32 = 0; cnt_gt1 = 0; }
    __syncthreads();
    const unsigned int* u = (const unsigned int*)raw;
    int lf = 0, lg = 0;
    for (int i = threadIdx.x; i < 1024; i += blockDim.x) {
        unsigned int v = u[i];
        if (v == 0x3f800000u) lf++;
        else if (v > 1u) lg++;
    }
    atomicAdd(&cnt_f32, lf);
    atomicAdd(&cnt_gt1, lg);
    __syncthreads();
    int mode;
    if (cnt_f32 > 64) mode = 2;
    else if (cnt_gt1 > 64) mode = 1;
    else mode = 0;
    for (int i = threadIdx.x; i < BB*NN; i += blockDim.x) {
        int m;
        if (mode == 2)      m = (((const unsigned int*)raw)[i] != 0u) ? 1 : 0;
        else if (mode == 1) m = raw[i] ? 1 : 0;
        else                m = (((const int*)raw)[i] != 0) ? 1 : 0;
        g_mask[i] = m;
    }
}

// ===========================================================================
// Projection GEMM (SIMT fp32): C = x @ W, head-split store
// ===========================================================================
__global__ __launch_bounds__(256) void proj_kernel(
    const float* __restrict__ X, const float* __restrict__ W, float* __restrict__ dst)
{
    __shared__ float As[16][128];
    __shared__ float Bs[16][128];
    const int row0 = blockIdx.y * 128;
    const int col0 = blockIdx.x * 128;
    const int tid = threadIdx.x;
    const int tx = tid & 15, ty = tid >> 4;
    float acc[8][8];
#pragma unroll
    for (int i = 0; i < 8; i++)
#pragma unroll
        for (int j = 0; j < 8; j++) acc[i][j] = 0.f;

    for (int kt = 0; kt < 64; kt += 16) {
#pragma unroll
        for (int l = 0; l < 2; l++) {
            int f = tid + l * 256;
            int r = f >> 2;
            int c = (f & 3) * 4;
            float4 v = *(const float4*)(X + (size_t)(row0 + r) * 64 + kt + c);
            As[c+0][r] = v.x; As[c+1][r] = v.y; As[c+2][r] = v.z; As[c+3][r] = v.w;
        }
#pragma unroll
        for (int l = 0; l < 2; l++) {
            int f = tid + l * 256;
            int r = f >> 5;
            int c = (f & 31) * 4;
            float4 v = *(const float4*)(W + (size_t)(kt + r) * 4096 + col0 + c);
            *(float4*)&Bs[r][c] = v;
        }
        __syncthreads();
#pragma unroll
        for (int k = 0; k < 16; k++) {
            float4 a0 = *(const float4*)&As[k][ty*8];
            float4 a1 = *(const float4*)&As[k][ty*8+4];
            float4 b0 = *(const float4*)&Bs[k][tx*8];
            float4 b1 = *(const float4*)&Bs[k][tx*8+4];
            float ar[8] = {a0.x,a0.y,a0.z,a0.w,a1.x,a1.y,a1.z,a1.w};
            float br[8] = {b0.x,b0.y,b0.z,b0.w,b1.x,b1.y,b1.z,b1.w};
#pragma unroll
            for (int i = 0; i < 8; i++)
#pragma unroll
                for (int j = 0; j < 8; j++) acc[i][j] = fmaf(ar[i], br[j], acc[i][j]);
        }
        __syncthreads();
    }
    const int col = col0 + tx * 8;
    const int h = col >> 9;
    const int d = col & 511;
#pragma unroll
    for (int i = 0; i < 8; i++) {
        int m = row0 + ty * 8 + i;
        int b = m >> 11;
        int n = m & 2047;
        float* p = dst + (((size_t)(b * HH + h) * NN + n) * DD + d);
        *(float4*)p       = make_float4(acc[i][0], acc[i][1], acc[i][2], acc[i][3]);
        *(float4*)(p + 4) = make_float4(acc[i][4], acc[i][5], acc[i][6], acc[i][7]);
    }
}

// ===========================================================================
// V transpose: v[z][n][d] -> vt[z][d][n], 32x32 tiles
// ===========================================================================
__global__ void transpose_v_kernel(const float* __restrict__ v, float* __restrict__ vt) {
    __shared__ float t[32][33];
    const int z = blockIdx.z;
    const int n0 = blockIdx.x * 32, d0 = blockIdx.y * 32;
    const float* src = v + (size_t)z * NN * DD;
    float* dst = vt + (size_t)z * DD * NN;
    const int tx = threadIdx.x, ty = threadIdx.y;
#pragma unroll
    for (int i = 0; i < 4; i++)
        t[ty + i*8][tx] = src[(size_t)(n0 + ty + i*8) * DD + d0 + tx];
    __syncthreads();
#pragma unroll
    for (int i = 0; i < 4; i++)
        dst[(size_t)(d0 + ty + i*8) * NN + n0 + tx] = t[tx][ty + i*8];
}

// ===========================================================================
// hi/lo split of float4 -> two uint2 (4 bf16 each)
// ===========================================================================
__device__ __forceinline__ void split4(float4 v, uint2& hh, uint2& ll) {
    __nv_bfloat162 h01 = __floats2bfloat162_rn(v.x, v.y);
    __nv_bfloat162 h23 = __floats2bfloat162_rn(v.z, v.w);
    float2 f01 = __bfloat1622float2(h01);
    float2 f23 = __bfloat1622float2(h23);
    __nv_bfloat162 l01 = __floats2bfloat162_rn(v.x - f01.x, v.y - f01.y);
    __nv_bfloat162 l23 = __floats2bfloat162_rn(v.z - f23.x, v.w - f23.y);
    hh.x = *(uint32_t*)&h01; hh.y = *(uint32_t*)&h23;
    ll.x = *(uint32_t*)&l01; ll.y = *(uint32_t*)&l23;
}

// ===========================================================================
// mma.sync bf16 split-precision batched GEMM, CTA tile 128x128, 512 threads.
// 16 warps in 4(m) x 4(n); warp tile 32x32; K-chunk 32, double buffered.
// SMEM stage: Ahi 8K | Alo 8K | Bhi 8K | Blo 8K = 32K; 2 stages = 64K (+mask).
// MODE 0: dots epilogue (scale+mask -> pre). MODE 1: av epilogue (-> ctx).
// ===========================================================================
#define MG_SMEM (65536 + 512)
#define STAGE 32768u

template<int KLD, int MODE>
__global__ __launch_bounds__(512, 1) void mma_gemm(
    const float* __restrict__ Aall, const float* __restrict__ Ball, float* __restrict__ Out)
{
    extern __shared__ char sm[];
    const uint32_t sbase = smem_u32(sm);
    int* cmask = (int*)(sm + 65536);

    const int tid = threadIdx.x;
    const int wid = tid >> 5, lane = tid & 31;
    const int wm = wid >> 2, wn = wid & 3;        // 4 x 4 warps, 32x32 tiles
    const int z = blockIdx.z, b = z >> 3, h = z & 7;
    const int row0 = blockIdx.y * 128, col0 = blockIdx.x * 128;
    const float* A  = Aall + (size_t)z * NN * KLD;
    const float* Bm = Ball + (size_t)z * (MODE == 0 ? NN : DD) * KLD;

    if (MODE == 0 && tid < 128) cmask[tid] = g_mask[b * NN + col0 + tid];

    float acc[2][4][4];
#pragma unroll
    for (int mf = 0; mf < 2; mf++)
#pragma unroll
        for (int nf = 0; nf < 4; nf++)
#pragma unroll
            for (int r = 0; r < 4; r++) acc[mf][nf][r] = 0.f;

    // per-thread global load coords: idx = tid + i*512; r=idx>>3, c4=idx&7
    float4 ra[2], rb[2];
    const int NC = KLD / 32;

    // prologue: chunk 0 -> buffer 0
#pragma unroll
    for (int i = 0; i < 2; i++) {
        int idx = tid + i * 512;
        ra[i] = *(const float4*)(A  + (size_t)(row0 + (idx >> 3)) * KLD + (idx & 7) * 4);
        rb[i] = *(const float4*)(Bm + (size_t)(col0 + (idx >> 3)) * KLD + (idx & 7) * 4);
    }
#pragma unroll
    for (int i = 0; i < 2; i++) {
        int idx = tid + i * 512;
        uint32_t off = swz(idx >> 3, (idx & 7) * 8);
        uint2 hh, ll;
        split4(ra[i], hh, ll);
        *(uint2*)(sm + off)         = hh;
        *(uint2*)(sm + 8192 + off)  = ll;
        split4(rb[i], hh, ll);
        *(uint2*)(sm + 16384 + off) = hh;
        *(uint2*)(sm + 24576 + off) = ll;
    }
    __syncthreads();

    // ldmatrix lane addressing
    const uint32_t a_row = (uint32_t)(wm * 32) + (lane & 15);
    const uint32_t a_kb  = ((lane >> 4) & 1) * 16;
    const uint32_t b_row = (uint32_t)(wn * 32) + ((lane >> 4) & 1) * 8 + (lane & 7);
    const uint32_t b_kb  = ((lane >> 3) & 1) * 16;

    for (int ch = 0; ch < NC; ++ch) {
        const int nxt = ch + 1;
        if (nxt < NC) {
            const int kt = nxt * 32;
#pragma unroll
            for (int i = 0; i < 2; i++) {
                int idx = tid + i * 512;
                ra[i] = *(const float4*)(A  + (size_t)(row0 + (idx >> 3)) * KLD + kt + (idx & 7) * 4);
                rb[i] = *(const float4*)(Bm + (size_t)(col0 + (idx >> 3)) * KLD + kt + (idx & 7) * 4);
            }
        }
        // MMA on buffer ch&1
        {
            const uint32_t AH = sbase + (uint32_t)(ch & 1) * STAGE;
            const uint32_t AL = AH + 8192, BH = AH + 16384, BL = AH + 24576;
#pragma unroll
            for (int ks = 0; ks < 2; ks++) {
                const uint32_t kb0 = (uint32_t)ks * 32;
                uint32_t bh[4][2], bl[4][2];
#pragma unroll
                for (int p = 0; p < 2; p++) {
                    uint32_t o = swz(b_row + p * 16, kb0 + b_kb);
                    uint32_t t4[4];
                    ldsm_x4(t4, BH + o);
                    bh[2*p][0] = t4[0]; bh[2*p][1] = t4[1];
                    bh[2*p+1][0] = t4[2]; bh[2*p+1][1] = t4[3];
                    ldsm_x4(t4, BL + o);
                    bl[2*p][0] = t4[0]; bl[2*p][1] = t4[1];
                    bl[2*p+1][0] = t4[2]; bl[2*p+1][1] = t4[3];
                }
#pragma unroll
                for (int mf = 0; mf < 2; mf++) {
                    uint32_t o = swz(a_row + mf * 16, kb0 + a_kb);
                    uint32_t ah[4], al[4];
                    ldsm_x4(ah, AH + o);
                    ldsm_x4(al, AL + o);
#pragma unroll
                    for (int nf = 0; nf < 4; nf++) {
                        mma_bf16(acc[mf][nf], ah, bh[nf]);
                        mma_bf16(acc[mf][nf], ah, bl[nf]);
                        mma_bf16(acc[mf][nf], al, bh[nf]);
                    }
                }
            }
        }
        if (nxt < NC) {
            char* base = sm + (uint32_t)(nxt & 1) * STAGE;
#pragma unroll
            for (int i = 0; i < 2; i++) {
                int idx = tid + i * 512;
                uint32_t off = swz(idx >> 3, (idx & 7) * 8);
                uint2 hh, ll;
                split4(ra[i], hh, ll);
                *(uint2*)(base + off)         = hh;
                *(uint2*)(base + 8192 + off)  = ll;
                split4(rb[i], hh, ll);
                *(uint2*)(base + 16384 + off) = hh;
                *(uint2*)(base + 24576 + off) = ll;
            }
        }
        __syncthreads();
    }

    // epilogue
    const int r_lo = row0 + wm * 32 + (lane >> 2);
    const int c_base = wn * 32 + (lane & 3) * 2;     // within 128-col tile
    if (MODE == 0) {
        float* outz = Out + (size_t)z * NN * NN;
#pragma unroll
        for (int mf = 0; mf < 2; mf++) {
            int rg0 = r_lo + mf * 16;
            int m0 = g_mask[b * NN + rg0];
            int m1 = g_mask[b * NN + rg0 + 8];
#pragma unroll
            for (int nf = 0; nf < 4; nf++) {
                int cg = c_base + nf * 8;
                int cmA = cmask[cg], cmB = cmask[cg + 1];
                float2 v0, v1;
                v0.x = (m0 && cmA) ? acc[mf][nf][0] * SCALE : MASKV;
                v0.y = (m0 && cmB) ? acc[mf][nf][1] * SCALE : MASKV;
                v1.x = (m1 && cmA) ? acc[mf][nf][2] * SCALE : MASKV;
                v1.y = (m1 && cmB) ? acc[mf][nf][3] * SCALE : MASKV;
                *(float2*)(outz + (size_t)rg0 * NN + col0 + cg)       = v0;
                *(float2*)(outz + (size_t)(rg0 + 8) * NN + col0 + cg) = v1;
            }
        }
    } else {
#pragma unroll
        for (int mf = 0; mf < 2; mf++) {
            int rg0 = r_lo + mf * 16;
            float* p0 = Out + ((size_t)(b * NN + rg0)) * INNER + (size_t)h * DD + col0;
            float* p1 = Out + ((size_t)(b * NN + rg0 + 8)) * INNER + (size_t)h * DD + col0;
#pragma unroll
            for (int nf = 0; nf < 4; nf++) {
                int cg = c_base + nf * 8;
                *(float2*)(p0 + cg) = make_float2(acc[mf][nf][0], acc[mf][nf][1]);
                *(float2*)(p1 + cg) = make_float2(acc[mf][nf][2], acc[mf][nf][3]);
            }
        }
    }
}

// ===========================================================================
// entmax-1.5: one warp per row, 64 elems/thread in registers, shfl-only.
// Newton on f(tau) = sum (x-tau)_+^2 - 1 from tau0 = -1 (monotone from left).
// ===========================================================================
__global__ __launch_bounds__(256) void entmax_kernel(
    const float* __restrict__ pre, float* __restrict__ att)
{
    const int wid = threadIdx.x >> 5, lane = threadIdx.x & 31;
    const size_t row = (size_t)blockIdx.x * 8 + wid;
    const float4* p4 = (const float4*)(pre + row * NN);
    float4* o4 = (float4*)(att + row * NN);

    float x[64];
    float mx = -3.0e38f;
#pragma unroll
    for (int i = 0; i < 16; i++) {
        float4 v = p4[lane + i * 32];
        x[4*i+0] = 0.5f * v.x; x[4*i+1] = 0.5f * v.y;
        x[4*i+2] = 0.5f * v.z; x[4*i+3] = 0.5f * v.w;
        mx = fmaxf(mx, fmaxf(fmaxf(x[4*i], x[4*i+1]), fmaxf(x[4*i+2], x[4*i+3])));
    }
#pragma unroll
    for (int off = 16; off; off >>= 1)
        mx = fmaxf(mx, __shfl_xor_sync(0xffffffffu, mx, off));
#pragma unroll
    for (int j = 0; j < 64; j++) x[j] -= mx;

    float tau = -1.0f;
#pragma unroll 1
    for (int it = 0; it < 20; ++it) {
        float s1 = 0.f, s2 = 0.f;
#pragma unroll
        for (int j = 0; j < 64; j++) {
            float d = fmaxf(x[j] - tau, 0.f);
            s1 += d;
            s2 = fmaf(d, d, s2);
        }
#pragma unroll
        for (int off = 16; off; off >>= 1) {
            s1 += __shfl_xor_sync(0xffffffffu, s1, off);
            s2 += __shfl_xor_sync(0xffffffffu, s2, off);
        }
        float step = (s1 > 1e-20f) ? (s2 - 1.0f) / (2.0f * s1) : 0.f;
        tau += step;
    }
#pragma unroll
    for (int i = 0; i < 16; i++) {
        float4 w;
        float d;
        d = fmaxf(x[4*i+0] - tau, 0.f); w.x = d * d;
        d = fmaxf(x[4*i+1] - tau, 0.f); w.y = d * d;
        d = fmaxf(x[4*i+2] - tau, 0.f); w.z = d * d;
        d = fmaxf(x[4*i+3] - tau, 0.f); w.w = d * d;
        o4[lane + i * 32] = w;
    }
}

// ===========================================================================
// out = ctx @ Wo + bo
// ===========================================================================
__global__ __launch_bounds__(256) void final_kernel(
    const float* __restrict__ C, const float* __restrict__ Wo,
    const float* __restrict__ bo, float* __restrict__ out)
{
    __shared__ float As[32][32];
    __shared__ float Ws[32][64];
    const int row0 = blockIdx.x * 32;
    const int tid = threadIdx.x;
    const int tx = tid & 15, ty = tid >> 4;
    float acc[2][4] = {{0.f,0.f,0.f,0.f},{0.f,0.f,0.f,0.f}};

    for (int kt = 0; kt < INNER; kt += 32) {
        {
            int r = tid >> 3;
            int c = (tid & 7) * 4;
            float4 v = *(const float4*)(C + (size_t)(row0 + r) * INNER + kt + c);
            As[c+0][r] = v.x; As[c+1][r] = v.y; As[c+2][r] = v.z; As[c+3][r] = v.w;
        }
#pragma unroll
        for (int l = 0; l < 2; l++) {
            int f = tid + l * 256;
            int r = f >> 4;
            int c = (f & 15) * 4;
            float4 v = *(const float4*)(Wo + (size_t)(kt + r) * 64 + c);
            *(float4*)&Ws[r][c] = v;
        }
        __syncthreads();
#pragma unroll
        for (int k = 0; k < 32; k++) {
            float a0 = As[k][ty*2 + 0];
            float a1 = As[k][ty*2 + 1];
            float4 w = *(const float4*)&Ws[k][tx*4];
            float wr[4] = {w.x, w.y, w.z, w.w};
#pragma unroll
            for (int j = 0; j < 4; j++) {
                acc[0][j] = fmaf(a0, wr[j], acc[0][j]);
                acc[1][j] = fmaf(a1, wr[j], acc[1][j]);
            }
        }
        __syncthreads();
    }
    float4 bias = *(const float4*)(bo + tx * 4);
    float br[4] = {bias.x, bias.y, bias.z, bias.w};
#pragma unroll
    for (int i = 0; i < 2; i++) {
        int m = row0 + ty * 2 + i;
        float* p = out + (size_t)m * 64 + tx * 4;
        *(float4*)p = make_float4(acc[i][0] + br[0], acc[i][1] + br[1],
                                  acc[i][2] + br[2], acc[i][3] + br[3]);
    }
}

// ===========================================================================
extern "C" void kernel_launch(void* const* d_in, const int* in_sizes, int n_in,
                              void* d_out, int out_size)
{
    const float* x   = (const float*)d_in[0];
    const unsigned char* mask_raw = (const unsigned char*)d_in[1];
    const float* Wq  = (const float*)d_in[2];
    const float* Wk  = (const float*)d_in[3];
    const float* Wv  = (const float*)d_in[4];
    const float* Wo  = (const float*)d_in[5];
    const float* bo  = (const float*)d_in[6];

    float* out = (float*)d_out;
    float* pre = out + OUT_ELEMS;
    float* att = pre + PRE_ELEMS;

    float *pq, *pk, *pv, *pvt, *pctx;
    cudaGetSymbolAddress((void**)&pq,  g_q);
    cudaGetSymbolAddress((void**)&pk,  g_k);
    cudaGetSymbolAddress((void**)&pv,  g_v);
    cudaGetSymbolAddress((void**)&pvt, g_vt);
    cudaGetSymbolAddress((void**)&pctx, g_ctx);

    static int smem_set = 0;
    if (!smem_set) {
        cudaFuncSetAttribute(mma_gemm<512, 0>,
                             cudaFuncAttributeMaxDynamicSharedMemorySize, MG_SMEM);
        cudaFuncSetAttribute(mma_gemm<2048, 1>,
                             cudaFuncAttributeMaxDynamicSharedMemorySize, MG_SMEM);
        smem_set = 1;
    }

    prep_mask_kernel<<<1, 256>>>(mask_raw);

    dim3 pg(32, 32);
    proj_kernel<<<pg, 256>>>(x, Wq, pq);
    proj_kernel<<<pg, 256>>>(x, Wk, pk);
    proj_kernel<<<pg, 256>>>(x, Wv, pv);

    transpose_v_kernel<<<dim3(64, 16, 16), dim3(32, 8)>>>(pv, pvt);

    // dots = scale*Q@K^T (+mask) -> pre
    mma_gemm<512, 0><<<dim3(16, 16, 16), 512, MG_SMEM>>>(pq, pk, pre);

    entmax_kernel<<<BB * HH * NN / 8, 256>>>(pre, att);

    // ctx = attn @ V
    mma_gemm<2048, 1><<<dim3(4, 16, 16), 512, MG_SMEM>>>(att, pvt, pctx);

    final_kernel<<<128, 256>>>(pctx, Wo, bo, out);
}

// round 5
// speedup vs baseline: 2.7885x; 1.1543x over previous
#include <cuda_runtime.h>
#include <cuda_bf16.h>
#include <cuda_fp16.h>
#include <cstdint>

// Problem constants
#define BB 2
#define NN 2048
#define DIMX 64
#define HH 8
#define DD 512            // per-head dim
#define INNER 4096
#define SCALE 0.125f
#define MASKV -1e9f

// Output layout in d_out (fp32): [out | pre_softmax_attn | attn]
#define OUT_ELEMS   (BB*NN*DIMX)          // 262144
#define PRE_ELEMS   (BB*HH*NN*NN)         // 67108864

// Scratch
__device__ float g_q[BB*HH*NN*DD];
__device__ float g_k[BB*HH*NN*DD];
__device__ float g_v[BB*HH*NN*DD];
__device__ float g_vt[BB*HH*DD*NN];
__device__ float g_ctx[BB*NN*INNER];
__device__ int   g_mask[BB*NN];

// ===========================================================================
// Helpers (baseline PTX only: ldmatrix sm_75+, mma.sync fp16 sm_80+)
// ===========================================================================
__device__ __forceinline__ uint32_t smem_u32(const void* p) {
    uint32_t r;
    asm("{ .reg .u64 t; cvta.to.shared.u64 t, %1; cvt.u32.u64 %0, t; }" : "=r"(r) : "l"(p));
    return r;
}
__device__ __forceinline__ void ldsm_x4(uint32_t* r, uint32_t addr) {
    asm volatile("ldmatrix.sync.aligned.m8n8.x4.shared.b16 {%0,%1,%2,%3}, [%4];"
        : "=r"(r[0]), "=r"(r[1]), "=r"(r[2]), "=r"(r[3]) : "r"(addr));
}
__device__ __forceinline__ void mma_f16(float* c, const uint32_t* a, const uint32_t* b) {
    asm volatile("mma.sync.aligned.m16n8k16.row.col.f32.f16.f16.f32 "
        "{%0,%1,%2,%3}, {%4,%5,%6,%7}, {%8,%9}, {%0,%1,%2,%3};"
        : "+f"(c[0]), "+f"(c[1]), "+f"(c[2]), "+f"(c[3])
        : "r"(a[0]), "r"(a[1]), "r"(a[2]), "r"(a[3]), "r"(b[0]), "r"(b[1]));
}

// swizzled byte offset inside a [rows][32] bf16/fp16 tile stored as 64B rows
__device__ __forceinline__ uint32_t swz(uint32_t r, uint32_t kb) {
    uint32_t off = r * 64u + kb;
    return off ^ ((off >> 3) & 0x70u);
}

// fp16 hi/lo split of float4
__device__ __forceinline__ void split4h(float4 v, uint2& hh, uint2& ll) {
    __half2 h01 = __floats2half2_rn(v.x, v.y);
    __half2 h23 = __floats2half2_rn(v.z, v.w);
    float2 f01 = __half22float2(h01);
    float2 f23 = __half22float2(h23);
    __half2 l01 = __floats2half2_rn(v.x - f01.x, v.y - f01.y);
    __half2 l23 = __floats2half2_rn(v.z - f23.x, v.w - f23.y);
    hh.x = *(uint32_t*)&h01; hh.y = *(uint32_t*)&h23;
    ll.x = *(uint32_t*)&l01; ll.y = *(uint32_t*)&l23;
}
// plain fp16 pack of float4
__device__ __forceinline__ uint2 pack4h(float4 v) {
    __half2 h01 = __floats2half2_rn(v.x, v.y);
    __half2 h23 = __floats2half2_rn(v.z, v.w);
    uint2 r;
    r.x = *(uint32_t*)&h01; r.y = *(uint32_t*)&h23;
    return r;
}

// ===========================================================================
// Mask prep (dtype detect)
// ===========================================================================
__global__ void prep_mask_kernel(const unsigned char* __restrict__ raw) {
    __shared__ int cnt_f32, cnt_gt1;
    if (threadIdx.x == 0) { cnt_f32 = 0; cnt_gt1 = 0; }
    __syncthreads();
    const unsigned int* u = (const unsigned int*)raw;
    int lf = 0, lg = 0;
    for (int i = threadIdx.x; i < 1024; i += blockDim.x) {
        unsigned int v = u[i];
        if (v == 0x3f800000u) lf++;
        else if (v > 1u) lg++;
    }
    atomicAdd(&cnt_f32, lf);
    atomicAdd(&cnt_gt1, lg);
    __syncthreads();
    int mode;
    if (cnt_f32 > 64) mode = 2;
    else if (cnt_gt1 > 64) mode = 1;
    else mode = 0;
    for (int i = threadIdx.x; i < BB*NN; i += blockDim.x) {
        int m;
        if (mode == 2)      m = (((const unsigned int*)raw)[i] != 0u) ? 1 : 0;
        else if (mode == 1) m = raw[i] ? 1 : 0;
        else                m = (((const int*)raw)[i] != 0) ? 1 : 0;
        g_mask[i] = m;
    }
}

// ===========================================================================
// Projection GEMM (SIMT fp32): C = x @ W, head-split store
// ===========================================================================
__global__ __launch_bounds__(256) void proj_kernel(
    const float* __restrict__ X, const float* __restrict__ W, float* __restrict__ dst)
{
    __shared__ float As[16][128];
    __shared__ float Bs[16][128];
    const int row0 = blockIdx.y * 128;
    const int col0 = blockIdx.x * 128;
    const int tid = threadIdx.x;
    const int tx = tid & 15, ty = tid >> 4;
    float acc[8][8];
#pragma unroll
    for (int i = 0; i < 8; i++)
#pragma unroll
        for (int j = 0; j < 8; j++) acc[i][j] = 0.f;

    for (int kt = 0; kt < 64; kt += 16) {
#pragma unroll
        for (int l = 0; l < 2; l++) {
            int f = tid + l * 256;
            int r = f >> 2;
            int c = (f & 3) * 4;
            float4 v = *(const float4*)(X + (size_t)(row0 + r) * 64 + kt + c);
            As[c+0][r] = v.x; As[c+1][r] = v.y; As[c+2][r] = v.z; As[c+3][r] = v.w;
        }
#pragma unroll
        for (int l = 0; l < 2; l++) {
            int f = tid + l * 256;
            int r = f >> 5;
            int c = (f & 31) * 4;
            float4 v = *(const float4*)(W + (size_t)(kt + r) * 4096 + col0 + c);
            *(float4*)&Bs[r][c] = v;
        }
        __syncthreads();
#pragma unroll
        for (int k = 0; k < 16; k++) {
            float4 a0 = *(const float4*)&As[k][ty*8];
            float4 a1 = *(const float4*)&As[k][ty*8+4];
            float4 b0 = *(const float4*)&Bs[k][tx*8];
            float4 b1 = *(const float4*)&Bs[k][tx*8+4];
            float ar[8] = {a0.x,a0.y,a0.z,a0.w,a1.x,a1.y,a1.z,a1.w};
            float br[8] = {b0.x,b0.y,b0.z,b0.w,b1.x,b1.y,b1.z,b1.w};
#pragma unroll
            for (int i = 0; i < 8; i++)
#pragma unroll
                for (int j = 0; j < 8; j++) acc[i][j] = fmaf(ar[i], br[j], acc[i][j]);
        }
        __syncthreads();
    }
    const int col = col0 + tx * 8;
    const int h = col >> 9;
    const int d = col & 511;
#pragma unroll
    for (int i = 0; i < 8; i++) {
        int m = row0 + ty * 8 + i;
        int b = m >> 11;
        int n = m & 2047;
        float* p = dst + (((size_t)(b * HH + h) * NN + n) * DD + d);
        *(float4*)p       = make_float4(acc[i][0], acc[i][1], acc[i][2], acc[i][3]);
        *(float4*)(p + 4) = make_float4(acc[i][4], acc[i][5], acc[i][6], acc[i][7]);
    }
}

// ===========================================================================
// V transpose: v[z][n][d] -> vt[z][d][n], 32x32 tiles
// ===========================================================================
__global__ void transpose_v_kernel(const float* __restrict__ v, float* __restrict__ vt) {
    __shared__ float t[32][33];
    const int z = blockIdx.z;
    const int n0 = blockIdx.x * 32, d0 = blockIdx.y * 32;
    const float* src = v + (size_t)z * NN * DD;
    float* dst = vt + (size_t)z * DD * NN;
    const int tx = threadIdx.x, ty = threadIdx.y;
#pragma unroll
    for (int i = 0; i < 4; i++)
        t[ty + i*8][tx] = src[(size_t)(n0 + ty + i*8) * DD + d0 + tx];
    __syncthreads();
#pragma unroll
    for (int i = 0; i < 4; i++)
        dst[(size_t)(d0 + ty + i*8) * NN + n0 + tx] = t[tx][ty + i*8];
}

// ===========================================================================
// mma.sync fp16 A-split batched GEMM, CTA tile 128x128, 512 threads.
// C = (Ah + Al) @ Bh^T : 2 MMAs per fragment pair (B single fp16).
// 16 warps 4x4; warp tile 32x32; K-chunk 32, double buffered.
// SMEM stage: Ahi 8K | Alo 8K | Bh 8K = 24K; 2 stages = 48K (+mask 512).
// MODE 0: dots epilogue (scale+mask -> pre). MODE 1: av epilogue (-> ctx).
// ===========================================================================
#define STAGE 24576u
#define MG_SMEM (49152 + 512)

template<int KLD, int MODE>
__global__ __launch_bounds__(512, 1) void mma_gemm(
    const float* __restrict__ Aall, const float* __restrict__ Ball, float* __restrict__ Out)
{
    extern __shared__ char sm[];
    const uint32_t sbase = smem_u32(sm);
    int* cmask = (int*)(sm + 49152);

    const int tid = threadIdx.x;
    const int wid = tid >> 5, lane = tid & 31;
    const int wm = wid >> 2, wn = wid & 3;        // 4 x 4 warps, 32x32 tiles
    const int z = blockIdx.z, b = z >> 3, h = z & 7;
    const int row0 = blockIdx.y * 128, col0 = blockIdx.x * 128;
    const float* A  = Aall + (size_t)z * NN * KLD;
    const float* Bm = Ball + (size_t)z * (MODE == 0 ? NN : DD) * KLD;

    if (MODE == 0 && tid < 128) cmask[tid] = g_mask[b * NN + col0 + tid];

    float acc[2][4][4];
#pragma unroll
    for (int mf = 0; mf < 2; mf++)
#pragma unroll
        for (int nf = 0; nf < 4; nf++)
#pragma unroll
            for (int r = 0; r < 4; r++) acc[mf][nf][r] = 0.f;

    // per-thread load coords: idx = tid + i*512; r=idx>>3, c4=idx&7
    float4 ra[2], rb[2];
    const int NC = KLD / 32;

    // prologue: chunk 0 -> buffer 0
#pragma unroll
    for (int i = 0; i < 2; i++) {
        int idx = tid + i * 512;
        ra[i] = *(const float4*)(A  + (size_t)(row0 + (idx >> 3)) * KLD + (idx & 7) * 4);
        rb[i] = *(const float4*)(Bm + (size_t)(col0 + (idx >> 3)) * KLD + (idx & 7) * 4);
    }
#pragma unroll
    for (int i = 0; i < 2; i++) {
        int idx = tid + i * 512;
        uint32_t off = swz(idx >> 3, (idx & 7) * 8);
        uint2 hh, ll;
        split4h(ra[i], hh, ll);
        *(uint2*)(sm + off)         = hh;
        *(uint2*)(sm + 8192 + off)  = ll;
        *(uint2*)(sm + 16384 + off) = pack4h(rb[i]);
    }
    __syncthreads();

    // ldmatrix lane addressing
    const uint32_t a_row = (uint32_t)(wm * 32) + (lane & 15);
    const uint32_t a_kb  = ((lane >> 4) & 1) * 16;
    const uint32_t b_row = (uint32_t)(wn * 32) + ((lane >> 4) & 1) * 8 + (lane & 7);
    const uint32_t b_kb  = ((lane >> 3) & 1) * 16;

    for (int ch = 0; ch < NC; ++ch) {
        const int nxt = ch + 1;
        if (nxt < NC) {
            const int kt = nxt * 32;
#pragma unroll
            for (int i = 0; i < 2; i++) {
                int idx = tid + i * 512;
                ra[i] = *(const float4*)(A  + (size_t)(row0 + (idx >> 3)) * KLD + kt + (idx & 7) * 4);
                rb[i] = *(const float4*)(Bm + (size_t)(col0 + (idx >> 3)) * KLD + kt + (idx & 7) * 4);
            }
        }
        // MMA on buffer ch&1
        {
            const uint32_t AH = sbase + (uint32_t)(ch & 1) * STAGE;
            const uint32_t AL = AH + 8192, BH = AH + 16384;
#pragma unroll
            for (int ks = 0; ks < 2; ks++) {
                const uint32_t kb0 = (uint32_t)ks * 32;
                uint32_t bh[4][2];
#pragma unroll
                for (int p = 0; p < 2; p++) {
                    uint32_t o = swz(b_row + p * 16, kb0 + b_kb);
                    uint32_t t4[4];
                    ldsm_x4(t4, BH + o);
                    bh[2*p][0] = t4[0]; bh[2*p][1] = t4[1];
                    bh[2*p+1][0] = t4[2]; bh[2*p+1][1] = t4[3];
                }
#pragma unroll
                for (int mf = 0; mf < 2; mf++) {
                    uint32_t o = swz(a_row + mf * 16, kb0 + a_kb);
                    uint32_t ah[4], al[4];
                    ldsm_x4(ah, AH + o);
                    ldsm_x4(al, AL + o);
#pragma unroll
                    for (int nf = 0; nf < 4; nf++) {
                        mma_f16(acc[mf][nf], ah, bh[nf]);
                        mma_f16(acc[mf][nf], al, bh[nf]);
                    }
                }
            }
        }
        if (nxt < NC) {
            char* base = sm + (uint32_t)(nxt & 1) * STAGE;
#pragma unroll
            for (int i = 0; i < 2; i++) {
                int idx = tid + i * 512;
                uint32_t off = swz(idx >> 3, (idx & 7) * 8);
                uint2 hh, ll;
                split4h(ra[i], hh, ll);
                *(uint2*)(base + off)         = hh;
                *(uint2*)(base + 8192 + off)  = ll;
                *(uint2*)(base + 16384 + off) = pack4h(rb[i]);
            }
        }
        __syncthreads();
    }

    // epilogue
    const int r_lo = row0 + wm * 32 + (lane >> 2);
    const int c_base = wn * 32 + (lane & 3) * 2;     // within 128-col tile
    if (MODE == 0) {
        float* outz = Out + (size_t)z * NN * NN;
#pragma unroll
        for (int mf = 0; mf < 2; mf++) {
            int rg0 = r_lo + mf * 16;
            int m0 = g_mask[b * NN + rg0];
            int m1 = g_mask[b * NN + rg0 + 8];
#pragma unroll
            for (int nf = 0; nf < 4; nf++) {
                int cg = c_base + nf * 8;
                int cmA = cmask[cg], cmB = cmask[cg + 1];
                float2 v0, v1;
                v0.x = (m0 && cmA) ? acc[mf][nf][0] * SCALE : MASKV;
                v0.y = (m0 && cmB) ? acc[mf][nf][1] * SCALE : MASKV;
                v1.x = (m1 && cmA) ? acc[mf][nf][2] * SCALE : MASKV;
                v1.y = (m1 && cmB) ? acc[mf][nf][3] * SCALE : MASKV;
                *(float2*)(outz + (size_t)rg0 * NN + col0 + cg)       = v0;
                *(float2*)(outz + (size_t)(rg0 + 8) * NN + col0 + cg) = v1;
            }
        }
    } else {
#pragma unroll
        for (int mf = 0; mf < 2; mf++) {
            int rg0 = r_lo + mf * 16;
            float* p0 = Out + ((size_t)(b * NN + rg0)) * INNER + (size_t)h * DD + col0;
            float* p1 = Out + ((size_t)(b * NN + rg0 + 8)) * INNER + (size_t)h * DD + col0;
#pragma unroll
            for (int nf = 0; nf < 4; nf++) {
                int cg = c_base + nf * 8;
                *(float2*)(p0 + cg) = make_float2(acc[mf][nf][0], acc[mf][nf][1]);
                *(float2*)(p1 + cg) = make_float2(acc[mf][nf][2], acc[mf][nf][3]);
            }
        }
    }
}

// ===========================================================================
// entmax-1.5: one warp per row, 64 elems/thread in registers, shfl-only.
// Newton on f(tau) = sum (x-tau)_+^2 - 1 from tau0 = -1 (monotone from left).
// ===========================================================================
__global__ __launch_bounds__(256) void entmax_kernel(
    const float* __restrict__ pre, float* __restrict__ att)
{
    const int wid = threadIdx.x >> 5, lane = threadIdx.x & 31;
    const size_t row = (size_t)blockIdx.x * 8 + wid;
    const float4* p4 = (const float4*)(pre + row * NN);
    float4* o4 = (float4*)(att + row * NN);

    float x[64];
    float mx = -3.0e38f;
#pragma unroll
    for (int i = 0; i < 16; i++) {
        float4 v = p4[lane + i * 32];
        x[4*i+0] = 0.5f * v.x; x[4*i+1] = 0.5f * v.y;
        x[4*i+2] = 0.5f * v.z; x[4*i+3] = 0.5f * v.w;
        mx = fmaxf(mx, fmaxf(fmaxf(x[4*i], x[4*i+1]), fmaxf(x[4*i+2], x[4*i+3])));
    }
#pragma unroll
    for (int off = 16; off; off >>= 1)
        mx = fmaxf(mx, __shfl_xor_sync(0xffffffffu, mx, off));
#pragma unroll
    for (int j = 0; j < 64; j++) x[j] -= mx;

    float tau = -1.0f;
#pragma unroll 1
    for (int it = 0; it < 16; ++it) {
        float s1 = 0.f, s2 = 0.f;
#pragma unroll
        for (int j = 0; j < 64; j++) {
            float d = fmaxf(x[j] - tau, 0.f);
            s1 += d;
            s2 = fmaf(d, d, s2);
        }
#pragma unroll
        for (int off = 16; off; off >>= 1) {
            s1 += __shfl_xor_sync(0xffffffffu, s1, off);
            s2 += __shfl_xor_sync(0xffffffffu, s2, off);
        }
        float step = (s1 > 1e-20f) ? (s2 - 1.0f) / (2.0f * s1) : 0.f;
        tau += step;
    }
#pragma unroll
    for (int i = 0; i < 16; i++) {
        float4 w;
        float d;
        d = fmaxf(x[4*i+0] - tau, 0.f); w.x = d * d;
        d = fmaxf(x[4*i+1] - tau, 0.f); w.y = d * d;
        d = fmaxf(x[4*i+2] - tau, 0.f); w.z = d * d;
        d = fmaxf(x[4*i+3] - tau, 0.f); w.w = d * d;
        o4[lane + i * 32] = w;
    }
}

// ===========================================================================
// out = ctx @ Wo + bo
// ===========================================================================
__global__ __launch_bounds__(256) void final_kernel(
    const float* __restrict__ C, const float* __restrict__ Wo,
    const float* __restrict__ bo, float* __restrict__ out)
{
    __shared__ float As[32][32];
    __shared__ float Ws[32][64];
    const int row0 = blockIdx.x * 32;
    const int tid = threadIdx.x;
    const int tx = tid & 15, ty = tid >> 4;
    float acc[2][4] = {{0.f,0.f,0.f,0.f},{0.f,0.f,0.f,0.f}};

    for (int kt = 0; kt < INNER; kt += 32) {
        {
            int r = tid >> 3;
            int c = (tid & 7) * 4;
            float4 v = *(const float4*)(C + (size_t)(row0 + r) * INNER + kt + c);
            As[c+0][r] = v.x; As[c+1][r] = v.y; As[c+2][r] = v.z; As[c+3][r] = v.w;
        }
#pragma unroll
        for (int l = 0; l < 2; l++) {
            int f = tid + l * 256;
            int r = f >> 4;
            int c = (f & 15) * 4;
            float4 v = *(const float4*)(Wo + (size_t)(kt + r) * 64 + c);
            *(float4*)&Ws[r][c] = v;
        }
        __syncthreads();
#pragma unroll
        for (int k = 0; k < 32; k++) {
            float a0 = As[k][ty*2 + 0];
            float a1 = As[k][ty*2 + 1];
            float4 w = *(const float4*)&Ws[k][tx*4];
            float wr[4] = {w.x, w.y, w.z, w.w};
#pragma unroll
            for (int j = 0; j < 4; j++) {
                acc[0][j] = fmaf(a0, wr[j], acc[0][j]);
                acc[1][j] = fmaf(a1, wr[j], acc[1][j]);
            }
        }
        __syncthreads();
    }
    float4 bias = *(const float4*)(bo + tx * 4);
    float br[4] = {bias.x, bias.y, bias.z, bias.w};
#pragma unroll
    for (int i = 0; i < 2; i++) {
        int m = row0 + ty * 2 + i;
        float* p = out + (size_t)m * 64 + tx * 4;
        *(float4*)p = make_float4(acc[i][0] + br[0], acc[i][1] + br[1],
                                  acc[i][2] + br[2], acc[i][3] + br[3]);
    }
}

// ===========================================================================
extern "C" void kernel_launch(void* const* d_in, const int* in_sizes, int n_in,
                              void* d_out, int out_size)
{
    const float* x   = (const float*)d_in[0];
    const unsigned char* mask_raw = (const unsigned char*)d_in[1];
    const float* Wq  = (const float*)d_in[2];
    const float* Wk  = (const float*)d_in[3];
    const float* Wv  = (const float*)d_in[4];
    const float* Wo  = (const float*)d_in[5];
    const float* bo  = (const float*)d_in[6];

    float* out = (float*)d_out;
    float* pre = out + OUT_ELEMS;
    float* att = pre + PRE_ELEMS;

    float *pq, *pk, *pv, *pvt, *pctx;
    cudaGetSymbolAddress((void**)&pq,  g_q);
    cudaGetSymbolAddress((void**)&pk,  g_k);
    cudaGetSymbolAddress((void**)&pv,  g_v);
    cudaGetSymbolAddress((void**)&pvt, g_vt);
    cudaGetSymbolAddress((void**)&pctx, g_ctx);

    static int smem_set = 0;
    if (!smem_set) {
        cudaFuncSetAttribute(mma_gemm<512, 0>,
                             cudaFuncAttributeMaxDynamicSharedMemorySize, MG_SMEM);
        cudaFuncSetAttribute(mma_gemm<2048, 1>,
                             cudaFuncAttributeMaxDynamicSharedMemorySize, MG_SMEM);
        smem_set = 1;
    }

    prep_mask_kernel<<<1, 256>>>(mask_raw);

    dim3 pg(32, 32);
    proj_kernel<<<pg, 256>>>(x, Wq, pq);
    proj_kernel<<<pg, 256>>>(x, Wk, pk);
    proj_kernel<<<pg, 256>>>(x, Wv, pv);

    transpose_v_kernel<<<dim3(64, 16, 16), dim3(32, 8)>>>(pv, pvt);

    // dots = scale*Q@K^T (+mask) -> pre
    mma_gemm<512, 0><<<dim3(16, 16, 16), 512, MG_SMEM>>>(pq, pk, pre);

    entmax_kernel<<<BB * HH * NN / 8, 256>>>(pre, att);

    // ctx = attn @ V
    mma_gemm<2048, 1><<<dim3(4, 16, 16), 512, MG_SMEM>>>(att, pvt, pctx);

    final_kernel<<<128, 256>>>(pctx, Wo, bo, out);
}

// round 6
// speedup vs baseline: 3.7551x; 1.3466x over previous
#include <cuda_runtime.h>
#include <cuda_bf16.h>
#include <cuda_fp16.h>
#include <cstdint>

// Problem constants
#define BB 2
#define NN 2048
#define DIMX 64
#define HH 8
#define DD 512            // per-head dim
#define INNER 4096
#define SCALE 0.125f
#define MASKV -1e9f

// Output layout in d_out (fp32): [out | pre_softmax_attn | attn]
#define OUT_ELEMS   (BB*NN*DIMX)          // 262144
#define PRE_ELEMS   (BB*HH*NN*NN)         // 67108864

#define NROWS (BB*HH*NN)   // 32768
#define MAXS  512

// Scratch
__device__ float g_q[BB*HH*NN*DD];
__device__ float g_k[BB*HH*NN*DD];
__device__ float g_v[BB*HH*NN*DD];
__device__ float g_ctx[BB*NN*INNER];
__device__ int   g_mask[BB*NN];
__device__ int   g_si[(size_t)NROWS * MAXS];
__device__ float g_sw[(size_t)NROWS * MAXS];
__device__ int   g_cnt[NROWS];
__device__ float g_vsum[BB*HH*DD];

// ===========================================================================
// Helpers (baseline PTX only: ldmatrix sm_75+, mma.sync fp16 sm_80+)
// ===========================================================================
__device__ __forceinline__ uint32_t smem_u32(const void* p) {
    uint32_t r;
    asm("{ .reg .u64 t; cvta.to.shared.u64 t, %1; cvt.u32.u64 %0, t; }" : "=r"(r) : "l"(p));
    return r;
}
__device__ __forceinline__ void ldsm_x4(uint32_t* r, uint32_t addr) {
    asm volatile("ldmatrix.sync.aligned.m8n8.x4.shared.b16 {%0,%1,%2,%3}, [%4];"
        : "=r"(r[0]), "=r"(r[1]), "=r"(r[2]), "=r"(r[3]) : "r"(addr));
}
__device__ __forceinline__ void mma_f16(float* c, const uint32_t* a, const uint32_t* b) {
    asm volatile("mma.sync.aligned.m16n8k16.row.col.f32.f16.f16.f32 "
        "{%0,%1,%2,%3}, {%4,%5,%6,%7}, {%8,%9}, {%0,%1,%2,%3};"
        : "+f"(c[0]), "+f"(c[1]), "+f"(c[2]), "+f"(c[3])
        : "r"(a[0]), "r"(a[1]), "r"(a[2]), "r"(a[3]), "r"(b[0]), "r"(b[1]));
}

// swizzled byte offset inside a [rows][32] fp16 tile stored as 64B rows
__device__ __forceinline__ uint32_t swz(uint32_t r, uint32_t kb) {
    uint32_t off = r * 64u + kb;
    return off ^ ((off >> 3) & 0x70u);
}

// fp16 hi/lo split of float4
__device__ __forceinline__ void split4h(float4 v, uint2& hh, uint2& ll) {
    __half2 h01 = __floats2half2_rn(v.x, v.y);
    __half2 h23 = __floats2half2_rn(v.z, v.w);
    float2 f01 = __half22float2(h01);
    float2 f23 = __half22float2(h23);
    __half2 l01 = __floats2half2_rn(v.x - f01.x, v.y - f01.y);
    __half2 l23 = __floats2half2_rn(v.z - f23.x, v.w - f23.y);
    hh.x = *(uint32_t*)&h01; hh.y = *(uint32_t*)&h23;
    ll.x = *(uint32_t*)&l01; ll.y = *(uint32_t*)&l23;
}

// ===========================================================================
// Mask prep (dtype detect)
// ===========================================================================
__global__ void prep_mask_kernel(const unsigned char* __restrict__ raw) {
    __shared__ int cnt_f32, cnt_gt1;
    if (threadIdx.x == 0) { cnt_f32 = 0; cnt_gt1 = 0; }
    __syncthreads();
    const unsigned int* u = (const unsigned int*)raw;
    int lf = 0, lg = 0;
    for (int i = threadIdx.x; i < 1024; i += blockDim.x) {
        unsigned int v = u[i];
        if (v == 0x3f800000u) lf++;
        else if (v > 1u) lg++;
    }
    atomicAdd(&cnt_f32, lf);
    atomicAdd(&cnt_gt1, lg);
    __syncthreads();
    int mode;
    if (cnt_f32 > 64) mode = 2;
    else if (cnt_gt1 > 64) mode = 1;
    else mode = 0;
    for (int i = threadIdx.x; i < BB*NN; i += blockDim.x) {
        int m;
        if (mode == 2)      m = (((const unsigned int*)raw)[i] != 0u) ? 1 : 0;
        else if (mode == 1) m = raw[i] ? 1 : 0;
        else                m = (((const int*)raw)[i] != 0) ? 1 : 0;
        g_mask[i] = m;
    }
}

// ===========================================================================
// Fused projection GEMM (SIMT fp32): z selects (Wq->q, Wk->k, Wv->v)
// ===========================================================================
__global__ __launch_bounds__(256) void proj3_kernel(
    const float* __restrict__ X,
    const float* __restrict__ Wq, const float* __restrict__ Wk, const float* __restrict__ Wv,
    float* __restrict__ dq, float* __restrict__ dk, float* __restrict__ dv)
{
    const float* W = (blockIdx.z == 0) ? Wq : (blockIdx.z == 1) ? Wk : Wv;
    float* dst     = (blockIdx.z == 0) ? dq : (blockIdx.z == 1) ? dk : dv;

    __shared__ float As[16][128];
    __shared__ float Bs[16][128];
    const int row0 = blockIdx.y * 128;
    const int col0 = blockIdx.x * 128;
    const int tid = threadIdx.x;
    const int tx = tid & 15, ty = tid >> 4;
    float acc[8][8];
#pragma unroll
    for (int i = 0; i < 8; i++)
#pragma unroll
        for (int j = 0; j < 8; j++) acc[i][j] = 0.f;

    for (int kt = 0; kt < 64; kt += 16) {
#pragma unroll
        for (int l = 0; l < 2; l++) {
            int f = tid + l * 256;
            int r = f >> 2;
            int c = (f & 3) * 4;
            float4 v = *(const float4*)(X + (size_t)(row0 + r) * 64 + kt + c);
            As[c+0][r] = v.x; As[c+1][r] = v.y; As[c+2][r] = v.z; As[c+3][r] = v.w;
        }
#pragma unroll
        for (int l = 0; l < 2; l++) {
            int f = tid + l * 256;
            int r = f >> 5;
            int c = (f & 31) * 4;
            float4 v = *(const float4*)(W + (size_t)(kt + r) * 4096 + col0 + c);
            *(float4*)&Bs[r][c] = v;
        }
        __syncthreads();
#pragma unroll
        for (int k = 0; k < 16; k++) {
            float4 a0 = *(const float4*)&As[k][ty*8];
            float4 a1 = *(const float4*)&As[k][ty*8+4];
            float4 b0 = *(const float4*)&Bs[k][tx*8];
            float4 b1 = *(const float4*)&Bs[k][tx*8+4];
            float ar[8] = {a0.x,a0.y,a0.z,a0.w,a1.x,a1.y,a1.z,a1.w};
            float br[8] = {b0.x,b0.y,b0.z,b0.w,b1.x,b1.y,b1.z,b1.w};
#pragma unroll
            for (int i = 0; i < 8; i++)
#pragma unroll
                for (int j = 0; j < 8; j++) acc[i][j] = fmaf(ar[i], br[j], acc[i][j]);
        }
        __syncthreads();
    }
    const int col = col0 + tx * 8;
    const int h = col >> 9;
    const int d = col & 511;
#pragma unroll
    for (int i = 0; i < 8; i++) {
        int m = row0 + ty * 8 + i;
        int b = m >> 11;
        int n = m & 2047;
        float* p = dst + (((size_t)(b * HH + h) * NN + n) * DD + d);
        *(float4*)p       = make_float4(acc[i][0], acc[i][1], acc[i][2], acc[i][3]);
        *(float4*)(p + 4) = make_float4(acc[i][4], acc[i][5], acc[i][6], acc[i][7]);
    }
}

// ===========================================================================
// V column-sum per (b,h): vsum[z][d] = sum_n V[z][n][d]
// ===========================================================================
__global__ __launch_bounds__(256) void vsum_kernel(const float* __restrict__ V) {
    const int z = blockIdx.y;
    const int d = blockIdx.x * 256 + threadIdx.x;
    const float* p = V + (size_t)z * NN * DD + d;
    float s = 0.f;
#pragma unroll 8
    for (int n = 0; n < NN; n++) s += p[(size_t)n * DD];
    g_vsum[z * DD + d] = s;
}

// ===========================================================================
// mma.sync fp16 A-split batched GEMM (dots only), CTA tile 128x128, 512 thr.
// C = (Ah + Al) @ Bh^T, K=512, scale+mask epilogue -> pre
// ===========================================================================
#define STAGE 24576u
#define MG_SMEM (49152 + 512)

__global__ __launch_bounds__(512, 1) void dots_gemm(
    const float* __restrict__ Aall, const float* __restrict__ Ball, float* __restrict__ Out)
{
    constexpr int KLD = DD;
    extern __shared__ char sm[];
    const uint32_t sbase = smem_u32(sm);
    int* cmask = (int*)(sm + 49152);

    const int tid = threadIdx.x;
    const int wid = tid >> 5, lane = tid & 31;
    const int wm = wid >> 2, wn = wid & 3;
    const int z = blockIdx.z, b = z >> 3;
    const int row0 = blockIdx.y * 128, col0 = blockIdx.x * 128;
    const float* A  = Aall + (size_t)z * NN * KLD;
    const float* Bm = Ball + (size_t)z * NN * KLD;

    if (tid < 128) cmask[tid] = g_mask[b * NN + col0 + tid];

    float acc[2][4][4];
#pragma unroll
    for (int mf = 0; mf < 2; mf++)
#pragma unroll
        for (int nf = 0; nf < 4; nf++)
#pragma unroll
            for (int r = 0; r < 4; r++) acc[mf][nf][r] = 0.f;

    float4 ra[2], rb[2];
    const int NC = KLD / 32;

#pragma unroll
    for (int i = 0; i < 2; i++) {
        int idx = tid + i * 512;
        ra[i] = *(const float4*)(A  + (size_t)(row0 + (idx >> 3)) * KLD + (idx & 7) * 4);
        rb[i] = *(const float4*)(Bm + (size_t)(col0 + (idx >> 3)) * KLD + (idx & 7) * 4);
    }
#pragma unroll
    for (int i = 0; i < 2; i++) {
        int idx = tid + i * 512;
        uint32_t off = swz(idx >> 3, (idx & 7) * 8);
        uint2 hh, ll;
        split4h(ra[i], hh, ll);
        *(uint2*)(sm + off)         = hh;
        *(uint2*)(sm + 8192 + off)  = ll;
        split4h(rb[i], hh, ll);
        *(uint2*)(sm + 16384 + off) = hh;   // B hi only
    }
    __syncthreads();

    const uint32_t a_row = (uint32_t)(wm * 32) + (lane & 15);
    const uint32_t a_kb  = ((lane >> 4) & 1) * 16;
    const uint32_t b_row = (uint32_t)(wn * 32) + ((lane >> 4) & 1) * 8 + (lane & 7);
    const uint32_t b_kb  = ((lane >> 3) & 1) * 16;

    for (int ch = 0; ch < NC; ++ch) {
        const int nxt = ch + 1;
        if (nxt < NC) {
            const int kt = nxt * 32;
#pragma unroll
            for (int i = 0; i < 2; i++) {
                int idx = tid + i * 512;
                ra[i] = *(const float4*)(A  + (size_t)(row0 + (idx >> 3)) * KLD + kt + (idx & 7) * 4);
                rb[i] = *(const float4*)(Bm + (size_t)(col0 + (idx >> 3)) * KLD + kt + (idx & 7) * 4);
            }
        }
        {
            const uint32_t AH = sbase + (uint32_t)(ch & 1) * STAGE;
            const uint32_t AL = AH + 8192, BH = AH + 16384;
#pragma unroll
            for (int ks = 0; ks < 2; ks++) {
                const uint32_t kb0 = (uint32_t)ks * 32;
                uint32_t bh[4][2];
#pragma unroll
                for (int p = 0; p < 2; p++) {
                    uint32_t o = swz(b_row + p * 16, kb0 + b_kb);
                    uint32_t t4[4];
                    ldsm_x4(t4, BH + o);
                    bh[2*p][0] = t4[0]; bh[2*p][1] = t4[1];
                    bh[2*p+1][0] = t4[2]; bh[2*p+1][1] = t4[3];
                }
#pragma unroll
                for (int mf = 0; mf < 2; mf++) {
                    uint32_t o = swz(a_row + mf * 16, kb0 + a_kb);
                    uint32_t ah[4], al[4];
                    ldsm_x4(ah, AH + o);
                    ldsm_x4(al, AL + o);
#pragma unroll
                    for (int nf = 0; nf < 4; nf++) {
                        mma_f16(acc[mf][nf], ah, bh[nf]);
                        mma_f16(acc[mf][nf], al, bh[nf]);
                    }
                }
            }
        }
        if (nxt < NC) {
            char* base = sm + (uint32_t)(nxt & 1) * STAGE;
#pragma unroll
            for (int i = 0; i < 2; i++) {
                int idx = tid + i * 512;
                uint32_t off = swz(idx >> 3, (idx & 7) * 8);
                uint2 hh, ll;
                split4h(ra[i], hh, ll);
                *(uint2*)(base + off)         = hh;
                *(uint2*)(base + 8192 + off)  = ll;
                split4h(rb[i], hh, ll);
                *(uint2*)(base + 16384 + off) = hh;
            }
        }
        __syncthreads();
    }

    const int r_lo = row0 + wm * 32 + (lane >> 2);
    const int c_base = wn * 32 + (lane & 3) * 2;
    float* outz = Out + (size_t)z * NN * NN;
#pragma unroll
    for (int mf = 0; mf < 2; mf++) {
        int rg0 = r_lo + mf * 16;
        int m0 = g_mask[b * NN + rg0];
        int m1 = g_mask[b * NN + rg0 + 8];
#pragma unroll
        for (int nf = 0; nf < 4; nf++) {
            int cg = c_base + nf * 8;
            int cmA = cmask[cg], cmB = cmask[cg + 1];
            float2 v0, v1;
            v0.x = (m0 && cmA) ? acc[mf][nf][0] * SCALE : MASKV;
            v0.y = (m0 && cmB) ? acc[mf][nf][1] * SCALE : MASKV;
            v1.x = (m1 && cmA) ? acc[mf][nf][2] * SCALE : MASKV;
            v1.y = (m1 && cmB) ? acc[mf][nf][3] * SCALE : MASKV;
            *(float2*)(outz + (size_t)rg0 * NN + col0 + cg)       = v0;
            *(float2*)(outz + (size_t)(rg0 + 8) * NN + col0 + cg) = v1;
        }
    }
}

// ===========================================================================
// entmax-1.5: one warp per row. Dense att write + compact (col, weight) list.
// Masked rows: uniform 1/2048 (exact), flag -1.
// ===========================================================================
__global__ __launch_bounds__(256) void entmax_kernel(
    const float* __restrict__ pre, float* __restrict__ att)
{
    const int wid = threadIdx.x >> 5, lane = threadIdx.x & 31;
    const size_t row = (size_t)blockIdx.x * 8 + wid;
    const int z = (int)(row >> 11), n = (int)(row & 2047), b = z >> 3;
    float4* o4 = (float4*)(att + row * NN);

    if (!g_mask[b * NN + n]) {
        float t = __fsqrt_rn(1.0f / 2048.0f);
        float P = t * t;
        float4 u = make_float4(P, P, P, P);
#pragma unroll
        for (int i = 0; i < 16; i++) o4[lane + i * 32] = u;
        if (lane == 0) g_cnt[row] = -1;
        return;
    }

    const float4* p4 = (const float4*)(pre + row * NN);
    float x[64];
    float mx = -3.0e38f;
#pragma unroll
    for (int i = 0; i < 16; i++) {
        float4 v = p4[lane + i * 32];
        x[4*i+0] = 0.5f * v.x; x[4*i+1] = 0.5f * v.y;
        x[4*i+2] = 0.5f * v.z; x[4*i+3] = 0.5f * v.w;
        mx = fmaxf(mx, fmaxf(fmaxf(x[4*i], x[4*i+1]), fmaxf(x[4*i+2], x[4*i+3])));
    }
#pragma unroll
    for (int off = 16; off; off >>= 1)
        mx = fmaxf(mx, __shfl_xor_sync(0xffffffffu, mx, off));
#pragma unroll
    for (int j = 0; j < 64; j++) x[j] -= mx;

    float tau = -1.0f;
#pragma unroll 1
    for (int it = 0; it < 12; ++it) {
        float s1 = 0.f, s2 = 0.f;
#pragma unroll
        for (int j = 0; j < 64; j++) {
            float d = fmaxf(x[j] - tau, 0.f);
            s1 += d;
            s2 = fmaf(d, d, s2);
        }
#pragma unroll
        for (int off = 16; off; off >>= 1) {
            s1 += __shfl_xor_sync(0xffffffffu, s1, off);
            s2 += __shfl_xor_sync(0xffffffffu, s2, off);
        }
        float step = (s1 > 1e-20f) ? (s2 - 1.0f) / (2.0f * s1) : 0.f;
        tau += step;
    }

    // dense write
#pragma unroll
    for (int i = 0; i < 16; i++) {
        float4 w;
        float d;
        d = fmaxf(x[4*i+0] - tau, 0.f); w.x = d * d;
        d = fmaxf(x[4*i+1] - tau, 0.f); w.y = d * d;
        d = fmaxf(x[4*i+2] - tau, 0.f); w.z = d * d;
        d = fmaxf(x[4*i+3] - tau, 0.f); w.w = d * d;
        o4[lane + i * 32] = w;
    }

    // compact list emission
    int cl = 0;
#pragma unroll
    for (int j = 0; j < 64; j++) cl += (x[j] > tau) ? 1 : 0;
    int v = cl;
#pragma unroll
    for (int d = 1; d < 32; d <<= 1) {
        int t = __shfl_up_sync(0xffffffffu, v, d);
        if (lane >= d) v += t;
    }
    int total = __shfl_sync(0xffffffffu, v, 31);
    int pos = v - cl;
    if (total <= MAXS) {
        int*   si = g_si + row * MAXS;
        float* sw = g_sw + row * MAXS;
#pragma unroll
        for (int i = 0; i < 16; i++)
#pragma unroll
            for (int c = 0; c < 4; c++) {
                int j = 4*i + c;
                if (x[j] > tau) {
                    float d = x[j] - tau;
                    si[pos] = 4*lane + 128*i + c;
                    sw[pos] = d * d;
                    pos++;
                }
            }
        if (lane == 31) g_cnt[row] = total;
    } else if (lane == 31) {
        g_cnt[row] = -2;
    }
}

// ===========================================================================
// Sparse AV: ctx[b][n][h*512+d] = sum_j w_j * V[z][idx_j][d]
// One warp per (row, 128-d chunk).
// ===========================================================================
__global__ __launch_bounds__(256) void av_sparse_kernel(
    const float* __restrict__ V, const float* __restrict__ att, float* __restrict__ ctx)
{
    const int wid = threadIdx.x >> 5, lane = threadIdx.x & 31;
    const int gw = blockIdx.x * 8 + wid;
    const int row = gw >> 2, chunk = gw & 3;
    const int z = row >> 11, n = row & 2047, b = z >> 3, h = z & 7;
    const int dbase = chunk * 128 + lane * 4;
    const float* Vz = V + (size_t)z * NN * DD;
    float4 acc = make_float4(0.f, 0.f, 0.f, 0.f);
    const int cnt = g_cnt[row];

    if (cnt == -1) {
        float t = __fsqrt_rn(1.0f / 2048.0f);
        float P = t * t;
        float4 s = *(const float4*)(g_vsum + z * DD + dbase);
        acc = make_float4(P * s.x, P * s.y, P * s.z, P * s.w);
    } else if (cnt >= 0) {
        const int*   si = g_si + (size_t)row * MAXS;
        const float* sw = g_sw + (size_t)row * MAXS;
        int j = 0;
        for (; j + 2 <= cnt; j += 2) {
            int   i0 = si[j],   i1 = si[j+1];
            float w0 = sw[j],   w1 = sw[j+1];
            float4 v0 = *(const float4*)(Vz + (size_t)i0 * DD + dbase);
            float4 v1 = *(const float4*)(Vz + (size_t)i1 * DD + dbase);
            acc.x = fmaf(w0, v0.x, acc.x); acc.x = fmaf(w1, v1.x, acc.x);
            acc.y = fmaf(w0, v0.y, acc.y); acc.y = fmaf(w1, v1.y, acc.y);
            acc.z = fmaf(w0, v0.z, acc.z); acc.z = fmaf(w1, v1.z, acc.z);
            acc.w = fmaf(w0, v0.w, acc.w); acc.w = fmaf(w1, v1.w, acc.w);
        }
        if (j < cnt) {
            int   i0 = si[j];
            float w0 = sw[j];
            float4 v0 = *(const float4*)(Vz + (size_t)i0 * DD + dbase);
            acc.x = fmaf(w0, v0.x, acc.x);
            acc.y = fmaf(w0, v0.y, acc.y);
            acc.z = fmaf(w0, v0.z, acc.z);
            acc.w = fmaf(w0, v0.w, acc.w);
        }
    } else {  // -2: dense fallback over the written att row
        const float* arow = att + (size_t)row * NN;
        for (int c = 0; c < NN; c++) {
            float p = arow[c];
            if (p != 0.f) {
                float4 v0 = *(const float4*)(Vz + (size_t)c * DD + dbase);
                acc.x = fmaf(p, v0.x, acc.x);
                acc.y = fmaf(p, v0.y, acc.y);
                acc.z = fmaf(p, v0.z, acc.z);
                acc.w = fmaf(p, v0.w, acc.w);
            }
        }
    }
    *(float4*)(ctx + ((size_t)(b * NN + n)) * INNER + (size_t)h * DD + dbase) = acc;
}

// ===========================================================================
// out = ctx @ Wo + bo
// ===========================================================================
__global__ __launch_bounds__(256) void final_kernel(
    const float* __restrict__ C, const float* __restrict__ Wo,
    const float* __restrict__ bo, float* __restrict__ out)
{
    __shared__ float As[32][32];
    __shared__ float Ws[32][64];
    const int row0 = blockIdx.x * 32;
    const int tid = threadIdx.x;
    const int tx = tid & 15, ty = tid >> 4;
    float acc[2][4] = {{0.f,0.f,0.f,0.f},{0.f,0.f,0.f,0.f}};

    for (int kt = 0; kt < INNER; kt += 32) {
        {
            int r = tid >> 3;
            int c = (tid & 7) * 4;
            float4 v = *(const float4*)(C + (size_t)(row0 + r) * INNER + kt + c);
            As[c+0][r] = v.x; As[c+1][r] = v.y; As[c+2][r] = v.z; As[c+3][r] = v.w;
        }
#pragma unroll
        for (int l = 0; l < 2; l++) {
            int f = tid + l * 256;
            int r = f >> 4;
            int c = (f & 15) * 4;
            float4 v = *(const float4*)(Wo + (size_t)(kt + r) * 64 + c);
            *(float4*)&Ws[r][c] = v;
        }
        __syncthreads();
#pragma unroll
        for (int k = 0; k < 32; k++) {
            float a0 = As[k][ty*2 + 0];
            float a1 = As[k][ty*2 + 1];
            float4 w = *(const float4*)&Ws[k][tx*4];
            float wr[4] = {w.x, w.y, w.z, w.w};
#pragma unroll
            for (int j = 0; j < 4; j++) {
                acc[0][j] = fmaf(a0, wr[j], acc[0][j]);
                acc[1][j] = fmaf(a1, wr[j], acc[1][j]);
            }
        }
        __syncthreads();
    }
    float4 bias = *(const float4*)(bo + tx * 4);
    float br[4] = {bias.x, bias.y, bias.z, bias.w};
#pragma unroll
    for (int i = 0; i < 2; i++) {
        int m = row0 + ty * 2 + i;
        float* p = out + (size_t)m * 64 + tx * 4;
        *(float4*)p = make_float4(acc[i][0] + br[0], acc[i][1] + br[1],
                                  acc[i][2] + br[2], acc[i][3] + br[3]);
    }
}

// ===========================================================================
extern "C" void kernel_launch(void* const* d_in, const int* in_sizes, int n_in,
                              void* d_out, int out_size)
{
    const float* x   = (const float*)d_in[0];
    const unsigned char* mask_raw = (const unsigned char*)d_in[1];
    const float* Wq  = (const float*)d_in[2];
    const float* Wk  = (const float*)d_in[3];
    const float* Wv  = (const float*)d_in[4];
    const float* Wo  = (const float*)d_in[5];
    const float* bo  = (const float*)d_in[6];

    float* out = (float*)d_out;
    float* pre = out + OUT_ELEMS;
    float* att = pre + PRE_ELEMS;

    float *pq, *pk, *pv, *pctx;
    cudaGetSymbolAddress((void**)&pq,  g_q);
    cudaGetSymbolAddress((void**)&pk,  g_k);
    cudaGetSymbolAddress((void**)&pv,  g_v);
    cudaGetSymbolAddress((void**)&pctx, g_ctx);

    static int smem_set = 0;
    if (!smem_set) {
        cudaFuncSetAttribute(dots_gemm,
                             cudaFuncAttributeMaxDynamicSharedMemorySize, MG_SMEM);
        smem_set = 1;
    }

    prep_mask_kernel<<<1, 256>>>(mask_raw);

    proj3_kernel<<<dim3(32, 32, 3), 256>>>(x, Wq, Wk, Wv, pq, pk, pv);

    vsum_kernel<<<dim3(2, 16), 256>>>(pv);

    // dots = scale*Q@K^T (+mask) -> pre
    dots_gemm<<<dim3(16, 16, 16), 512, MG_SMEM>>>(pq, pk, pre);

    // entmax + compact list emission
    entmax_kernel<<<BB * HH * NN / 8, 256>>>(pre, att);

    // ctx = attn @ V (sparse gather)
    av_sparse_kernel<<<NROWS * 4 / 8, 256>>>(pv, att, pctx);

    final_kernel<<<128, 256>>>(pctx, Wo, bo, out);
}

// round 7
// speedup vs baseline: 4.7458x; 1.2638x over previous
#include <cuda_runtime.h>
#include <cuda_bf16.h>
#include <cuda_fp16.h>
#include <cstdint>

// Problem constants
#define BB 2
#define NN 2048
#define DIMX 64
#define HH 8
#define DD 512            // per-head dim
#define INNER 4096
#define SCALE 0.125f
#define MASKV -1e9f

#define OUT_ELEMS   (BB*NN*DIMX)          // 262144
#define PRE_ELEMS   (BB*HH*NN*NN)         // 67108864

#define NROWS (BB*HH*NN)   // 32768
#define MAXS  512

// Scratch
__device__ __half g_qh[BB*HH*NN*DD];
__device__ __half g_ql[BB*HH*NN*DD];
__device__ __half g_kh[BB*HH*NN*DD];
__device__ float  g_v[BB*HH*NN*DD];
__device__ float  g_ctx[BB*NN*INNER];
__device__ float  g_fpart[4][OUT_ELEMS];
__device__ int    g_mask[BB*NN];
__device__ int    g_si[(size_t)NROWS * MAXS];
__device__ float  g_sw[(size_t)NROWS * MAXS];
__device__ int    g_cnt[NROWS];
__device__ float  g_vsum[BB*HH*DD];

// ===========================================================================
// Helpers (baseline PTX: ldmatrix sm_75+, mma.sync fp16 sm_80+, cp.async sm_80+)
// ===========================================================================
__device__ __forceinline__ uint32_t smem_u32(const void* p) {
    uint32_t r;
    asm("{ .reg .u64 t; cvta.to.shared.u64 t, %1; cvt.u32.u64 %0, t; }" : "=r"(r) : "l"(p));
    return r;
}
__device__ __forceinline__ void ldsm_x4(uint32_t* r, uint32_t addr) {
    asm volatile("ldmatrix.sync.aligned.m8n8.x4.shared.b16 {%0,%1,%2,%3}, [%4];"
        : "=r"(r[0]), "=r"(r[1]), "=r"(r[2]), "=r"(r[3]) : "r"(addr));
}
__device__ __forceinline__ void mma_f16(float* c, const uint32_t* a, const uint32_t* b) {
    asm volatile("mma.sync.aligned.m16n8k16.row.col.f32.f16.f16.f32 "
        "{%0,%1,%2,%3}, {%4,%5,%6,%7}, {%8,%9}, {%0,%1,%2,%3};"
        : "+f"(c[0]), "+f"(c[1]), "+f"(c[2]), "+f"(c[3])
        : "r"(a[0]), "r"(a[1]), "r"(a[2]), "r"(a[3]), "r"(b[0]), "r"(b[1]));
}
#define CP16(saddr, gptr) \
    asm volatile("cp.async.cg.shared.global [%0], [%1], 16;" :: "r"(saddr), "l"(gptr))
#define CP_COMMIT() asm volatile("cp.async.commit_group;")
#define CP_WAIT1()  asm volatile("cp.async.wait_group 1;")

// swizzled byte offset inside a [128 rows][32 cols] fp16 tile, 64B rows
__device__ __forceinline__ uint32_t swz(uint32_t r, uint32_t kb) {
    uint32_t off = r * 64u + kb;
    return off ^ ((off >> 3) & 0x70u);
}

// ===========================================================================
// Mask prep (dtype detect)
// ===========================================================================
__global__ void prep_mask_kernel(const unsigned char* __restrict__ raw) {
    __shared__ int cnt_f32, cnt_gt1;
    if (threadIdx.x == 0) { cnt_f32 = 0; cnt_gt1 = 0; }
    __syncthreads();
    const unsigned int* u = (const unsigned int*)raw;
    int lf = 0, lg = 0;
    for (int i = threadIdx.x; i < 1024; i += blockDim.x) {
        unsigned int v = u[i];
        if (v == 0x3f800000u) lf++;
        else if (v > 1u) lg++;
    }
    atomicAdd(&cnt_f32, lf);
    atomicAdd(&cnt_gt1, lg);
    __syncthreads();
    int mode;
    if (cnt_f32 > 64) mode = 2;
    else if (cnt_gt1 > 64) mode = 1;
    else mode = 0;
    for (int i = threadIdx.x; i < BB*NN; i += blockDim.x) {
        int m;
        if (mode == 2)      m = (((const unsigned int*)raw)[i] != 0u) ? 1 : 0;
        else if (mode == 1) m = raw[i] ? 1 : 0;
        else                m = (((const int*)raw)[i] != 0) ? 1 : 0;
        g_mask[i] = m;
    }
}

// ===========================================================================
// Fused projection GEMM (SIMT fp32):
// z=0: x@Wq -> qh/ql (fp16 hi/lo, tile-swizzled)   z=1: x@Wk -> kh (fp16 hi)
// z=2: x@Wv -> v (fp32 row-major, head-split)
// Tile-swizzled layout: tile (z16, rt16, ch16) = 8KB block of [128r][32c] fp16,
// byte offset inside = swz(r, c*2). Matches dots SMEM stage exactly.
// ===========================================================================
__global__ __launch_bounds__(256) void proj3_kernel(
    const float* __restrict__ X,
    const float* __restrict__ Wq, const float* __restrict__ Wk, const float* __restrict__ Wv)
{
    const float* W = (blockIdx.z == 0) ? Wq : (blockIdx.z == 1) ? Wk : Wv;

    __shared__ float As[16][128];
    __shared__ float Bs[16][128];
    const int row0 = blockIdx.y * 128;
    const int col0 = blockIdx.x * 128;
    const int tid = threadIdx.x;
    const int tx = tid & 15, ty = tid >> 4;
    float acc[8][8];
#pragma unroll
    for (int i = 0; i < 8; i++)
#pragma unroll
        for (int j = 0; j < 8; j++) acc[i][j] = 0.f;

    for (int kt = 0; kt < 64; kt += 16) {
#pragma unroll
        for (int l = 0; l < 2; l++) {
            int f = tid + l * 256;
            int r = f >> 2;
            int c = (f & 3) * 4;
            float4 v = *(const float4*)(X + (size_t)(row0 + r) * 64 + kt + c);
            As[c+0][r] = v.x; As[c+1][r] = v.y; As[c+2][r] = v.z; As[c+3][r] = v.w;
        }
#pragma unroll
        for (int l = 0; l < 2; l++) {
            int f = tid + l * 256;
            int r = f >> 5;
            int c = (f & 31) * 4;
            float4 v = *(const float4*)(W + (size_t)(kt + r) * 4096 + col0 + c);
            *(float4*)&Bs[r][c] = v;
        }
        __syncthreads();
#pragma unroll
        for (int k = 0; k < 16; k++) {
            float4 a0 = *(const float4*)&As[k][ty*8];
            float4 a1 = *(const float4*)&As[k][ty*8+4];
            float4 b0 = *(const float4*)&Bs[k][tx*8];
            float4 b1 = *(const float4*)&Bs[k][tx*8+4];
            float ar[8] = {a0.x,a0.y,a0.z,a0.w,a1.x,a1.y,a1.z,a1.w};
            float br[8] = {b0.x,b0.y,b0.z,b0.w,b1.x,b1.y,b1.z,b1.w};
#pragma unroll
            for (int i = 0; i < 8; i++)
#pragma unroll
                for (int j = 0; j < 8; j++) acc[i][j] = fmaf(ar[i], br[j], acc[i][j]);
        }
        __syncthreads();
    }

    const int col = col0 + tx * 8;
    const int h = col >> 9;
    const int dd = col & 511;
    if (blockIdx.z == 2) {
#pragma unroll
        for (int i = 0; i < 8; i++) {
            int m = row0 + ty * 8 + i;
            int b = m >> 11;
            int n = m & 2047;
            float* p = g_v + (((size_t)(b * HH + h) * NN + n) * DD + dd);
            *(float4*)p       = make_float4(acc[i][0], acc[i][1], acc[i][2], acc[i][3]);
            *(float4*)(p + 4) = make_float4(acc[i][4], acc[i][5], acc[i][6], acc[i][7]);
        }
    } else {
        const int chk = dd >> 5;
        const uint32_t cb = (uint32_t)(dd & 31) * 2;
#pragma unroll
        for (int i = 0; i < 8; i++) {
            int m = row0 + ty * 8 + i;
            int b = m >> 11;
            int n = m & 2047;
            int rt = n >> 7, r = n & 127;
            int z = b * HH + h;
            size_t tb = (((size_t)z * 16 + rt) * 16 + chk) * 8192;
            uint32_t so = swz((uint32_t)r, cb);
            // hi
            __half2 h0 = __floats2half2_rn(acc[i][0], acc[i][1]);
            __half2 h1 = __floats2half2_rn(acc[i][2], acc[i][3]);
            __half2 h2 = __floats2half2_rn(acc[i][4], acc[i][5]);
            __half2 h3 = __floats2half2_rn(acc[i][6], acc[i][7]);
            uint4 hv = make_uint4(*(uint32_t*)&h0, *(uint32_t*)&h1, *(uint32_t*)&h2, *(uint32_t*)&h3);
            if (blockIdx.z == 0) {
                *(uint4*)((char*)g_qh + tb + so) = hv;
                float2 f0 = __half22float2(h0), f1 = __half22float2(h1);
                float2 f2 = __half22float2(h2), f3 = __half22float2(h3);
                __half2 l0 = __floats2half2_rn(acc[i][0]-f0.x, acc[i][1]-f0.y);
                __half2 l1 = __floats2half2_rn(acc[i][2]-f1.x, acc[i][3]-f1.y);
                __half2 l2 = __floats2half2_rn(acc[i][4]-f2.x, acc[i][5]-f2.y);
                __half2 l3 = __floats2half2_rn(acc[i][6]-f3.x, acc[i][7]-f3.y);
                uint4 lv = make_uint4(*(uint32_t*)&l0, *(uint32_t*)&l1, *(uint32_t*)&l2, *(uint32_t*)&l3);
                *(uint4*)((char*)g_ql + tb + so) = lv;
            } else {
                *(uint4*)((char*)g_kh + tb + so) = hv;
            }
        }
    }
}

// ===========================================================================
// V column-sum per (b,h)
// ===========================================================================
__global__ __launch_bounds__(256) void vsum_kernel() {
    const int z = blockIdx.y;
    const int d = blockIdx.x * 256 + threadIdx.x;
    const float* p = g_v + (size_t)z * NN * DD + d;
    float s = 0.f;
#pragma unroll 8
    for (int n = 0; n < NN; n++) s += p[(size_t)n * DD];
    g_vsum[z * DD + d] = s;
}

// ===========================================================================
// dots = scale*(Qh+Ql)@Kh^T (+mask) -> pre
// 256 threads, 8 warps (2m x 4n), warp tile 64x32, CTA tile 128x128.
// cp.async 3-stage pipeline of pre-swizzled 8KB tile blocks.
// ===========================================================================
#define DSTAGE 24576u
#define DOTS_SMEM (3 * 24576)

__global__ __launch_bounds__(256, 2) void dots_gemm(float* __restrict__ Out)
{
    extern __shared__ char sm[];
    __shared__ int cmask[128];
    const uint32_t sbase = smem_u32(sm);

    const int tid = threadIdx.x;
    const int wid = tid >> 5, lane = tid & 31;
    const int wm = wid >> 2, wn = wid & 3;
    const int z = blockIdx.z, b = z >> 3;
    const int row0 = blockIdx.y * 128, col0 = blockIdx.x * 128;

    if (tid < 128) cmask[tid] = g_mask[b * NN + col0 + tid];

    const char* qhB = (const char*)g_qh + (((size_t)z * 16 + blockIdx.y) * 16) * 8192;
    const char* qlB = (const char*)g_ql + (((size_t)z * 16 + blockIdx.y) * 16) * 8192;
    const char* khB = (const char*)g_kh + (((size_t)z * 16 + blockIdx.x) * 16) * 8192;

    float acc[4][4][4];
#pragma unroll
    for (int mf = 0; mf < 4; mf++)
#pragma unroll
        for (int nf = 0; nf < 4; nf++)
#pragma unroll
            for (int r = 0; r < 4; r++) acc[mf][nf][r] = 0.f;

    // issue stage for chunk ch
    auto issue = [&](int ch) {
        const uint32_t ss = sbase + (uint32_t)(ch % 3) * DSTAGE;
        const char* q1 = qhB + (size_t)ch * 8192;
        const char* l1 = qlB + (size_t)ch * 8192;
        const char* k1 = khB + (size_t)ch * 8192;
#pragma unroll
        for (int k = 0; k < 2; k++) {
            uint32_t off = (uint32_t)(tid + k * 256) * 16;
            CP16(ss + off,         q1 + off);
            CP16(ss + 8192 + off,  l1 + off);
            CP16(ss + 16384 + off, k1 + off);
        }
    };

    issue(0); CP_COMMIT();
    issue(1); CP_COMMIT();

    const uint32_t a_row = (uint32_t)(wm * 64) + (lane & 15);
    const uint32_t a_kb  = ((lane >> 4) & 1) * 16;
    const uint32_t b_row = (uint32_t)(wn * 32) + ((lane >> 4) & 1) * 8 + (lane & 7);
    const uint32_t b_kb  = ((lane >> 3) & 1) * 16;

    for (int ch = 0; ch < 16; ++ch) {
        CP_WAIT1();
        __syncthreads();
        const uint32_t S = sbase + (uint32_t)(ch % 3) * DSTAGE;
        const uint32_t AH = S, AL = S + 8192, BH = S + 16384;
#pragma unroll
        for (int ks = 0; ks < 2; ks++) {
            const uint32_t kb0 = (uint32_t)ks * 32;
            uint32_t bh[4][2];
#pragma unroll
            for (int p = 0; p < 2; p++) {
                uint32_t o = swz(b_row + p * 16, kb0 + b_kb);
                uint32_t t4[4];
                ldsm_x4(t4, BH + o);
                bh[2*p][0] = t4[0]; bh[2*p][1] = t4[1];
                bh[2*p+1][0] = t4[2]; bh[2*p+1][1] = t4[3];
            }
#pragma unroll
            for (int mf = 0; mf < 4; mf++) {
                uint32_t o = swz(a_row + mf * 16, kb0 + a_kb);
                uint32_t ah[4], al[4];
                ldsm_x4(ah, AH + o);
                ldsm_x4(al, AL + o);
#pragma unroll
                for (int nf = 0; nf < 4; nf++) {
                    mma_f16(acc[mf][nf], ah, bh[nf]);
                    mma_f16(acc[mf][nf], al, bh[nf]);
                }
            }
        }
        if (ch + 2 < 16) issue(ch + 2);
        CP_COMMIT();
    }

    // epilogue
    const int r_lo = row0 + wm * 64 + (lane >> 2);
    const int c_base = wn * 32 + (lane & 3) * 2;
    float* outz = Out + (size_t)z * NN * NN;
#pragma unroll
    for (int mf = 0; mf < 4; mf++) {
        int rg0 = r_lo + mf * 16;
        int m0 = g_mask[b * NN + rg0];
        int m1 = g_mask[b * NN + rg0 + 8];
#pragma unroll
        for (int nf = 0; nf < 4; nf++) {
            int cg = c_base + nf * 8;
            int cmA = cmask[cg], cmB = cmask[cg + 1];
            float2 v0, v1;
            v0.x = (m0 && cmA) ? acc[mf][nf][0] * SCALE : MASKV;
            v0.y = (m0 && cmB) ? acc[mf][nf][1] * SCALE : MASKV;
            v1.x = (m1 && cmA) ? acc[mf][nf][2] * SCALE : MASKV;
            v1.y = (m1 && cmB) ? acc[mf][nf][3] * SCALE : MASKV;
            *(float2*)(outz + (size_t)rg0 * NN + col0 + cg)       = v0;
            *(float2*)(outz + (size_t)(rg0 + 8) * NN + col0 + cg) = v1;
        }
    }
}

// ===========================================================================
// entmax-1.5: one warp per row + compact list emission
// ===========================================================================
__global__ __launch_bounds__(256) void entmax_kernel(
    const float* __restrict__ pre, float* __restrict__ att)
{
    const int wid = threadIdx.x >> 5, lane = threadIdx.x & 31;
    const size_t row = (size_t)blockIdx.x * 8 + wid;
    const int z = (int)(row >> 11), n = (int)(row & 2047), b = z >> 3;
    float4* o4 = (float4*)(att + row * NN);

    if (!g_mask[b * NN + n]) {
        const float P = 1.0f / 2048.0f;
        float4 u = make_float4(P, P, P, P);
#pragma unroll
        for (int i = 0; i < 16; i++) o4[lane + i * 32] = u;
        if (lane == 0) g_cnt[row] = -1;
        return;
    }

    const float4* p4 = (const float4*)(pre + row * NN);
    float x[64];
    float mx = -3.0e38f;
#pragma unroll
    for (int i = 0; i < 16; i++) {
        float4 v = p4[lane + i * 32];
        x[4*i+0] = 0.5f * v.x; x[4*i+1] = 0.5f * v.y;
        x[4*i+2] = 0.5f * v.z; x[4*i+3] = 0.5f * v.w;
        mx = fmaxf(mx, fmaxf(fmaxf(x[4*i], x[4*i+1]), fmaxf(x[4*i+2], x[4*i+3])));
    }
#pragma unroll
    for (int off = 16; off; off >>= 1)
        mx = fmaxf(mx, __shfl_xor_sync(0xffffffffu, mx, off));
#pragma unroll
    for (int j = 0; j < 64; j++) x[j] -= mx;

    float tau = -1.0f;
#pragma unroll 1
    for (int it = 0; it < 12; ++it) {
        float s1 = 0.f, s2 = 0.f;
#pragma unroll
        for (int j = 0; j < 64; j++) {
            float d = fmaxf(x[j] - tau, 0.f);
            s1 += d;
            s2 = fmaf(d, d, s2);
        }
#pragma unroll
        for (int off = 16; off; off >>= 1) {
            s1 += __shfl_xor_sync(0xffffffffu, s1, off);
            s2 += __shfl_xor_sync(0xffffffffu, s2, off);
        }
        float step = (s1 > 1e-20f) ? (s2 - 1.0f) / (2.0f * s1) : 0.f;
        tau += step;
    }

#pragma unroll
    for (int i = 0; i < 16; i++) {
        float4 w;
        float d;
        d = fmaxf(x[4*i+0] - tau, 0.f); w.x = d * d;
        d = fmaxf(x[4*i+1] - tau, 0.f); w.y = d * d;
        d = fmaxf(x[4*i+2] - tau, 0.f); w.z = d * d;
        d = fmaxf(x[4*i+3] - tau, 0.f); w.w = d * d;
        o4[lane + i * 32] = w;
    }

    int cl = 0;
#pragma unroll
    for (int j = 0; j < 64; j++) cl += (x[j] > tau) ? 1 : 0;
    int v = cl;
#pragma unroll
    for (int d = 1; d < 32; d <<= 1) {
        int t = __shfl_up_sync(0xffffffffu, v, d);
        if (lane >= d) v += t;
    }
    int total = __shfl_sync(0xffffffffu, v, 31);
    int pos = v - cl;
    if (total <= MAXS) {
        int*   si = g_si + row * MAXS;
        float* sw = g_sw + row * MAXS;
#pragma unroll
        for (int i = 0; i < 16; i++)
#pragma unroll
            for (int c = 0; c < 4; c++) {
                int j = 4*i + c;
                if (x[j] > tau) {
                    float d = x[j] - tau;
                    si[pos] = 4*lane + 128*i + c;
                    sw[pos] = d * d;
                    pos++;
                }
            }
        if (lane == 31) g_cnt[row] = total;
    } else if (lane == 31) {
        g_cnt[row] = -2;
    }
}

// ===========================================================================
// Sparse AV: one warp per (row, 128-d chunk)
// ===========================================================================
__global__ __launch_bounds__(256) void av_sparse_kernel(const float* __restrict__ att)
{
    const int wid = threadIdx.x >> 5, lane = threadIdx.x & 31;
    const int gw = blockIdx.x * 8 + wid;
    const int row = gw >> 2, chunk = gw & 3;
    const int z = row >> 11, n = row & 2047, b = z >> 3, h = z & 7;
    const int dbase = chunk * 128 + lane * 4;
    const float* Vz = g_v + (size_t)z * NN * DD;
    float4 acc = make_float4(0.f, 0.f, 0.f, 0.f);
    const int cnt = g_cnt[row];

    if (cnt == -1) {
        const float P = 1.0f / 2048.0f;
        float4 s = *(const float4*)(g_vsum + z * DD + dbase);
        acc = make_float4(P * s.x, P * s.y, P * s.z, P * s.w);
    } else if (cnt >= 0) {
        const int*   si = g_si + (size_t)row * MAXS;
        const float* sw = g_sw + (size_t)row * MAXS;
        int j = 0;
        for (; j + 2 <= cnt; j += 2) {
            int   i0 = si[j],   i1 = si[j+1];
            float w0 = sw[j],   w1 = sw[j+1];
            float4 v0 = *(const float4*)(Vz + (size_t)i0 * DD + dbase);
            float4 v1 = *(const float4*)(Vz + (size_t)i1 * DD + dbase);
            acc.x = fmaf(w0, v0.x, acc.x); acc.x = fmaf(w1, v1.x, acc.x);
            acc.y = fmaf(w0, v0.y, acc.y); acc.y = fmaf(w1, v1.y, acc.y);
            acc.z = fmaf(w0, v0.z, acc.z); acc.z = fmaf(w1, v1.z, acc.z);
            acc.w = fmaf(w0, v0.w, acc.w); acc.w = fmaf(w1, v1.w, acc.w);
        }
        if (j < cnt) {
            int   i0 = si[j];
            float w0 = sw[j];
            float4 v0 = *(const float4*)(Vz + (size_t)i0 * DD + dbase);
            acc.x = fmaf(w0, v0.x, acc.x);
            acc.y = fmaf(w0, v0.y, acc.y);
            acc.z = fmaf(w0, v0.z, acc.z);
            acc.w = fmaf(w0, v0.w, acc.w);
        }
    } else {  // dense fallback
        const float* arow = att + (size_t)row * NN;
        for (int c = 0; c < NN; c++) {
            float p = arow[c];
            if (p != 0.f) {
                float4 v0 = *(const float4*)(Vz + (size_t)c * DD + dbase);
                acc.x = fmaf(p, v0.x, acc.x);
                acc.y = fmaf(p, v0.y, acc.y);
                acc.z = fmaf(p, v0.z, acc.z);
                acc.w = fmaf(p, v0.w, acc.w);
            }
        }
    }
    *(float4*)(g_ctx + ((size_t)(b * NN + n)) * INNER + (size_t)h * DD + dbase) = acc;
}

// ===========================================================================
// final split-K: partial[ks] = ctx[:, ks*1024:(ks+1)*1024] @ Wo[ks*1024:...]
// ===========================================================================
__global__ __launch_bounds__(256) void final_part_kernel(const float* __restrict__ Wo)
{
    __shared__ float As[32][32];
    __shared__ float Ws[32][64];
    const int row0 = blockIdx.x * 32;
    const int ks = blockIdx.y;
    const int tid = threadIdx.x;
    const int tx = tid & 15, ty = tid >> 4;
    float acc[2][4] = {{0.f,0.f,0.f,0.f},{0.f,0.f,0.f,0.f}};

    const int k0 = ks * 1024;
    for (int kt = k0; kt < k0 + 1024; kt += 32) {
        {
            int r = tid >> 3;
            int c = (tid & 7) * 4;
            float4 v = *(const float4*)(g_ctx + (size_t)(row0 + r) * INNER + kt + c);
            As[c+0][r] = v.x; As[c+1][r] = v.y; As[c+2][r] = v.z; As[c+3][r] = v.w;
        }
#pragma unroll
        for (int l = 0; l < 2; l++) {
            int f = tid + l * 256;
            int r = f >> 4;
            int c = (f & 15) * 4;
            float4 v = *(const float4*)(Wo + (size_t)(kt + r) * 64 + c);
            *(float4*)&Ws[r][c] = v;
        }
        __syncthreads();
#pragma unroll
        for (int k = 0; k < 32; k++) {
            float a0 = As[k][ty*2 + 0];
            float a1 = As[k][ty*2 + 1];
            float4 w = *(const float4*)&Ws[k][tx*4];
            float wr[4] = {w.x, w.y, w.z, w.w};
#pragma unroll
            for (int j = 0; j < 4; j++) {
                acc[0][j] = fmaf(a0, wr[j], acc[0][j]);
                acc[1][j] = fmaf(a1, wr[j], acc[1][j]);
            }
        }
        __syncthreads();
    }
#pragma unroll
    for (int i = 0; i < 2; i++) {
        int m = row0 + ty * 2 + i;
        float* p = g_fpart[ks] + (size_t)m * 64 + tx * 4;
        *(float4*)p = make_float4(acc[i][0], acc[i][1], acc[i][2], acc[i][3]);
    }
}

__global__ __launch_bounds__(256) void final_reduce_kernel(
    const float* __restrict__ bo, float* __restrict__ out)
{
    const int j = blockIdx.x * 256 + threadIdx.x;   // float4 index
    const int col4 = j & 15;
    float4 b4 = ((const float4*)bo)[col4];
    float4 p0 = ((const float4*)g_fpart[0])[j];
    float4 p1 = ((const float4*)g_fpart[1])[j];
    float4 p2 = ((const float4*)g_fpart[2])[j];
    float4 p3 = ((const float4*)g_fpart[3])[j];
    float4 r;
    r.x = p0.x + p1.x + p2.x + p3.x + b4.x;
    r.y = p0.y + p1.y + p2.y + p3.y + b4.y;
    r.z = p0.z + p1.z + p2.z + p3.z + b4.z;
    r.w = p0.w + p1.w + p2.w + p3.w + b4.w;
    ((float4*)out)[j] = r;
}

// ===========================================================================
extern "C" void kernel_launch(void* const* d_in, const int* in_sizes, int n_in,
                              void* d_out, int out_size)
{
    const float* x   = (const float*)d_in[0];
    const unsigned char* mask_raw = (const unsigned char*)d_in[1];
    const float* Wq  = (const float*)d_in[2];
    const float* Wk  = (const float*)d_in[3];
    const float* Wv  = (const float*)d_in[4];
    const float* Wo  = (const float*)d_in[5];
    const float* bo  = (const float*)d_in[6];

    float* out = (float*)d_out;
    float* pre = out + OUT_ELEMS;
    float* att = pre + PRE_ELEMS;

    static int smem_set = 0;
    if (!smem_set) {
        cudaFuncSetAttribute(dots_gemm,
                             cudaFuncAttributeMaxDynamicSharedMemorySize, DOTS_SMEM);
        smem_set = 1;
    }

    prep_mask_kernel<<<1, 256>>>(mask_raw);

    proj3_kernel<<<dim3(32, 32, 3), 256>>>(x, Wq, Wk, Wv);

    vsum_kernel<<<dim3(2, 16), 256>>>();

    dots_gemm<<<dim3(16, 16, 16), 256, DOTS_SMEM>>>(pre);

    entmax_kernel<<<BB * HH * NN / 8, 256>>>(pre, att);

    av_sparse_kernel<<<NROWS * 4 / 8, 256>>>(att);

    final_part_kernel<<<dim3(128, 4), 256>>>(Wo);
    final_reduce_kernel<<<OUT_ELEMS / 4 / 256, 256>>>(bo, out);
}

// round 8
// speedup vs baseline: 5.5317x; 1.1656x over previous
#include <cuda_runtime.h>
#include <cuda_bf16.h>
#include <cuda_fp16.h>
#include <cstdint>

// Problem constants
#define BB 2
#define NN 2048
#define DIMX 64
#define HH 8
#define DD 512            // per-head dim
#define INNER 4096
#define SCALE 0.125f
#define MASKV -1e9f

#define OUT_ELEMS   (BB*NN*DIMX)          // 262144
#define PRE_ELEMS   (BB*HH*NN*NN)         // 67108864

#define NROWS (BB*HH*NN)   // 32768
#define NZ    (BB*HH)      // 16
#define MAXS  512

// Scratch
__device__ __half g_qh[BB*HH*NN*DD];
__device__ __half g_ql[BB*HH*NN*DD];
__device__ __half g_kh[BB*HH*NN*DD];
__device__ float  g_v[BB*HH*NN*DD];
__device__ float  g_p[(size_t)NZ * NN * 64];    // P[z] = V_z @ Wo_head  (8MB)
__device__ float  g_psum[NZ * 64];
__device__ int    g_mask[BB*NN];
__device__ int    g_si[(size_t)NROWS * MAXS];
__device__ float  g_sw[(size_t)NROWS * MAXS];
__device__ int    g_cnt[NROWS];

// ===========================================================================
// Helpers (baseline PTX: ldmatrix sm_75+, mma.sync fp16 sm_80+, cp.async sm_80+)
// ===========================================================================
__device__ __forceinline__ uint32_t smem_u32(const void* p) {
    uint32_t r;
    asm("{ .reg .u64 t; cvta.to.shared.u64 t, %1; cvt.u32.u64 %0, t; }" : "=r"(r) : "l"(p));
    return r;
}
__device__ __forceinline__ void ldsm_x4(uint32_t* r, uint32_t addr) {
    asm volatile("ldmatrix.sync.aligned.m8n8.x4.shared.b16 {%0,%1,%2,%3}, [%4];"
        : "=r"(r[0]), "=r"(r[1]), "=r"(r[2]), "=r"(r[3]) : "r"(addr));
}
__device__ __forceinline__ void mma_f16(float* c, const uint32_t* a, const uint32_t* b) {
    asm volatile("mma.sync.aligned.m16n8k16.row.col.f32.f16.f16.f32 "
        "{%0,%1,%2,%3}, {%4,%5,%6,%7}, {%8,%9}, {%0,%1,%2,%3};"
        : "+f"(c[0]), "+f"(c[1]), "+f"(c[2]), "+f"(c[3])
        : "r"(a[0]), "r"(a[1]), "r"(a[2]), "r"(a[3]), "r"(b[0]), "r"(b[1]));
}
#define CP16(saddr, gptr) \
    asm volatile("cp.async.cg.shared.global [%0], [%1], 16;" :: "r"(saddr), "l"(gptr))
#define CP_COMMIT() asm volatile("cp.async.commit_group;")
#define CP_WAIT2()  asm volatile("cp.async.wait_group 2;")

// swizzled byte offset inside a [128 rows][32 cols] fp16 tile, 64B rows
__device__ __forceinline__ uint32_t swz(uint32_t r, uint32_t kb) {
    uint32_t off = r * 64u + kb;
    return off ^ ((off >> 3) & 0x70u);
}

// ===========================================================================
// Mask prep (dtype detect)
// ===========================================================================
__global__ void prep_mask_kernel(const unsigned char* __restrict__ raw) {
    __shared__ int cnt_f32, cnt_gt1;
    if (threadIdx.x == 0) { cnt_f32 = 0; cnt_gt1 = 0; }
    __syncthreads();
    const unsigned int* u = (const unsigned int*)raw;
    int lf = 0, lg = 0;
    for (int i = threadIdx.x; i < 1024; i += blockDim.x) {
        unsigned int v = u[i];
        if (v == 0x3f800000u) lf++;
        else if (v > 1u) lg++;
    }
    atomicAdd(&cnt_f32, lf);
    atomicAdd(&cnt_gt1, lg);
    __syncthreads();
    int mode;
    if (cnt_f32 > 64) mode = 2;
    else if (cnt_gt1 > 64) mode = 1;
    else mode = 0;
    for (int i = threadIdx.x; i < BB*NN; i += blockDim.x) {
        int m;
        if (mode == 2)      m = (((const unsigned int*)raw)[i] != 0u) ? 1 : 0;
        else if (mode == 1) m = raw[i] ? 1 : 0;
        else                m = (((const int*)raw)[i] != 0) ? 1 : 0;
        g_mask[i] = m;
    }
}

// ===========================================================================
// Fused projection GEMM (SIMT fp32):
// z=0: x@Wq -> qh/ql (fp16 hi/lo, tile-swizzled)   z=1: x@Wk -> kh (fp16 hi)
// z=2: x@Wv -> v (fp32 row-major, head-split)
// ===========================================================================
__global__ __launch_bounds__(256) void proj3_kernel(
    const float* __restrict__ X,
    const float* __restrict__ Wq, const float* __restrict__ Wk, const float* __restrict__ Wv)
{
    const float* W = (blockIdx.z == 0) ? Wq : (blockIdx.z == 1) ? Wk : Wv;

    __shared__ float As[16][128];
    __shared__ float Bs[16][128];
    const int row0 = blockIdx.y * 128;
    const int col0 = blockIdx.x * 128;
    const int tid = threadIdx.x;
    const int tx = tid & 15, ty = tid >> 4;
    float acc[8][8];
#pragma unroll
    for (int i = 0; i < 8; i++)
#pragma unroll
        for (int j = 0; j < 8; j++) acc[i][j] = 0.f;

    for (int kt = 0; kt < 64; kt += 16) {
#pragma unroll
        for (int l = 0; l < 2; l++) {
            int f = tid + l * 256;
            int r = f >> 2;
            int c = (f & 3) * 4;
            float4 v = *(const float4*)(X + (size_t)(row0 + r) * 64 + kt + c);
            As[c+0][r] = v.x; As[c+1][r] = v.y; As[c+2][r] = v.z; As[c+3][r] = v.w;
        }
#pragma unroll
        for (int l = 0; l < 2; l++) {
            int f = tid + l * 256;
            int r = f >> 5;
            int c = (f & 31) * 4;
            float4 v = *(const float4*)(W + (size_t)(kt + r) * 4096 + col0 + c);
            *(float4*)&Bs[r][c] = v;
        }
        __syncthreads();
#pragma unroll
        for (int k = 0; k < 16; k++) {
            float4 a0 = *(const float4*)&As[k][ty*8];
            float4 a1 = *(const float4*)&As[k][ty*8+4];
            float4 b0 = *(const float4*)&Bs[k][tx*8];
            float4 b1 = *(const float4*)&Bs[k][tx*8+4];
            float ar[8] = {a0.x,a0.y,a0.z,a0.w,a1.x,a1.y,a1.z,a1.w};
            float br[8] = {b0.x,b0.y,b0.z,b0.w,b1.x,b1.y,b1.z,b1.w};
#pragma unroll
            for (int i = 0; i < 8; i++)
#pragma unroll
                for (int j = 0; j < 8; j++) acc[i][j] = fmaf(ar[i], br[j], acc[i][j]);
        }
        __syncthreads();
    }

    const int col = col0 + tx * 8;
    const int h = col >> 9;
    const int dd = col & 511;
    if (blockIdx.z == 2) {
#pragma unroll
        for (int i = 0; i < 8; i++) {
            int m = row0 + ty * 8 + i;
            int b = m >> 11;
            int n = m & 2047;
            float* p = g_v + (((size_t)(b * HH + h) * NN + n) * DD + dd);
            *(float4*)p       = make_float4(acc[i][0], acc[i][1], acc[i][2], acc[i][3]);
            *(float4*)(p + 4) = make_float4(acc[i][4], acc[i][5], acc[i][6], acc[i][7]);
        }
    } else {
        const int chk = dd >> 5;
        const uint32_t cb = (uint32_t)(dd & 31) * 2;
#pragma unroll
        for (int i = 0; i < 8; i++) {
            int m = row0 + ty * 8 + i;
            int b = m >> 11;
            int n = m & 2047;
            int rt = n >> 7, r = n & 127;
            int z = b * HH + h;
            size_t tb = (((size_t)z * 16 + rt) * 16 + chk) * 8192;
            uint32_t so = swz((uint32_t)r, cb);
            __half2 h0 = __floats2half2_rn(acc[i][0], acc[i][1]);
            __half2 h1 = __floats2half2_rn(acc[i][2], acc[i][3]);
            __half2 h2 = __floats2half2_rn(acc[i][4], acc[i][5]);
            __half2 h3 = __floats2half2_rn(acc[i][6], acc[i][7]);
            uint4 hv = make_uint4(*(uint32_t*)&h0, *(uint32_t*)&h1, *(uint32_t*)&h2, *(uint32_t*)&h3);
            if (blockIdx.z == 0) {
                *(uint4*)((char*)g_qh + tb + so) = hv;
                float2 f0 = __half22float2(h0), f1 = __half22float2(h1);
                float2 f2 = __half22float2(h2), f3 = __half22float2(h3);
                __half2 l0 = __floats2half2_rn(acc[i][0]-f0.x, acc[i][1]-f0.y);
                __half2 l1 = __floats2half2_rn(acc[i][2]-f1.x, acc[i][3]-f1.y);
                __half2 l2 = __floats2half2_rn(acc[i][4]-f2.x, acc[i][5]-f2.y);
                __half2 l3 = __floats2half2_rn(acc[i][6]-f3.x, acc[i][7]-f3.y);
                uint4 lv = make_uint4(*(uint32_t*)&l0, *(uint32_t*)&l1, *(uint32_t*)&l2, *(uint32_t*)&l3);
                *(uint4*)((char*)g_ql + tb + so) = lv;
            } else {
                *(uint4*)((char*)g_kh + tb + so) = hv;
            }
        }
    }
}

// ===========================================================================
// P[z] = V_z @ Wo_head : per z (b,h), (2048 x 512) @ (512 x 64)
// BM=32, BN=64, BK=32; grid (64, 16)
// ===========================================================================
__global__ __launch_bounds__(256) void pvw_kernel(const float* __restrict__ Wo)
{
    __shared__ float As[32][32];
    __shared__ float Ws[32][64];
    const int z = blockIdx.y, h = z & 7;
    const int row0 = blockIdx.x * 32;
    const int tid = threadIdx.x;
    const int tx = tid & 15, ty = tid >> 4;
    const float* A = g_v + (size_t)z * NN * DD;
    const float* W = Wo + (size_t)h * DD * 64;
    float acc[2][4] = {{0.f,0.f,0.f,0.f},{0.f,0.f,0.f,0.f}};

    for (int kt = 0; kt < DD; kt += 32) {
        {
            int r = tid >> 3;
            int c = (tid & 7) * 4;
            float4 v = *(const float4*)(A + (size_t)(row0 + r) * DD + kt + c);
            As[c+0][r] = v.x; As[c+1][r] = v.y; As[c+2][r] = v.z; As[c+3][r] = v.w;
        }
#pragma unroll
        for (int l = 0; l < 2; l++) {
            int f = tid + l * 256;
            int r = f >> 4;
            int c = (f & 15) * 4;
            float4 v = *(const float4*)(W + (size_t)(kt + r) * 64 + c);
            *(float4*)&Ws[r][c] = v;
        }
        __syncthreads();
#pragma unroll
        for (int k = 0; k < 32; k++) {
            float a0 = As[k][ty*2 + 0];
            float a1 = As[k][ty*2 + 1];
            float4 w = *(const float4*)&Ws[k][tx*4];
            float wr[4] = {w.x, w.y, w.z, w.w};
#pragma unroll
            for (int j = 0; j < 4; j++) {
                acc[0][j] = fmaf(a0, wr[j], acc[0][j]);
                acc[1][j] = fmaf(a1, wr[j], acc[1][j]);
            }
        }
        __syncthreads();
    }
#pragma unroll
    for (int i = 0; i < 2; i++) {
        int m = row0 + ty * 2 + i;
        float* p = g_p + ((size_t)z * NN + m) * 64 + tx * 4;
        *(float4*)p = make_float4(acc[i][0], acc[i][1], acc[i][2], acc[i][3]);
    }
}

// ===========================================================================
// psum[z][d] = sum_n P[z][n][d]   (for masked-row uniform attention)
// ===========================================================================
__global__ __launch_bounds__(256) void psum_kernel()
{
    __shared__ float red[4][64];
    const int z = blockIdx.x;
    const int d = threadIdx.x & 63, seg = threadIdx.x >> 6;
    const float* p = g_p + (size_t)z * NN * 64 + (size_t)seg * 512 * 64 + d;
    float s = 0.f;
#pragma unroll 8
    for (int n = 0; n < 512; n++) s += p[(size_t)n * 64];
    red[seg][d] = s;
    __syncthreads();
    if (threadIdx.x < 64)
        g_psum[z * 64 + d] = red[0][d] + red[1][d] + red[2][d] + red[3][d];
}

// ===========================================================================
// dots = scale*(Qh+Ql)@Kh^T (+mask) -> pre
// 256 threads, 8 warps (2m x 4n), warp tile 64x32, CTA tile 128x128.
// cp.async 4-stage pipeline of pre-swizzled 8KB tile blocks.
// ===========================================================================
#define DSTAGE 24576u
#define DOTS_SMEM (4 * 24576)

__global__ __launch_bounds__(256, 2) void dots_gemm(float* __restrict__ Out)
{
    extern __shared__ char sm[];
    __shared__ int cmask[128];
    const uint32_t sbase = smem_u32(sm);

    const int tid = threadIdx.x;
    const int wid = tid >> 5, lane = tid & 31;
    const int wm = wid >> 2, wn = wid & 3;
    const int z = blockIdx.z, b = z >> 3;
    const int row0 = blockIdx.y * 128, col0 = blockIdx.x * 128;

    if (tid < 128) cmask[tid] = g_mask[b * NN + col0 + tid];

    const char* qhB = (const char*)g_qh + (((size_t)z * 16 + blockIdx.y) * 16) * 8192;
    const char* qlB = (const char*)g_ql + (((size_t)z * 16 + blockIdx.y) * 16) * 8192;
    const char* khB = (const char*)g_kh + (((size_t)z * 16 + blockIdx.x) * 16) * 8192;

    float acc[4][4][4];
#pragma unroll
    for (int mf = 0; mf < 4; mf++)
#pragma unroll
        for (int nf = 0; nf < 4; nf++)
#pragma unroll
            for (int r = 0; r < 4; r++) acc[mf][nf][r] = 0.f;

    auto issue = [&](int ch) {
        const uint32_t ss = sbase + (uint32_t)(ch & 3) * DSTAGE;
        const char* q1 = qhB + (size_t)ch * 8192;
        const char* l1 = qlB + (size_t)ch * 8192;
        const char* k1 = khB + (size_t)ch * 8192;
#pragma unroll
        for (int k = 0; k < 2; k++) {
            uint32_t off = (uint32_t)(tid + k * 256) * 16;
            CP16(ss + off,         q1 + off);
            CP16(ss + 8192 + off,  l1 + off);
            CP16(ss + 16384 + off, k1 + off);
        }
    };

    issue(0); CP_COMMIT();
    issue(1); CP_COMMIT();
    issue(2); CP_COMMIT();

    const uint32_t a_row = (uint32_t)(wm * 64) + (lane & 15);
    const uint32_t a_kb  = ((lane >> 4) & 1) * 16;
    const uint32_t b_row = (uint32_t)(wn * 32) + ((lane >> 4) & 1) * 8 + (lane & 7);
    const uint32_t b_kb  = ((lane >> 3) & 1) * 16;

    for (int ch = 0; ch < 16; ++ch) {
        CP_WAIT2();
        __syncthreads();
        const uint32_t S = sbase + (uint32_t)(ch & 3) * DSTAGE;
        const uint32_t AH = S, AL = S + 8192, BH = S + 16384;
#pragma unroll
        for (int ks = 0; ks < 2; ks++) {
            const uint32_t kb0 = (uint32_t)ks * 32;
            uint32_t bh[4][2];
#pragma unroll
            for (int p = 0; p < 2; p++) {
                uint32_t o = swz(b_row + p * 16, kb0 + b_kb);
                uint32_t t4[4];
                ldsm_x4(t4, BH + o);
                bh[2*p][0] = t4[0]; bh[2*p][1] = t4[1];
                bh[2*p+1][0] = t4[2]; bh[2*p+1][1] = t4[3];
            }
#pragma unroll
            for (int mf = 0; mf < 4; mf++) {
                uint32_t o = swz(a_row + mf * 16, kb0 + a_kb);
                uint32_t ah[4], al[4];
                ldsm_x4(ah, AH + o);
                ldsm_x4(al, AL + o);
#pragma unroll
                for (int nf = 0; nf < 4; nf++) {
                    mma_f16(acc[mf][nf], ah, bh[nf]);
                    mma_f16(acc[mf][nf], al, bh[nf]);
                }
            }
        }
        if (ch + 3 < 16) issue(ch + 3);
        CP_COMMIT();
    }

    const int r_lo = row0 + wm * 64 + (lane >> 2);
    const int c_base = wn * 32 + (lane & 3) * 2;
    float* outz = Out + (size_t)z * NN * NN;
#pragma unroll
    for (int mf = 0; mf < 4; mf++) {
        int rg0 = r_lo + mf * 16;
        int m0 = g_mask[b * NN + rg0];
        int m1 = g_mask[b * NN + rg0 + 8];
#pragma unroll
        for (int nf = 0; nf < 4; nf++) {
            int cg = c_base + nf * 8;
            int cmA = cmask[cg], cmB = cmask[cg + 1];
            float2 v0, v1;
            v0.x = (m0 && cmA) ? acc[mf][nf][0] * SCALE : MASKV;
            v0.y = (m0 && cmB) ? acc[mf][nf][1] * SCALE : MASKV;
            v1.x = (m1 && cmA) ? acc[mf][nf][2] * SCALE : MASKV;
            v1.y = (m1 && cmB) ? acc[mf][nf][3] * SCALE : MASKV;
            *(float2*)(outz + (size_t)rg0 * NN + col0 + cg)       = v0;
            *(float2*)(outz + (size_t)(rg0 + 8) * NN + col0 + cg) = v1;
        }
    }
}

// ===========================================================================
// entmax-1.5: one warp per row + compact list emission
// ===========================================================================
__global__ __launch_bounds__(256) void entmax_kernel(
    const float* __restrict__ pre, float* __restrict__ att)
{
    const int wid = threadIdx.x >> 5, lane = threadIdx.x & 31;
    const size_t row = (size_t)blockIdx.x * 8 + wid;
    const int z = (int)(row >> 11), n = (int)(row & 2047), b = z >> 3;
    float4* o4 = (float4*)(att + row * NN);

    if (!g_mask[b * NN + n]) {
        const float P = 1.0f / 2048.0f;
        float4 u = make_float4(P, P, P, P);
#pragma unroll
        for (int i = 0; i < 16; i++) o4[lane + i * 32] = u;
        if (lane == 0) g_cnt[row] = -1;
        return;
    }

    const float4* p4 = (const float4*)(pre + row * NN);
    float x[64];
    float mx = -3.0e38f;
#pragma unroll
    for (int i = 0; i < 16; i++) {
        float4 v = p4[lane + i * 32];
        x[4*i+0] = 0.5f * v.x; x[4*i+1] = 0.5f * v.y;
        x[4*i+2] = 0.5f * v.z; x[4*i+3] = 0.5f * v.w;
        mx = fmaxf(mx, fmaxf(fmaxf(x[4*i], x[4*i+1]), fmaxf(x[4*i+2], x[4*i+3])));
    }
#pragma unroll
    for (int off = 16; off; off >>= 1)
        mx = fmaxf(mx, __shfl_xor_sync(0xffffffffu, mx, off));
#pragma unroll
    for (int j = 0; j < 64; j++) x[j] -= mx;

    float tau = -1.0f;
#pragma unroll 1
    for (int it = 0; it < 12; ++it) {
        float s1 = 0.f, s2 = 0.f;
#pragma unroll
        for (int j = 0; j < 64; j++) {
            float d = fmaxf(x[j] - tau, 0.f);
            s1 += d;
            s2 = fmaf(d, d, s2);
        }
#pragma unroll
        for (int off = 16; off; off >>= 1) {
            s1 += __shfl_xor_sync(0xffffffffu, s1, off);
            s2 += __shfl_xor_sync(0xffffffffu, s2, off);
        }
        float step = (s1 > 1e-20f) ? (s2 - 1.0f) / (2.0f * s1) : 0.f;
        tau += step;
    }

#pragma unroll
    for (int i = 0; i < 16; i++) {
        float4 w;
        float d;
        d = fmaxf(x[4*i+0] - tau, 0.f); w.x = d * d;
        d = fmaxf(x[4*i+1] - tau, 0.f); w.y = d * d;
        d = fmaxf(x[4*i+2] - tau, 0.f); w.z = d * d;
        d = fmaxf(x[4*i+3] - tau, 0.f); w.w = d * d;
        o4[lane + i * 32] = w;
    }

    int cl = 0;
#pragma unroll
    for (int j = 0; j < 64; j++) cl += (x[j] > tau) ? 1 : 0;
    int v = cl;
#pragma unroll
    for (int d = 1; d < 32; d <<= 1) {
        int t = __shfl_up_sync(0xffffffffu, v, d);
        if (lane >= d) v += t;
    }
    int total = __shfl_sync(0xffffffffu, v, 31);
    int pos = v - cl;
    if (total <= MAXS) {
        int*   si = g_si + row * MAXS;
        float* sw = g_sw + row * MAXS;
#pragma unroll
        for (int i = 0; i < 16; i++)
#pragma unroll
            for (int c = 0; c < 4; c++) {
                int j = 4*i + c;
                if (x[j] > tau) {
                    float d = x[j] - tau;
                    si[pos] = 4*lane + 128*i + c;
                    sw[pos] = d * d;
                    pos++;
                }
            }
        if (lane == 31) g_cnt[row] = total;
    } else if (lane == 31) {
        g_cnt[row] = -2;
    }
}

// ===========================================================================
// Fused sparse attention-out: out[b,n,:] = bo + sum_h sum_j w_j * P[z][idx_j][:]
// One warp per (b,n) row; lane handles 2 columns.
// ===========================================================================
__global__ __launch_bounds__(256) void af_kernel(
    const float* __restrict__ att, const float* __restrict__ bo, float* __restrict__ out)
{
    const int wid = threadIdx.x >> 5, lane = threadIdx.x & 31;
    const int gw = blockIdx.x * 8 + wid;        // row index b*2048+n
    const int b = gw >> 11, n = gw & 2047;
    const int dc = lane * 2;

    float2 acc;
    float2 bb = *(const float2*)(bo + dc);
    acc.x = bb.x; acc.y = bb.y;

#pragma unroll 1
    for (int h = 0; h < HH; h++) {
        const int z = b * HH + h;
        const size_t row = (size_t)z * NN + n;
        const int cnt = g_cnt[row];
        const float* Pz = g_p + (size_t)z * NN * 64;
        if (cnt == -1) {
            const float Pu = 1.0f / 2048.0f;
            float2 s = *(const float2*)(g_psum + z * 64 + dc);
            acc.x = fmaf(Pu, s.x, acc.x);
            acc.y = fmaf(Pu, s.y, acc.y);
        } else if (cnt >= 0) {
            const int*   si = g_si + row * MAXS;
            const float* sw = g_sw + row * MAXS;
            for (int j = 0; j < cnt; j++) {
                int   i0 = si[j];
                float w0 = sw[j];
                float2 v = *(const float2*)(Pz + (size_t)i0 * 64 + dc);
                acc.x = fmaf(w0, v.x, acc.x);
                acc.y = fmaf(w0, v.y, acc.y);
            }
        } else {  // dense fallback
            const float* arow = att + row * NN;
            for (int c = 0; c < NN; c++) {
                float p = arow[c];
                if (p != 0.f) {
                    float2 v = *(const float2*)(Pz + (size_t)c * 64 + dc);
                    acc.x = fmaf(p, v.x, acc.x);
                    acc.y = fmaf(p, v.y, acc.y);
                }
            }
        }
    }
    *(float2*)(out + (size_t)gw * 64 + dc) = acc;
}

// ===========================================================================
extern "C" void kernel_launch(void* const* d_in, const int* in_sizes, int n_in,
                              void* d_out, int out_size)
{
    const float* x   = (const float*)d_in[0];
    const unsigned char* mask_raw = (const unsigned char*)d_in[1];
    const float* Wq  = (const float*)d_in[2];
    const float* Wk  = (const float*)d_in[3];
    const float* Wv  = (const float*)d_in[4];
    const float* Wo  = (const float*)d_in[5];
    const float* bo  = (const float*)d_in[6];

    float* out = (float*)d_out;
    float* pre = out + OUT_ELEMS;
    float* att = pre + PRE_ELEMS;

    static int smem_set = 0;
    if (!smem_set) {
        cudaFuncSetAttribute(dots_gemm,
                             cudaFuncAttributeMaxDynamicSharedMemorySize, DOTS_SMEM);
        smem_set = 1;
    }

    prep_mask_kernel<<<1, 256>>>(mask_raw);

    proj3_kernel<<<dim3(32, 32, 3), 256>>>(x, Wq, Wk, Wv);

    pvw_kernel<<<dim3(64, 16), 256>>>(Wo);
    psum_kernel<<<16, 256>>>();

    dots_gemm<<<dim3(16, 16, 16), 256, DOTS_SMEM>>>(pre);

    entmax_kernel<<<BB * HH * NN / 8, 256>>>(pre, att);

    af_kernel<<<BB * NN / 8, 256>>>(att, bo, out);
}

// round 9
// speedup vs baseline: 6.2593x; 1.1315x over previous
#include <cuda_runtime.h>
#include <cuda_bf16.h>
#include <cuda_fp16.h>
#include <cstdint>

// Problem constants
#define BB 2
#define NN 2048
#define DIMX 64
#define HH 8
#define DD 512            // per-head dim
#define INNER 4096
#define SCALE 0.125f
#define MASKV -1e9f

#define OUT_ELEMS   (BB*NN*DIMX)          // 262144
#define PRE_ELEMS   (BB*HH*NN*NN)         // 67108864

#define NROWS (BB*HH*NN)   // 32768
#define NZ    (BB*HH)      // 16
#define MAXS  512

// Scratch
__device__ __half g_qh[BB*HH*NN*DD];
__device__ __half g_ql[BB*HH*NN*DD];
__device__ __half g_kh[BB*HH*NN*DD];
__device__ __half g_xh[4096*64];
__device__ __half g_xl[4096*64];
__device__ __half g_wh[12288*64];
__device__ __half g_wl[12288*64];
__device__ float  g_v[BB*HH*NN*DD];
__device__ float  g_p[(size_t)NZ * NN * 64];    // P[z] = V_z @ Wo_head  (8MB)
__device__ float  g_psum[NZ * 64];
__device__ float  g_psumP[NZ][8][64];
__device__ int    g_mask[BB*NN];
__device__ int    g_si[(size_t)NROWS * MAXS];
__device__ float  g_sw[(size_t)NROWS * MAXS];
__device__ int    g_cnt[NROWS];

// ===========================================================================
// Helpers (baseline PTX: ldmatrix sm_75+, mma.sync fp16 sm_80+, cp.async sm_80+)
// ===========================================================================
__device__ __forceinline__ uint32_t smem_u32(const void* p) {
    uint32_t r;
    asm("{ .reg .u64 t; cvta.to.shared.u64 t, %1; cvt.u32.u64 %0, t; }" : "=r"(r) : "l"(p));
    return r;
}
__device__ __forceinline__ void ldsm_x4(uint32_t* r, uint32_t addr) {
    asm volatile("ldmatrix.sync.aligned.m8n8.x4.shared.b16 {%0,%1,%2,%3}, [%4];"
        : "=r"(r[0]), "=r"(r[1]), "=r"(r[2]), "=r"(r[3]) : "r"(addr));
}
__device__ __forceinline__ void mma_f16(float* c, const uint32_t* a, const uint32_t* b) {
    asm volatile("mma.sync.aligned.m16n8k16.row.col.f32.f16.f16.f32 "
        "{%0,%1,%2,%3}, {%4,%5,%6,%7}, {%8,%9}, {%0,%1,%2,%3};"
        : "+f"(c[0]), "+f"(c[1]), "+f"(c[2]), "+f"(c[3])
        : "r"(a[0]), "r"(a[1]), "r"(a[2]), "r"(a[3]), "r"(b[0]), "r"(b[1]));
}
#define CP16(saddr, gptr) \
    asm volatile("cp.async.cg.shared.global [%0], [%1], 16;" :: "r"(saddr), "l"(gptr))
#define CP_COMMIT() asm volatile("cp.async.commit_group;")
#define CP_WAIT2()  asm volatile("cp.async.wait_group 2;")
#define CP_WAIT0()  asm volatile("cp.async.wait_group 0;")

// swizzled byte offset inside a [128 rows][32 cols] fp16 tile, 64B rows
__device__ __forceinline__ uint32_t swz(uint32_t r, uint32_t kb) {
    uint32_t off = r * 64u + kb;
    return off ^ ((off >> 3) & 0x70u);
}
// fp16 hi/lo split of float4
__device__ __forceinline__ void split4h(float4 v, uint2& hh, uint2& ll) {
    __half2 h01 = __floats2half2_rn(v.x, v.y);
    __half2 h23 = __floats2half2_rn(v.z, v.w);
    float2 f01 = __half22float2(h01);
    float2 f23 = __half22float2(h23);
    __half2 l01 = __floats2half2_rn(v.x - f01.x, v.y - f01.y);
    __half2 l23 = __floats2half2_rn(v.z - f23.x, v.w - f23.y);
    hh.x = *(uint32_t*)&h01; hh.y = *(uint32_t*)&h23;
    ll.x = *(uint32_t*)&l01; ll.y = *(uint32_t*)&l23;
}

// ===========================================================================
// Mask prep (dtype detect)
// ===========================================================================
__global__ void prep_mask_kernel(const unsigned char* __restrict__ raw) {
    __shared__ int cnt_f32, cnt_gt1;
    if (threadIdx.x == 0) { cnt_f32 = 0; cnt_gt1 = 0; }
    __syncthreads();
    const unsigned int* u = (const unsigned int*)raw;
    int lf = 0, lg = 0;
    for (int i = threadIdx.x; i < 1024; i += blockDim.x) {
        unsigned int v = u[i];
        if (v == 0x3f800000u) lf++;
        else if (v > 1u) lg++;
    }
    atomicAdd(&cnt_f32, lf);
    atomicAdd(&cnt_gt1, lg);
    __syncthreads();
    int mode;
    if (cnt_f32 > 64) mode = 2;
    else if (cnt_gt1 > 64) mode = 1;
    else mode = 0;
    for (int i = threadIdx.x; i < BB*NN; i += blockDim.x) {
        int m;
        if (mode == 2)      m = (((const unsigned int*)raw)[i] != 0u) ? 1 : 0;
        else if (mode == 1) m = raw[i] ? 1 : 0;
        else                m = (((const int*)raw)[i] != 0) ? 1 : 0;
        g_mask[i] = m;
    }
}

// ===========================================================================
// conv_x: split x [4096,64] fp32 -> xh/xl fp16 tile-swizzled
// ===========================================================================
__global__ __launch_bounds__(256) void conv_x_kernel(const float* __restrict__ X) {
    int idx = blockIdx.x * 256 + threadIdx.x;    // float4 index, 65536 total
    int m = idx >> 4;
    int k = (idx & 15) * 4;
    float4 v = ((const float4*)X)[idx];
    uint2 hh, ll;
    split4h(v, hh, ll);
    size_t tb = ((size_t)(m >> 7) * 2 + (k >> 5)) * 8192;
    uint32_t so = swz((uint32_t)(m & 127), (uint32_t)(k & 31) * 2);
    *(uint2*)((char*)g_xh + tb + so) = hh;
    *(uint2*)((char*)g_xl + tb + so) = ll;
}

// ===========================================================================
// conv_w: transpose + split [Wq|Wk|Wv] (each [64,4096]) -> wh/wl [12288 n][64 k]
// tile-swizzled fp16. Grid (384, 2), 256 threads.
// ===========================================================================
__global__ __launch_bounds__(256) void conv_w_kernel(
    const float* __restrict__ Wq, const float* __restrict__ Wk, const float* __restrict__ Wv)
{
    __shared__ float t[32][33];
    const int n0 = blockIdx.x * 32;      // global n 0..12287
    const int kt = blockIdx.y;           // 0..1
    const float* W = (n0 < 4096) ? Wq : (n0 < 8192) ? Wk : Wv;
    const int nl0 = n0 & 4095;
    const int tx = threadIdx.x & 31, ty8 = threadIdx.x >> 5;
#pragma unroll
    for (int i = 0; i < 4; i++) {
        int kk = ty8 + i * 8;
        t[kk][tx] = W[(size_t)(kt * 32 + kk) * 4096 + nl0 + tx];
    }
    __syncthreads();
    const int nn = threadIdx.x >> 3;
    const int k4 = (threadIdx.x & 7) * 4;
    float4 v = make_float4(t[k4][nn], t[k4+1][nn], t[k4+2][nn], t[k4+3][nn]);
    uint2 hh, ll;
    split4h(v, hh, ll);
    const int gn = n0 + nn;
    const int gk = kt * 32 + k4;
    size_t tb = ((size_t)(gn >> 7) * 2 + (gk >> 5)) * 8192;
    uint32_t so = swz((uint32_t)(gn & 127), (uint32_t)(gk & 31) * 2);
    *(uint2*)((char*)g_wh + tb + so) = hh;
    *(uint2*)((char*)g_wl + tb + so) = ll;
}

// ===========================================================================
// proj_mma: C = x @ [Wq|Wk|Wv], 3-term fp16 split (AhBh + AhBl + AlBh).
// CTA tile 128x128, 256 thr, 8 warps (2m x 4n), K=64 single stage.
// Epilogue: Q cols -> qh/ql swizzled; K cols -> kh swizzled; V cols -> g_v fp32.
// ===========================================================================
#define PROJ_SMEM 65536

__global__ __launch_bounds__(256, 2) void proj_mma()
{
    extern __shared__ char sm[];
    const uint32_t sbase = smem_u32(sm);
    const int tid = threadIdx.x;
    const int wid = tid >> 5, lane = tid & 31;
    const int wm = wid >> 2, wn = wid & 3;
    const int row0 = blockIdx.y * 128;      // 0..4095
    const int col0 = blockIdx.x * 128;      // 0..12287

    const char* xhB = (const char*)g_xh + (size_t)(blockIdx.y * 2) * 8192;
    const char* xlB = (const char*)g_xl + (size_t)(blockIdx.y * 2) * 8192;
    const char* whB = (const char*)g_wh + (size_t)(blockIdx.x * 2) * 8192;
    const char* wlB = (const char*)g_wl + (size_t)(blockIdx.x * 2) * 8192;

#pragma unroll
    for (int k = 0; k < 4; k++) {
        uint32_t off = (uint32_t)(tid + k * 256) * 16;   // covers 16KB per region
        CP16(sbase + off,          xhB + off);
        CP16(sbase + 16384 + off,  xlB + off);
        CP16(sbase + 32768 + off,  whB + off);
        CP16(sbase + 49152 + off,  wlB + off);
    }
    CP_COMMIT();
    CP_WAIT0();
    __syncthreads();

    float acc[4][4][4];
#pragma unroll
    for (int mf = 0; mf < 4; mf++)
#pragma unroll
        for (int nf = 0; nf < 4; nf++)
#pragma unroll
            for (int r = 0; r < 4; r++) acc[mf][nf][r] = 0.f;

    const uint32_t a_row = (uint32_t)(wm * 64) + (lane & 15);
    const uint32_t a_kb  = ((lane >> 4) & 1) * 16;
    const uint32_t b_row = (uint32_t)(wn * 32) + ((lane >> 4) & 1) * 8 + (lane & 7);
    const uint32_t b_kb  = ((lane >> 3) & 1) * 16;

#pragma unroll
    for (int chk = 0; chk < 2; chk++) {
        const uint32_t AH = sbase + (uint32_t)chk * 8192;
        const uint32_t AL = AH + 16384;
        const uint32_t BH = sbase + 32768 + (uint32_t)chk * 8192;
        const uint32_t BL = BH + 16384;
#pragma unroll
        for (int ks = 0; ks < 2; ks++) {
            const uint32_t kb0 = (uint32_t)ks * 32;
            uint32_t bh[4][2], bl[4][2];
#pragma unroll
            for (int p = 0; p < 2; p++) {
                uint32_t o = swz(b_row + p * 16, kb0 + b_kb);
                uint32_t t4[4];
                ldsm_x4(t4, BH + o);
                bh[2*p][0] = t4[0]; bh[2*p][1] = t4[1];
                bh[2*p+1][0] = t4[2]; bh[2*p+1][1] = t4[3];
                ldsm_x4(t4, BL + o);
                bl[2*p][0] = t4[0]; bl[2*p][1] = t4[1];
                bl[2*p+1][0] = t4[2]; bl[2*p+1][1] = t4[3];
            }
#pragma unroll
            for (int mf = 0; mf < 4; mf++) {
                uint32_t o = swz(a_row + mf * 16, kb0 + a_kb);
                uint32_t ah[4], al[4];
                ldsm_x4(ah, AH + o);
                ldsm_x4(al, AL + o);
#pragma unroll
                for (int nf = 0; nf < 4; nf++) {
                    mma_f16(acc[mf][nf], ah, bh[nf]);
                    mma_f16(acc[mf][nf], ah, bl[nf]);
                    mma_f16(acc[mf][nf], al, bh[nf]);
                }
            }
        }
    }

    // epilogue
    const int wsel = col0 >> 12;           // 0=Q 1=K 2=V
    const int dcol0 = col0 & 4095;
    const int r_lo = row0 + wm * 64 + (lane >> 2);
    const int c_base = wn * 32 + (lane & 3) * 2;
#pragma unroll
    for (int mf = 0; mf < 4; mf++) {
#pragma unroll
        for (int nf = 0; nf < 4; nf++) {
            const int cg = c_base + nf * 8;
            const int col = dcol0 + cg;
            const int h = col >> 9, dd = col & 511;
#pragma unroll
            for (int rr = 0; rr < 2; rr++) {
                float v0 = acc[mf][nf][rr*2+0];
                float v1 = acc[mf][nf][rr*2+1];
                const int m = r_lo + mf * 16 + rr * 8;
                const int b = m >> 11, n = m & 2047;
                if (wsel == 2) {
                    *(float2*)(g_v + ((size_t)(b*HH+h)*NN + n)*DD + dd) = make_float2(v0, v1);
                } else {
                    size_t tb = (((size_t)(b*HH+h) * 16 + (n >> 7)) * 16 + (dd >> 5)) * 8192;
                    uint32_t so = swz((uint32_t)(n & 127), (uint32_t)(dd & 31) * 2);
                    __half2 hv = __floats2half2_rn(v0, v1);
                    if (wsel == 0) {
                        *(uint32_t*)((char*)g_qh + tb + so) = *(uint32_t*)&hv;
                        float2 f = __half22float2(hv);
                        __half2 lv = __floats2half2_rn(v0 - f.x, v1 - f.y);
                        *(uint32_t*)((char*)g_ql + tb + so) = *(uint32_t*)&lv;
                    } else {
                        *(uint32_t*)((char*)g_kh + tb + so) = *(uint32_t*)&hv;
                    }
                }
            }
        }
    }
}

// ===========================================================================
// P[z] = V_z @ Wo_head : per z (b,h), (2048 x 512) @ (512 x 64)
// ===========================================================================
__global__ __launch_bounds__(256) void pvw_kernel(const float* __restrict__ Wo)
{
    __shared__ float As[32][32];
    __shared__ float Ws[32][64];
    const int z = blockIdx.y, h = z & 7;
    const int row0 = blockIdx.x * 32;
    const int tid = threadIdx.x;
    const int tx = tid & 15, ty = tid >> 4;
    const float* A = g_v + (size_t)z * NN * DD;
    const float* W = Wo + (size_t)h * DD * 64;
    float acc[2][4] = {{0.f,0.f,0.f,0.f},{0.f,0.f,0.f,0.f}};

    for (int kt = 0; kt < DD; kt += 32) {
        {
            int r = tid >> 3;
            int c = (tid & 7) * 4;
            float4 v = *(const float4*)(A + (size_t)(row0 + r) * DD + kt + c);
            As[c+0][r] = v.x; As[c+1][r] = v.y; As[c+2][r] = v.z; As[c+3][r] = v.w;
        }
#pragma unroll
        for (int l = 0; l < 2; l++) {
            int f = tid + l * 256;
            int r = f >> 4;
            int c = (f & 15) * 4;
            float4 v = *(const float4*)(W + (size_t)(kt + r) * 64 + c);
            *(float4*)&Ws[r][c] = v;
        }
        __syncthreads();
#pragma unroll
        for (int k = 0; k < 32; k++) {
            float a0 = As[k][ty*2 + 0];
            float a1 = As[k][ty*2 + 1];
            float4 w = *(const float4*)&Ws[k][tx*4];
            float wr[4] = {w.x, w.y, w.z, w.w};
#pragma unroll
            for (int j = 0; j < 4; j++) {
                acc[0][j] = fmaf(a0, wr[j], acc[0][j]);
                acc[1][j] = fmaf(a1, wr[j], acc[1][j]);
            }
        }
        __syncthreads();
    }
#pragma unroll
    for (int i = 0; i < 2; i++) {
        int m = row0 + ty * 2 + i;
        float* p = g_p + ((size_t)z * NN + m) * 64 + tx * 4;
        *(float4*)p = make_float4(acc[i][0], acc[i][1], acc[i][2], acc[i][3]);
    }
}

// ===========================================================================
// psum: 2-phase parallel reduction (deterministic, no FP atomics)
// ===========================================================================
__global__ __launch_bounds__(256) void psum_part_kernel()
{
    __shared__ float red[4][64];
    const int z = blockIdx.x, seg = blockIdx.y;
    const int d = threadIdx.x & 63, sub = threadIdx.x >> 6;
    const float* p = g_p + ((size_t)z * NN + seg * 256 + sub * 64) * 64 + d;
    float s = 0.f;
#pragma unroll 8
    for (int n = 0; n < 64; n++) s += p[(size_t)n * 64];
    red[sub][d] = s;
    __syncthreads();
    if (threadIdx.x < 64)
        g_psumP[z][seg][d] = red[0][d] + red[1][d] + red[2][d] + red[3][d];
}
__global__ __launch_bounds__(256) void psum_red_kernel()
{
    const int i = blockIdx.x * 256 + threadIdx.x;   // 1024 total
    const int z = i >> 6, d = i & 63;
    float s = 0.f;
#pragma unroll
    for (int g = 0; g < 8; g++) s += g_psumP[z][g][d];
    g_psum[z * 64 + d] = s;
}

// ===========================================================================
// dots = scale*(Qh+Ql)@Kh^T (+mask) -> pre
// 256 threads, 8 warps (2m x 4n), warp tile 64x32, CTA tile 128x128.
// cp.async 4-stage pipeline of pre-swizzled 8KB tile blocks.
// ===========================================================================
#define DSTAGE 24576u
#define DOTS_SMEM (4 * 24576)

__global__ __launch_bounds__(256, 2) void dots_gemm(float* __restrict__ Out)
{
    extern __shared__ char sm[];
    __shared__ int cmask[128];
    const uint32_t sbase = smem_u32(sm);

    const int tid = threadIdx.x;
    const int wid = tid >> 5, lane = tid & 31;
    const int wm = wid >> 2, wn = wid & 3;
    const int z = blockIdx.z, b = z >> 3;
    const int row0 = blockIdx.y * 128, col0 = blockIdx.x * 128;

    if (tid < 128) cmask[tid] = g_mask[b * NN + col0 + tid];

    const char* qhB = (const char*)g_qh + (((size_t)z * 16 + blockIdx.y) * 16) * 8192;
    const char* qlB = (const char*)g_ql + (((size_t)z * 16 + blockIdx.y) * 16) * 8192;
    const char* khB = (const char*)g_kh + (((size_t)z * 16 + blockIdx.x) * 16) * 8192;

    float acc[4][4][4];
#pragma unroll
    for (int mf = 0; mf < 4; mf++)
#pragma unroll
        for (int nf = 0; nf < 4; nf++)
#pragma unroll
            for (int r = 0; r < 4; r++) acc[mf][nf][r] = 0.f;

    auto issue = [&](int ch) {
        const uint32_t ss = sbase + (uint32_t)(ch & 3) * DSTAGE;
        const char* q1 = qhB + (size_t)ch * 8192;
        const char* l1 = qlB + (size_t)ch * 8192;
        const char* k1 = khB + (size_t)ch * 8192;
#pragma unroll
        for (int k = 0; k < 2; k++) {
            uint32_t off = (uint32_t)(tid + k * 256) * 16;
            CP16(ss + off,         q1 + off);
            CP16(ss + 8192 + off,  l1 + off);
            CP16(ss + 16384 + off, k1 + off);
        }
    };

    issue(0); CP_COMMIT();
    issue(1); CP_COMMIT();
    issue(2); CP_COMMIT();

    const uint32_t a_row = (uint32_t)(wm * 64) + (lane & 15);
    const uint32_t a_kb  = ((lane >> 4) & 1) * 16;
    const uint32_t b_row = (uint32_t)(wn * 32) + ((lane >> 4) & 1) * 8 + (lane & 7);
    const uint32_t b_kb  = ((lane >> 3) & 1) * 16;

    for (int ch = 0; ch < 16; ++ch) {
        CP_WAIT2();
        __syncthreads();
        const uint32_t S = sbase + (uint32_t)(ch & 3) * DSTAGE;
        const uint32_t AH = S, AL = S + 8192, BH = S + 16384;
#pragma unroll
        for (int ks = 0; ks < 2; ks++) {
            const uint32_t kb0 = (uint32_t)ks * 32;
            uint32_t bh[4][2];
#pragma unroll
            for (int p = 0; p < 2; p++) {
                uint32_t o = swz(b_row + p * 16, kb0 + b_kb);
                uint32_t t4[4];
                ldsm_x4(t4, BH + o);
                bh[2*p][0] = t4[0]; bh[2*p][1] = t4[1];
                bh[2*p+1][0] = t4[2]; bh[2*p+1][1] = t4[3];
            }
#pragma unroll
            for (int mf = 0; mf < 4; mf++) {
                uint32_t o = swz(a_row + mf * 16, kb0 + a_kb);
                uint32_t ah[4], al[4];
                ldsm_x4(ah, AH + o);
                ldsm_x4(al, AL + o);
#pragma unroll
                for (int nf = 0; nf < 4; nf++) {
                    mma_f16(acc[mf][nf], ah, bh[nf]);
                    mma_f16(acc[mf][nf], al, bh[nf]);
                }
            }
        }
        if (ch + 3 < 16) issue(ch + 3);
        CP_COMMIT();
    }

    const int r_lo = row0 + wm * 64 + (lane >> 2);
    const int c_base = wn * 32 + (lane & 3) * 2;
    float* outz = Out + (size_t)z * NN * NN;
#pragma unroll
    for (int mf = 0; mf < 4; mf++) {
        int rg0 = r_lo + mf * 16;
        int m0 = g_mask[b * NN + rg0];
        int m1 = g_mask[b * NN + rg0 + 8];
#pragma unroll
        for (int nf = 0; nf < 4; nf++) {
            int cg = c_base + nf * 8;
            int cmA = cmask[cg], cmB = cmask[cg + 1];
            float2 v0, v1;
            v0.x = (m0 && cmA) ? acc[mf][nf][0] * SCALE : MASKV;
            v0.y = (m0 && cmB) ? acc[mf][nf][1] * SCALE : MASKV;
            v1.x = (m1 && cmA) ? acc[mf][nf][2] * SCALE : MASKV;
            v1.y = (m1 && cmB) ? acc[mf][nf][3] * SCALE : MASKV;
            *(float2*)(outz + (size_t)rg0 * NN + col0 + cg)       = v0;
            *(float2*)(outz + (size_t)(rg0 + 8) * NN + col0 + cg) = v1;
        }
    }
}

// ===========================================================================
// entmax-1.5: one warp per row + compact list emission
// ===========================================================================
__global__ __launch_bounds__(256) void entmax_kernel(
    const float* __restrict__ pre, float* __restrict__ att)
{
    const int wid = threadIdx.x >> 5, lane = threadIdx.x & 31;
    const size_t row = (size_t)blockIdx.x * 8 + wid;
    const int z = (int)(row >> 11), n = (int)(row & 2047), b = z >> 3;
    float4* o4 = (float4*)(att + row * NN);

    if (!g_mask[b * NN + n]) {
        const float P = 1.0f / 2048.0f;
        float4 u = make_float4(P, P, P, P);
#pragma unroll
        for (int i = 0; i < 16; i++) o4[lane + i * 32] = u;
        if (lane == 0) g_cnt[row] = -1;
        return;
    }

    const float4* p4 = (const float4*)(pre + row * NN);
    float x[64];
    float mx = -3.0e38f;
#pragma unroll
    for (int i = 0; i < 16; i++) {
        float4 v = p4[lane + i * 32];
        x[4*i+0] = 0.5f * v.x; x[4*i+1] = 0.5f * v.y;
        x[4*i+2] = 0.5f * v.z; x[4*i+3] = 0.5f * v.w;
        mx = fmaxf(mx, fmaxf(fmaxf(x[4*i], x[4*i+1]), fmaxf(x[4*i+2], x[4*i+3])));
    }
#pragma unroll
    for (int off = 16; off; off >>= 1)
        mx = fmaxf(mx, __shfl_xor_sync(0xffffffffu, mx, off));
#pragma unroll
    for (int j = 0; j < 64; j++) x[j] -= mx;

    float tau = -1.0f;
#pragma unroll 1
    for (int it = 0; it < 12; ++it) {
        float s1 = 0.f, s2 = 0.f;
#pragma unroll
        for (int j = 0; j < 64; j++) {
            float d = fmaxf(x[j] - tau, 0.f);
            s1 += d;
            s2 = fmaf(d, d, s2);
        }
#pragma unroll
        for (int off = 16; off; off >>= 1) {
            s1 += __shfl_xor_sync(0xffffffffu, s1, off);
            s2 += __shfl_xor_sync(0xffffffffu, s2, off);
        }
        float step = (s1 > 1e-20f) ? (s2 - 1.0f) / (2.0f * s1) : 0.f;
        tau += step;
    }

#pragma unroll
    for (int i = 0; i < 16; i++) {
        float4 w;
        float d;
        d = fmaxf(x[4*i+0] - tau, 0.f); w.x = d * d;
        d = fmaxf(x[4*i+1] - tau, 0.f); w.y = d * d;
        d = fmaxf(x[4*i+2] - tau, 0.f); w.z = d * d;
        d = fmaxf(x[4*i+3] - tau, 0.f); w.w = d * d;
        o4[lane + i * 32] = w;
    }

    int cl = 0;
#pragma unroll
    for (int j = 0; j < 64; j++) cl += (x[j] > tau) ? 1 : 0;
    int v = cl;
#pragma unroll
    for (int d = 1; d < 32; d <<= 1) {
        int t = __shfl_up_sync(0xffffffffu, v, d);
        if (lane >= d) v += t;
    }
    int total = __shfl_sync(0xffffffffu, v, 31);
    int pos = v - cl;
    if (total <= MAXS) {
        int*   si = g_si + row * MAXS;
        float* sw = g_sw + row * MAXS;
#pragma unroll
        for (int i = 0; i < 16; i++)
#pragma unroll
            for (int c = 0; c < 4; c++) {
                int j = 4*i + c;
                if (x[j] > tau) {
                    float d = x[j] - tau;
                    si[pos] = 4*lane + 128*i + c;
                    sw[pos] = d * d;
                    pos++;
                }
            }
        if (lane == 31) g_cnt[row] = total;
    } else if (lane == 31) {
        g_cnt[row] = -2;
    }
}

// ===========================================================================
// Fused sparse attention-out: out[b,n,:] = bo + sum_h sum_j w_j * P[z][idx_j][:]
// ===========================================================================
__global__ __launch_bounds__(256) void af_kernel(
    const float* __restrict__ att, const float* __restrict__ bo, float* __restrict__ out)
{
    const int wid = threadIdx.x >> 5, lane = threadIdx.x & 31;
    const int gw = blockIdx.x * 8 + wid;        // row index b*2048+n
    const int b = gw >> 11, n = gw & 2047;
    const int dc = lane * 2;

    float2 acc;
    float2 bb = *(const float2*)(bo + dc);
    acc.x = bb.x; acc.y = bb.y;

#pragma unroll 1
    for (int h = 0; h < HH; h++) {
        const int z = b * HH + h;
        const size_t row = (size_t)z * NN + n;
        const int cnt = g_cnt[row];
        const float* Pz = g_p + (size_t)z * NN * 64;
        if (cnt == -1) {
            const float Pu = 1.0f / 2048.0f;
            float2 s = *(const float2*)(g_psum + z * 64 + dc);
            acc.x = fmaf(Pu, s.x, acc.x);
            acc.y = fmaf(Pu, s.y, acc.y);
        } else if (cnt >= 0) {
            const int*   si = g_si + row * MAXS;
            const float* sw = g_sw + row * MAXS;
            for (int j = 0; j < cnt; j++) {
                int   i0 = si[j];
                float w0 = sw[j];
                float2 v = *(const float2*)(Pz + (size_t)i0 * 64 + dc);
                acc.x = fmaf(w0, v.x, acc.x);
                acc.y = fmaf(w0, v.y, acc.y);
            }
        } else {  // dense fallback
            const float* arow = att + row * NN;
            for (int c = 0; c < NN; c++) {
                float p = arow[c];
                if (p != 0.f) {
                    float2 v = *(const float2*)(Pz + (size_t)c * 64 + dc);
                    acc.x = fmaf(p, v.x, acc.x);
                    acc.y = fmaf(p, v.y, acc.y);
                }
            }
        }
    }
    *(float2*)(out + (size_t)gw * 64 + dc) = acc;
}

// ===========================================================================
extern "C" void kernel_launch(void* const* d_in, const int* in_sizes, int n_in,
                              void* d_out, int out_size)
{
    const float* x   = (const float*)d_in[0];
    const unsigned char* mask_raw = (const unsigned char*)d_in[1];
    const float* Wq  = (const float*)d_in[2];
    const float* Wk  = (const float*)d_in[3];
    const float* Wv  = (const float*)d_in[4];
    const float* Wo  = (const float*)d_in[5];
    const float* bo  = (const float*)d_in[6];

    float* out = (float*)d_out;
    float* pre = out + OUT_ELEMS;
    float* att = pre + PRE_ELEMS;

    static int smem_set = 0;
    if (!smem_set) {
        cudaFuncSetAttribute(dots_gemm,
                             cudaFuncAttributeMaxDynamicSharedMemorySize, DOTS_SMEM);
        cudaFuncSetAttribute(proj_mma,
                             cudaFuncAttributeMaxDynamicSharedMemorySize, PROJ_SMEM);
        smem_set = 1;
    }

    prep_mask_kernel<<<1, 256>>>(mask_raw);

    conv_x_kernel<<<256, 256>>>(x);
    conv_w_kernel<<<dim3(384, 2), 256>>>(Wq, Wk, Wv);

    proj_mma<<<dim3(96, 32), 256, PROJ_SMEM>>>();

    pvw_kernel<<<dim3(64, 16), 256>>>(Wo);
    psum_part_kernel<<<dim3(16, 8), 256>>>();
    psum_red_kernel<<<4, 256>>>();

    dots_gemm<<<dim3(16, 16, 16), 256, DOTS_SMEM>>>(pre);

    entmax_kernel<<<BB * HH * NN / 8, 256>>>(pre, att);

    af_kernel<<<BB * NN / 8, 256>>>(att, bo, out);
}

// round 10
// speedup vs baseline: 8.1906x; 1.3086x over previous
#include <cuda_runtime.h>
#include <cuda_bf16.h>
#include <cuda_fp16.h>
#include <cstdint>

// Problem constants
#define BB 2
#define NN 2048
#define DIMX 64
#define HH 8
#define DD 512            // per-head dim
#define INNER 4096
#define SCALE 0.125f
#define MASKV -1e9f

#define OUT_ELEMS   (BB*NN*DIMX)          // 262144
#define PRE_ELEMS   (BB*HH*NN*NN)         // 67108864

#define NROWS (BB*HH*NN)   // 32768
#define NZ    (BB*HH)      // 16
#define MAXS  512

// Scratch
__device__ __half g_qh[BB*HH*NN*DD];
__device__ __half g_ql[BB*HH*NN*DD];
__device__ __half g_kh[BB*HH*NN*DD];
__device__ __half g_vh[BB*HH*NN*DD];
__device__ __half g_vl[BB*HH*NN*DD];
__device__ __half g_xh[4096*64];
__device__ __half g_xl[4096*64];
__device__ __half g_wh[12288*64];
__device__ __half g_wl[12288*64];
__device__ __half g_wo[HH*64*DD];               // Woh: per-head [64 dc][512 d] swizzled
__device__ float  g_p[(size_t)NZ * NN * 64];    // P[z] = V_z @ Wo_head  (8MB)
__device__ float  g_psum[NZ * 64];
__device__ float  g_psumP[NZ][8][64];
__device__ int    g_mask[BB*NN];
__device__ int    g_si[(size_t)NROWS * MAXS];
__device__ float  g_sw[(size_t)NROWS * MAXS];
__device__ int    g_cnt[NROWS];

// ===========================================================================
// Helpers
// ===========================================================================
__device__ __forceinline__ uint32_t smem_u32(const void* p) {
    uint32_t r;
    asm("{ .reg .u64 t; cvta.to.shared.u64 t, %1; cvt.u32.u64 %0, t; }" : "=r"(r) : "l"(p));
    return r;
}
__device__ __forceinline__ void ldsm_x4(uint32_t* r, uint32_t addr) {
    asm volatile("ldmatrix.sync.aligned.m8n8.x4.shared.b16 {%0,%1,%2,%3}, [%4];"
        : "=r"(r[0]), "=r"(r[1]), "=r"(r[2]), "=r"(r[3]) : "r"(addr));
}
__device__ __forceinline__ void mma_f16(float* c, const uint32_t* a, const uint32_t* b) {
    asm volatile("mma.sync.aligned.m16n8k16.row.col.f32.f16.f16.f32 "
        "{%0,%1,%2,%3}, {%4,%5,%6,%7}, {%8,%9}, {%0,%1,%2,%3};"
        : "+f"(c[0]), "+f"(c[1]), "+f"(c[2]), "+f"(c[3])
        : "r"(a[0]), "r"(a[1]), "r"(a[2]), "r"(a[3]), "r"(b[0]), "r"(b[1]));
}
#define CP16(saddr, gptr) \
    asm volatile("cp.async.cg.shared.global [%0], [%1], 16;" :: "r"(saddr), "l"(gptr))
#define CP_COMMIT() asm volatile("cp.async.commit_group;")
#define CP_WAIT2()  asm volatile("cp.async.wait_group 2;")
#define CP_WAIT1()  asm volatile("cp.async.wait_group 1;")
#define CP_WAIT0()  asm volatile("cp.async.wait_group 0;")

// swizzled byte offset inside a [rows][32 cols] fp16 tile, 64B rows
__device__ __forceinline__ uint32_t swz(uint32_t r, uint32_t kb) {
    uint32_t off = r * 64u + kb;
    return off ^ ((off >> 3) & 0x70u);
}
// fp16 hi/lo split of float4
__device__ __forceinline__ void split4h(float4 v, uint2& hh, uint2& ll) {
    __half2 h01 = __floats2half2_rn(v.x, v.y);
    __half2 h23 = __floats2half2_rn(v.z, v.w);
    float2 f01 = __half22float2(h01);
    float2 f23 = __half22float2(h23);
    __half2 l01 = __floats2half2_rn(v.x - f01.x, v.y - f01.y);
    __half2 l23 = __floats2half2_rn(v.z - f23.x, v.w - f23.y);
    hh.x = *(uint32_t*)&h01; hh.y = *(uint32_t*)&h23;
    ll.x = *(uint32_t*)&l01; ll.y = *(uint32_t*)&l23;
}

// ===========================================================================
// Mask prep (dtype detect)
// ===========================================================================
__global__ void prep_mask_kernel(const unsigned char* __restrict__ raw) {
    __shared__ int cnt_f32, cnt_gt1;
    if (threadIdx.x == 0) { cnt_f32 = 0; cnt_gt1 = 0; }
    __syncthreads();
    const unsigned int* u = (const unsigned int*)raw;
    int lf = 0, lg = 0;
    for (int i = threadIdx.x; i < 1024; i += blockDim.x) {
        unsigned int v = u[i];
        if (v == 0x3f800000u) lf++;
        else if (v > 1u) lg++;
    }
    atomicAdd(&cnt_f32, lf);
    atomicAdd(&cnt_gt1, lg);
    __syncthreads();
    int mode;
    if (cnt_f32 > 64) mode = 2;
    else if (cnt_gt1 > 64) mode = 1;
    else mode = 0;
    for (int i = threadIdx.x; i < BB*NN; i += blockDim.x) {
        int m;
        if (mode == 2)      m = (((const unsigned int*)raw)[i] != 0u) ? 1 : 0;
        else if (mode == 1) m = raw[i] ? 1 : 0;
        else                m = (((const int*)raw)[i] != 0) ? 1 : 0;
        g_mask[i] = m;
    }
}

// ===========================================================================
// conv_x: split x [4096,64] fp32 -> xh/xl fp16 tile-swizzled
// ===========================================================================
__global__ __launch_bounds__(256) void conv_x_kernel(const float* __restrict__ X) {
    int idx = blockIdx.x * 256 + threadIdx.x;
    int m = idx >> 4;
    int k = (idx & 15) * 4;
    float4 v = ((const float4*)X)[idx];
    uint2 hh, ll;
    split4h(v, hh, ll);
    size_t tb = ((size_t)(m >> 7) * 2 + (k >> 5)) * 8192;
    uint32_t so = swz((uint32_t)(m & 127), (uint32_t)(k & 31) * 2);
    *(uint2*)((char*)g_xh + tb + so) = hh;
    *(uint2*)((char*)g_xl + tb + so) = ll;
}

// ===========================================================================
// conv_w: transpose + split [Wq|Wk|Wv] -> wh/wl [12288 n][64 k] tile-swizzled
// ===========================================================================
__global__ __launch_bounds__(256) void conv_w_kernel(
    const float* __restrict__ Wq, const float* __restrict__ Wk, const float* __restrict__ Wv)
{
    __shared__ float t[32][33];
    const int n0 = blockIdx.x * 32;
    const int kt = blockIdx.y;
    const float* W = (n0 < 4096) ? Wq : (n0 < 8192) ? Wk : Wv;
    const int nl0 = n0 & 4095;
    const int tx = threadIdx.x & 31, ty8 = threadIdx.x >> 5;
#pragma unroll
    for (int i = 0; i < 4; i++) {
        int kk = ty8 + i * 8;
        t[kk][tx] = W[(size_t)(kt * 32 + kk) * 4096 + nl0 + tx];
    }
    __syncthreads();
    const int nn = threadIdx.x >> 3;
    const int k4 = (threadIdx.x & 7) * 4;
    float4 v = make_float4(t[k4][nn], t[k4+1][nn], t[k4+2][nn], t[k4+3][nn]);
    uint2 hh, ll;
    split4h(v, hh, ll);
    const int gn = n0 + nn;
    const int gk = kt * 32 + k4;
    size_t tb = ((size_t)(gn >> 7) * 2 + (gk >> 5)) * 8192;
    uint32_t so = swz((uint32_t)(gn & 127), (uint32_t)(gk & 31) * 2);
    *(uint2*)((char*)g_wh + tb + so) = hh;
    *(uint2*)((char*)g_wl + tb + so) = ll;
}

// ===========================================================================
// conv_wo: Wo [4096(h*512+d)][64 dc] fp32 -> per-head Woh [64 dc][512 d] fp16
// swizzled 4KB blocks: base ((h*16)+d/32)*4096, offset swz(dc, (d&31)*2).
// Grid (8 dgroups, 8 heads), 256 thr.
// ===========================================================================
__global__ __launch_bounds__(256) void conv_wo_kernel(const float* __restrict__ Wo)
{
    __shared__ float t[64][65];
    const int h = blockIdx.y;
    const int d0 = blockIdx.x * 64;
#pragma unroll
    for (int i = 0; i < 16; i++) {
        int idx = threadIdx.x + i * 256;
        int dl = idx >> 6, dc = idx & 63;
        t[dl][dc] = Wo[(size_t)(h * 512 + d0 + dl) * 64 + dc];
    }
    __syncthreads();
#pragma unroll
    for (int i = 0; i < 4; i++) {
        int j = threadIdx.x + i * 256;
        int dc = j >> 4;
        int d4 = (j & 15) * 4;
        __half2 h01 = __floats2half2_rn(t[d4+0][dc], t[d4+1][dc]);
        __half2 h23 = __floats2half2_rn(t[d4+2][dc], t[d4+3][dc]);
        uint2 hv;
        hv.x = *(uint32_t*)&h01; hv.y = *(uint32_t*)&h23;
        const int d = d0 + d4;
        size_t tb = ((size_t)h * 16 + (d >> 5)) * 4096;
        uint32_t so = swz((uint32_t)dc, (uint32_t)(d & 31) * 2);
        *(uint2*)((char*)g_wo + tb + so) = hv;
    }
}

// ===========================================================================
// proj_mma: C = x @ [Wq|Wk|Wv], 3-term fp16 split.
// Epilogue: Q -> qh/ql; K -> kh; V -> vh/vl (all tile-swizzled fp16)
// ===========================================================================
#define PROJ_SMEM 65536

__global__ __launch_bounds__(256, 2) void proj_mma()
{
    extern __shared__ char sm[];
    const uint32_t sbase = smem_u32(sm);
    const int tid = threadIdx.x;
    const int wid = tid >> 5, lane = tid & 31;
    const int wm = wid >> 2, wn = wid & 3;
    const int row0 = blockIdx.y * 128;
    const int col0 = blockIdx.x * 128;

    const char* xhB = (const char*)g_xh + (size_t)(blockIdx.y * 2) * 8192;
    const char* xlB = (const char*)g_xl + (size_t)(blockIdx.y * 2) * 8192;
    const char* whB = (const char*)g_wh + (size_t)(blockIdx.x * 2) * 8192;
    const char* wlB = (const char*)g_wl + (size_t)(blockIdx.x * 2) * 8192;

#pragma unroll
    for (int k = 0; k < 4; k++) {
        uint32_t off = (uint32_t)(tid + k * 256) * 16;
        CP16(sbase + off,          xhB + off);
        CP16(sbase + 16384 + off,  xlB + off);
        CP16(sbase + 32768 + off,  whB + off);
        CP16(sbase + 49152 + off,  wlB + off);
    }
    CP_COMMIT();
    CP_WAIT0();
    __syncthreads();

    float acc[4][4][4];
#pragma unroll
    for (int mf = 0; mf < 4; mf++)
#pragma unroll
        for (int nf = 0; nf < 4; nf++)
#pragma unroll
            for (int r = 0; r < 4; r++) acc[mf][nf][r] = 0.f;

    const uint32_t a_row = (uint32_t)(wm * 64) + (lane & 15);
    const uint32_t a_kb  = ((lane >> 4) & 1) * 16;
    const uint32_t b_row = (uint32_t)(wn * 32) + ((lane >> 4) & 1) * 8 + (lane & 7);
    const uint32_t b_kb  = ((lane >> 3) & 1) * 16;

#pragma unroll
    for (int chk = 0; chk < 2; chk++) {
        const uint32_t AH = sbase + (uint32_t)chk * 8192;
        const uint32_t AL = AH + 16384;
        const uint32_t BH = sbase + 32768 + (uint32_t)chk * 8192;
        const uint32_t BL = BH + 16384;
#pragma unroll
        for (int ks = 0; ks < 2; ks++) {
            const uint32_t kb0 = (uint32_t)ks * 32;
            uint32_t bh[4][2], bl[4][2];
#pragma unroll
            for (int p = 0; p < 2; p++) {
                uint32_t o = swz(b_row + p * 16, kb0 + b_kb);
                uint32_t t4[4];
                ldsm_x4(t4, BH + o);
                bh[2*p][0] = t4[0]; bh[2*p][1] = t4[1];
                bh[2*p+1][0] = t4[2]; bh[2*p+1][1] = t4[3];
                ldsm_x4(t4, BL + o);
                bl[2*p][0] = t4[0]; bl[2*p][1] = t4[1];
                bl[2*p+1][0] = t4[2]; bl[2*p+1][1] = t4[3];
            }
#pragma unroll
            for (int mf = 0; mf < 4; mf++) {
                uint32_t o = swz(a_row + mf * 16, kb0 + a_kb);
                uint32_t ah[4], al[4];
                ldsm_x4(ah, AH + o);
                ldsm_x4(al, AL + o);
#pragma unroll
                for (int nf = 0; nf < 4; nf++) {
                    mma_f16(acc[mf][nf], ah, bh[nf]);
                    mma_f16(acc[mf][nf], ah, bl[nf]);
                    mma_f16(acc[mf][nf], al, bh[nf]);
                }
            }
        }
    }

    // epilogue
    const int wsel = col0 >> 12;           // 0=Q 1=K 2=V
    const int dcol0 = col0 & 4095;
    const int r_lo = row0 + wm * 64 + (lane >> 2);
    const int c_base = wn * 32 + (lane & 3) * 2;
#pragma unroll
    for (int mf = 0; mf < 4; mf++) {
#pragma unroll
        for (int nf = 0; nf < 4; nf++) {
            const int cg = c_base + nf * 8;
            const int col = dcol0 + cg;
            const int h = col >> 9, dd = col & 511;
#pragma unroll
            for (int rr = 0; rr < 2; rr++) {
                float v0 = acc[mf][nf][rr*2+0];
                float v1 = acc[mf][nf][rr*2+1];
                const int m = r_lo + mf * 16 + rr * 8;
                const int b = m >> 11, n = m & 2047;
                size_t tb = (((size_t)(b*HH+h) * 16 + (n >> 7)) * 16 + (dd >> 5)) * 8192;
                uint32_t so = swz((uint32_t)(n & 127), (uint32_t)(dd & 31) * 2);
                __half2 hv = __floats2half2_rn(v0, v1);
                if (wsel == 1) {
                    *(uint32_t*)((char*)g_kh + tb + so) = *(uint32_t*)&hv;
                } else {
                    float2 f = __half22float2(hv);
                    __half2 lv = __floats2half2_rn(v0 - f.x, v1 - f.y);
                    if (wsel == 0) {
                        *(uint32_t*)((char*)g_qh + tb + so) = *(uint32_t*)&hv;
                        *(uint32_t*)((char*)g_ql + tb + so) = *(uint32_t*)&lv;
                    } else {
                        *(uint32_t*)((char*)g_vh + tb + so) = *(uint32_t*)&hv;
                        *(uint32_t*)((char*)g_vl + tb + so) = *(uint32_t*)&lv;
                    }
                }
            }
        }
    }
}

// ===========================================================================
// pvw_mma: P[z] = (Vh+Vl) @ Woh^T per z: (2048x512)@(512x64) -> g_p fp32
// CTA tile 128(n) x 64(dc), 256 thr, 8 warps (4m x 2n), warp 32x32.
// cp.async double buffer, 16 K-chunks of 32.
// ===========================================================================
#define PVW_STAGE 20480u
#define PVW_SMEM (2 * 20480)

__global__ __launch_bounds__(256, 2) void pvw_mma()
{
    extern __shared__ char sm[];
    const uint32_t sbase = smem_u32(sm);
    const int tid = threadIdx.x;
    const int wid = tid >> 5, lane = tid & 31;
    const int wm = wid >> 1, wn = wid & 1;
    const int z = blockIdx.y, h = z & 7;
    const int nt = blockIdx.x;

    const char* vhB = (const char*)g_vh + (((size_t)z * 16 + nt) * 16) * 8192;
    const char* vlB = (const char*)g_vl + (((size_t)z * 16 + nt) * 16) * 8192;
    const char* woB = (const char*)g_wo + (size_t)(h * 16) * 4096;

    float acc[2][4][4];
#pragma unroll
    for (int mf = 0; mf < 2; mf++)
#pragma unroll
        for (int nf = 0; nf < 4; nf++)
#pragma unroll
            for (int r = 0; r < 4; r++) acc[mf][nf][r] = 0.f;

    auto issue = [&](int ch) {
        const uint32_t ss = sbase + (uint32_t)(ch & 1) * PVW_STAGE;
#pragma unroll
        for (int k = 0; k < 2; k++) {
            uint32_t off = (uint32_t)(tid + k * 256) * 16;
            CP16(ss + off,        vhB + (size_t)ch * 8192 + off);
            CP16(ss + 8192 + off, vlB + (size_t)ch * 8192 + off);
        }
        if (tid < 256) {   // 4KB B tile: 1 CP16/thread
            uint32_t off = (uint32_t)tid * 16;
            CP16(ss + 16384 + off, woB + (size_t)ch * 4096 + off);
        }
    };

    issue(0); CP_COMMIT();

    const uint32_t a_row = (uint32_t)(wm * 32) + (lane & 15);
    const uint32_t a_kb  = ((lane >> 4) & 1) * 16;
    const uint32_t b_row = (uint32_t)(wn * 32) + ((lane >> 4) & 1) * 8 + (lane & 7);
    const uint32_t b_kb  = ((lane >> 3) & 1) * 16;

    for (int ch = 0; ch < 16; ++ch) {
        if (ch + 1 < 16) { issue(ch + 1); CP_COMMIT(); CP_WAIT1(); }
        else CP_WAIT0();
        __syncthreads();
        const uint32_t S = sbase + (uint32_t)(ch & 1) * PVW_STAGE;
        const uint32_t AH = S, AL = S + 8192, BH = S + 16384;
#pragma unroll
        for (int ks = 0; ks < 2; ks++) {
            const uint32_t kb0 = (uint32_t)ks * 32;
            uint32_t bh[4][2];
#pragma unroll
            for (int p = 0; p < 2; p++) {
                uint32_t o = swz(b_row + p * 16, kb0 + b_kb);
                uint32_t t4[4];
                ldsm_x4(t4, BH + o);
                bh[2*p][0] = t4[0]; bh[2*p][1] = t4[1];
                bh[2*p+1][0] = t4[2]; bh[2*p+1][1] = t4[3];
            }
#pragma unroll
            for (int mf = 0; mf < 2; mf++) {
                uint32_t o = swz(a_row + mf * 16, kb0 + a_kb);
                uint32_t ah[4], al[4];
                ldsm_x4(ah, AH + o);
                ldsm_x4(al, AL + o);
#pragma unroll
                for (int nf = 0; nf < 4; nf++) {
                    mma_f16(acc[mf][nf], ah, bh[nf]);
                    mma_f16(acc[mf][nf], al, bh[nf]);
                }
            }
        }
        __syncthreads();
    }

    const int r_lo = nt * 128 + wm * 32 + (lane >> 2);
    const int c_base = wn * 32 + (lane & 3) * 2;
    float* Pz = g_p + (size_t)z * NN * 64;
#pragma unroll
    for (int mf = 0; mf < 2; mf++) {
        int rg0 = r_lo + mf * 16;
#pragma unroll
        for (int nf = 0; nf < 4; nf++) {
            int cg = c_base + nf * 8;
            *(float2*)(Pz + (size_t)rg0 * 64 + cg)       = make_float2(acc[mf][nf][0], acc[mf][nf][1]);
            *(float2*)(Pz + (size_t)(rg0 + 8) * 64 + cg) = make_float2(acc[mf][nf][2], acc[mf][nf][3]);
        }
    }
}

// ===========================================================================
// psum: 2-phase parallel reduction
// ===========================================================================
__global__ __launch_bounds__(256) void psum_part_kernel()
{
    __shared__ float red[4][64];
    const int z = blockIdx.x, seg = blockIdx.y;
    const int d = threadIdx.x & 63, sub = threadIdx.x >> 6;
    const float* p = g_p + ((size_t)z * NN + seg * 256 + sub * 64) * 64 + d;
    float s = 0.f;
#pragma unroll 8
    for (int n = 0; n < 64; n++) s += p[(size_t)n * 64];
    red[sub][d] = s;
    __syncthreads();
    if (threadIdx.x < 64)
        g_psumP[z][seg][d] = red[0][d] + red[1][d] + red[2][d] + red[3][d];
}
__global__ __launch_bounds__(256) void psum_red_kernel()
{
    const int i = blockIdx.x * 256 + threadIdx.x;
    const int z = i >> 6, d = i & 63;
    float s = 0.f;
#pragma unroll
    for (int g = 0; g < 8; g++) s += g_psumP[z][g][d];
    g_psum[z * 64 + d] = s;
}

// ===========================================================================
// dots = scale*(Qh+Ql)@Kh^T (+mask) -> pre
// ===========================================================================
#define DSTAGE 24576u
#define DOTS_SMEM (4 * 24576)

__global__ __launch_bounds__(256, 2) void dots_gemm(float* __restrict__ Out)
{
    extern __shared__ char sm[];
    __shared__ int cmask[128];
    const uint32_t sbase = smem_u32(sm);

    const int tid = threadIdx.x;
    const int wid = tid >> 5, lane = tid & 31;
    const int wm = wid >> 2, wn = wid & 3;
    const int z = blockIdx.z, b = z >> 3;
    const int row0 = blockIdx.y * 128, col0 = blockIdx.x * 128;

    if (tid < 128) cmask[tid] = g_mask[b * NN + col0 + tid];

    const char* qhB = (const char*)g_qh + (((size_t)z * 16 + blockIdx.y) * 16) * 8192;
    const char* qlB = (const char*)g_ql + (((size_t)z * 16 + blockIdx.y) * 16) * 8192;
    const char* khB = (const char*)g_kh + (((size_t)z * 16 + blockIdx.x) * 16) * 8192;

    float acc[4][4][4];
#pragma unroll
    for (int mf = 0; mf < 4; mf++)
#pragma unroll
        for (int nf = 0; nf < 4; nf++)
#pragma unroll
            for (int r = 0; r < 4; r++) acc[mf][nf][r] = 0.f;

    auto issue = [&](int ch) {
        const uint32_t ss = sbase + (uint32_t)(ch & 3) * DSTAGE;
        const char* q1 = qhB + (size_t)ch * 8192;
        const char* l1 = qlB + (size_t)ch * 8192;
        const char* k1 = khB + (size_t)ch * 8192;
#pragma unroll
        for (int k = 0; k < 2; k++) {
            uint32_t off = (uint32_t)(tid + k * 256) * 16;
            CP16(ss + off,         q1 + off);
            CP16(ss + 8192 + off,  l1 + off);
            CP16(ss + 16384 + off, k1 + off);
        }
    };

    issue(0); CP_COMMIT();
    issue(1); CP_COMMIT();
    issue(2); CP_COMMIT();

    const uint32_t a_row = (uint32_t)(wm * 64) + (lane & 15);
    const uint32_t a_kb  = ((lane >> 4) & 1) * 16;
    const uint32_t b_row = (uint32_t)(wn * 32) + ((lane >> 4) & 1) * 8 + (lane & 7);
    const uint32_t b_kb  = ((lane >> 3) & 1) * 16;

    for (int ch = 0; ch < 16; ++ch) {
        CP_WAIT2();
        __syncthreads();
        const uint32_t S = sbase + (uint32_t)(ch & 3) * DSTAGE;
        const uint32_t AH = S, AL = S + 8192, BH = S + 16384;
#pragma unroll
        for (int ks = 0; ks < 2; ks++) {
            const uint32_t kb0 = (uint32_t)ks * 32;
            uint32_t bh[4][2];
#pragma unroll
            for (int p = 0; p < 2; p++) {
                uint32_t o = swz(b_row + p * 16, kb0 + b_kb);
                uint32_t t4[4];
                ldsm_x4(t4, BH + o);
                bh[2*p][0] = t4[0]; bh[2*p][1] = t4[1];
                bh[2*p+1][0] = t4[2]; bh[2*p+1][1] = t4[3];
            }
#pragma unroll
            for (int mf = 0; mf < 4; mf++) {
                uint32_t o = swz(a_row + mf * 16, kb0 + a_kb);
                uint32_t ah[4], al[4];
                ldsm_x4(ah, AH + o);
                ldsm_x4(al, AL + o);
#pragma unroll
                for (int nf = 0; nf < 4; nf++) {
                    mma_f16(acc[mf][nf], ah, bh[nf]);
                    mma_f16(acc[mf][nf], al, bh[nf]);
                }
            }
        }
        if (ch + 3 < 16) issue(ch + 3);
        CP_COMMIT();
    }

    const int r_lo = row0 + wm * 64 + (lane >> 2);
    const int c_base = wn * 32 + (lane & 3) * 2;
    float* outz = Out + (size_t)z * NN * NN;
#pragma unroll
    for (int mf = 0; mf < 4; mf++) {
        int rg0 = r_lo + mf * 16;
        int m0 = g_mask[b * NN + rg0];
        int m1 = g_mask[b * NN + rg0 + 8];
#pragma unroll
        for (int nf = 0; nf < 4; nf++) {
            int cg = c_base + nf * 8;
            int cmA = cmask[cg], cmB = cmask[cg + 1];
            float2 v0, v1;
            v0.x = (m0 && cmA) ? acc[mf][nf][0] * SCALE : MASKV;
            v0.y = (m0 && cmB) ? acc[mf][nf][1] * SCALE : MASKV;
            v1.x = (m1 && cmA) ? acc[mf][nf][2] * SCALE : MASKV;
            v1.y = (m1 && cmB) ? acc[mf][nf][3] * SCALE : MASKV;
            *(float2*)(outz + (size_t)rg0 * NN + col0 + cg)       = v0;
            *(float2*)(outz + (size_t)(rg0 + 8) * NN + col0 + cg) = v1;
        }
    }
}

// ===========================================================================
// entmax-1.5: one warp per row + compact list; Newton with uniform early-exit
// ===========================================================================
__global__ __launch_bounds__(256) void entmax_kernel(
    const float* __restrict__ pre, float* __restrict__ att)
{
    const int wid = threadIdx.x >> 5, lane = threadIdx.x & 31;
    const size_t row = (size_t)blockIdx.x * 8 + wid;
    const int z = (int)(row >> 11), n = (int)(row & 2047), b = z >> 3;
    float4* o4 = (float4*)(att + row * NN);

    if (!g_mask[b * NN + n]) {
        const float P = 1.0f / 2048.0f;
        float4 u = make_float4(P, P, P, P);
#pragma unroll
        for (int i = 0; i < 16; i++) o4[lane + i * 32] = u;
        if (lane == 0) g_cnt[row] = -1;
        return;
    }

    const float4* p4 = (const float4*)(pre + row * NN);
    float x[64];
    float mx = -3.0e38f;
#pragma unroll
    for (int i = 0; i < 16; i++) {
        float4 v = p4[lane + i * 32];
        x[4*i+0] = 0.5f * v.x; x[4*i+1] = 0.5f * v.y;
        x[4*i+2] = 0.5f * v.z; x[4*i+3] = 0.5f * v.w;
        mx = fmaxf(mx, fmaxf(fmaxf(x[4*i], x[4*i+1]), fmaxf(x[4*i+2], x[4*i+3])));
    }
#pragma unroll
    for (int off = 16; off; off >>= 1)
        mx = fmaxf(mx, __shfl_xor_sync(0xffffffffu, mx, off));
#pragma unroll
    for (int j = 0; j < 64; j++) x[j] -= mx;

    float tau = -1.0f;
#pragma unroll 1
    for (int it = 0; it < 12; ++it) {
        float s1 = 0.f, s2 = 0.f;
#pragma unroll
        for (int j = 0; j < 64; j++) {
            float d = fmaxf(x[j] - tau, 0.f);
            s1 += d;
            s2 = fmaf(d, d, s2);
        }
#pragma unroll
        for (int off = 16; off; off >>= 1) {
            s1 += __shfl_xor_sync(0xffffffffu, s1, off);
            s2 += __shfl_xor_sync(0xffffffffu, s2, off);
        }
        float step = (s1 > 1e-20f) ? (s2 - 1.0f) / (2.0f * s1) : 0.f;
        tau += step;
        if (fabsf(step) < 1e-6f) break;   // uniform across warp (post-reduction)
    }

#pragma unroll
    for (int i = 0; i < 16; i++) {
        float4 w;
        float d;
        d = fmaxf(x[4*i+0] - tau, 0.f); w.x = d * d;
        d = fmaxf(x[4*i+1] - tau, 0.f); w.y = d * d;
        d = fmaxf(x[4*i+2] - tau, 0.f); w.z = d * d;
        d = fmaxf(x[4*i+3] - tau, 0.f); w.w = d * d;
        o4[lane + i * 32] = w;
    }

    int cl = 0;
#pragma unroll
    for (int j = 0; j < 64; j++) cl += (x[j] > tau) ? 1 : 0;
    int v = cl;
#pragma unroll
    for (int d = 1; d < 32; d <<= 1) {
        int t = __shfl_up_sync(0xffffffffu, v, d);
        if (lane >= d) v += t;
    }
    int total = __shfl_sync(0xffffffffu, v, 31);
    int pos = v - cl;
    if (total <= MAXS) {
        int*   si = g_si + row * MAXS;
        float* sw = g_sw + row * MAXS;
#pragma unroll
        for (int i = 0; i < 16; i++)
#pragma unroll
            for (int c = 0; c < 4; c++) {
                int j = 4*i + c;
                if (x[j] > tau) {
                    float d = x[j] - tau;
                    si[pos] = 4*lane + 128*i + c;
                    sw[pos] = d * d;
                    pos++;
                }
            }
        if (lane == 31) g_cnt[row] = total;
    } else if (lane == 31) {
        g_cnt[row] = -2;
    }
}

// ===========================================================================
// Fused sparse attention-out: out[b,n,:] = bo + sum_h sum_j w_j * P[z][idx_j][:]
// ===========================================================================
__global__ __launch_bounds__(256) void af_kernel(
    const float* __restrict__ att, const float* __restrict__ bo, float* __restrict__ out)
{
    const int wid = threadIdx.x >> 5, lane = threadIdx.x & 31;
    const int gw = blockIdx.x * 8 + wid;
    const int b = gw >> 11, n = gw & 2047;
    const int dc = lane * 2;

    float2 acc;
    float2 bb = *(const float2*)(bo + dc);
    acc.x = bb.x; acc.y = bb.y;

#pragma unroll 1
    for (int h = 0; h < HH; h++) {
        const int z = b * HH + h;
        const size_t row = (size_t)z * NN + n;
        const int cnt = g_cnt[row];
        const float* Pz = g_p + (size_t)z * NN * 64;
        if (cnt == -1) {
            const float Pu = 1.0f / 2048.0f;
            float2 s = *(const float2*)(g_psum + z * 64 + dc);
            acc.x = fmaf(Pu, s.x, acc.x);
            acc.y = fmaf(Pu, s.y, acc.y);
        } else if (cnt >= 0) {
            const int*   si = g_si + row * MAXS;
            const float* sw = g_sw + row * MAXS;
            for (int j = 0; j < cnt; j++) {
                int   i0 = si[j];
                float w0 = sw[j];
                float2 v = *(const float2*)(Pz + (size_t)i0 * 64 + dc);
                acc.x = fmaf(w0, v.x, acc.x);
                acc.y = fmaf(w0, v.y, acc.y);
            }
        } else {
            const float* arow = att + row * NN;
            for (int c = 0; c < NN; c++) {
                float p = arow[c];
                if (p != 0.f) {
                    float2 v = *(const float2*)(Pz + (size_t)c * 64 + dc);
                    acc.x = fmaf(p, v.x, acc.x);
                    acc.y = fmaf(p, v.y, acc.y);
                }
            }
        }
    }
    *(float2*)(out + (size_t)gw * 64 + dc) = acc;
}

// ===========================================================================
extern "C" void kernel_launch(void* const* d_in, const int* in_sizes, int n_in,
                              void* d_out, int out_size)
{
    const float* x   = (const float*)d_in[0];
    const unsigned char* mask_raw = (const unsigned char*)d_in[1];
    const float* Wq  = (const float*)d_in[2];
    const float* Wk  = (const float*)d_in[3];
    const float* Wv  = (const float*)d_in[4];
    const float* Wo  = (const float*)d_in[5];
    const float* bo  = (const float*)d_in[6];

    float* out = (float*)d_out;
    float* pre = out + OUT_ELEMS;
    float* att = pre + PRE_ELEMS;

    static int smem_set = 0;
    if (!smem_set) {
        cudaFuncSetAttribute(dots_gemm,
                             cudaFuncAttributeMaxDynamicSharedMemorySize, DOTS_SMEM);
        cudaFuncSetAttribute(proj_mma,
                             cudaFuncAttributeMaxDynamicSharedMemorySize, PROJ_SMEM);
        cudaFuncSetAttribute(pvw_mma,
                             cudaFuncAttributeMaxDynamicSharedMemorySize, PVW_SMEM);
        smem_set = 1;
    }

    prep_mask_kernel<<<1, 256>>>(mask_raw);

    conv_x_kernel<<<256, 256>>>(x);
    conv_w_kernel<<<dim3(384, 2), 256>>>(Wq, Wk, Wv);
    conv_wo_kernel<<<dim3(8, 8), 256>>>(Wo);

    proj_mma<<<dim3(96, 32), 256, PROJ_SMEM>>>();

    pvw_mma<<<dim3(16, 16), 256, PVW_SMEM>>>();
    psum_part_kernel<<<dim3(16, 8), 256>>>();
    psum_red_kernel<<<4, 256>>>();

    dots_gemm<<<dim3(16, 16, 16), 256, DOTS_SMEM>>>(pre);

    entmax_kernel<<<BB * HH * NN / 8, 256>>>(pre, att);

    af_kernel<<<BB * NN / 8, 256>>>(att, bo, out);
}

// round 11
// speedup vs baseline: 8.5824x; 1.0478x over previous
#include <cuda_runtime.h>
#include <cuda_bf16.h>
#include <cuda_fp16.h>
#include <cstdint>

// Problem constants
#define BB 2
#define NN 2048
#define DIMX 64
#define HH 8
#define DD 512            // per-head dim
#define INNER 4096
#define SCALE 0.125f
#define MASKV -1e9f

#define OUT_ELEMS   (BB*NN*DIMX)          // 262144
#define PRE_ELEMS   (BB*HH*NN*NN)         // 67108864

#define NROWS (BB*HH*NN)   // 32768
#define NZ    (BB*HH)      // 16
#define MAXS  512

// Scratch
__device__ __half g_qh[BB*HH*NN*DD];
__device__ __half g_ql[BB*HH*NN*DD];
__device__ __half g_kh[BB*HH*NN*DD];
__device__ __half g_vh[BB*HH*NN*DD];
__device__ __half g_vl[BB*HH*NN*DD];
__device__ __half g_xh[4096*64];
__device__ __half g_xl[4096*64];
__device__ __half g_wh[12288*64];
__device__ __half g_wl[12288*64];
__device__ __half g_wo[HH*64*DD];
__device__ float  g_p[(size_t)NZ * NN * 64];
__device__ float  g_psum[NZ * 64];
__device__ float  g_psumP[NZ][8][64];
__device__ int    g_mask[BB*NN];
__device__ int    g_slot[BB*NN];       // n -> compact slot (-1 if masked)
__device__ int    g_rowmap[BB][NN];    // compact slot -> n
__device__ int    g_validcnt[BB];
__device__ int    g_si[(size_t)NROWS * MAXS];
__device__ float  g_sw[(size_t)NROWS * MAXS];
__device__ int    g_cnt[NROWS];

// ===========================================================================
// Helpers
// ===========================================================================
__device__ __forceinline__ uint32_t smem_u32(const void* p) {
    uint32_t r;
    asm("{ .reg .u64 t; cvta.to.shared.u64 t, %1; cvt.u32.u64 %0, t; }" : "=r"(r) : "l"(p));
    return r;
}
__device__ __forceinline__ void ldsm_x4(uint32_t* r, uint32_t addr) {
    asm volatile("ldmatrix.sync.aligned.m8n8.x4.shared.b16 {%0,%1,%2,%3}, [%4];"
        : "=r"(r[0]), "=r"(r[1]), "=r"(r[2]), "=r"(r[3]) : "r"(addr));
}
__device__ __forceinline__ void mma_f16(float* c, const uint32_t* a, const uint32_t* b) {
    asm volatile("mma.sync.aligned.m16n8k16.row.col.f32.f16.f16.f32 "
        "{%0,%1,%2,%3}, {%4,%5,%6,%7}, {%8,%9}, {%0,%1,%2,%3};"
        : "+f"(c[0]), "+f"(c[1]), "+f"(c[2]), "+f"(c[3])
        : "r"(a[0]), "r"(a[1]), "r"(a[2]), "r"(a[3]), "r"(b[0]), "r"(b[1]));
}
#define CP16(saddr, gptr) \
    asm volatile("cp.async.cg.shared.global [%0], [%1], 16;" :: "r"(saddr), "l"(gptr))
#define CP_COMMIT() asm volatile("cp.async.commit_group;")
#define CP_WAIT2()  asm volatile("cp.async.wait_group 2;")
#define CP_WAIT1()  asm volatile("cp.async.wait_group 1;")
#define CP_WAIT0()  asm volatile("cp.async.wait_group 0;")

__device__ __forceinline__ uint32_t swz(uint32_t r, uint32_t kb) {
    uint32_t off = r * 64u + kb;
    return off ^ ((off >> 3) & 0x70u);
}
__device__ __forceinline__ void split4h(float4 v, uint2& hh, uint2& ll) {
    __half2 h01 = __floats2half2_rn(v.x, v.y);
    __half2 h23 = __floats2half2_rn(v.z, v.w);
    float2 f01 = __half22float2(h01);
    float2 f23 = __half22float2(h23);
    __half2 l01 = __floats2half2_rn(v.x - f01.x, v.y - f01.y);
    __half2 l23 = __floats2half2_rn(v.z - f23.x, v.w - f23.y);
    hh.x = *(uint32_t*)&h01; hh.y = *(uint32_t*)&h23;
    ll.x = *(uint32_t*)&l01; ll.y = *(uint32_t*)&l23;
}

// ===========================================================================
// Mask prep (dtype detect)
// ===========================================================================
__global__ void prep_mask_kernel(const unsigned char* __restrict__ raw) {
    __shared__ int cnt_f32, cnt_gt1;
    if (threadIdx.x == 0) { cnt_f32 = 0; cnt_gt1 = 0; }
    __syncthreads();
    const unsigned int* u = (const unsigned int*)raw;
    int lf = 0, lg = 0;
    for (int i = threadIdx.x; i < 1024; i += blockDim.x) {
        unsigned int v = u[i];
        if (v == 0x3f800000u) lf++;
        else if (v > 1u) lg++;
    }
    atomicAdd(&cnt_f32, lf);
    atomicAdd(&cnt_gt1, lg);
    __syncthreads();
    int mode;
    if (cnt_f32 > 64) mode = 2;
    else if (cnt_gt1 > 64) mode = 1;
    else mode = 0;
    for (int i = threadIdx.x; i < BB*NN; i += blockDim.x) {
        int m;
        if (mode == 2)      m = (((const unsigned int*)raw)[i] != 0u) ? 1 : 0;
        else if (mode == 1) m = raw[i] ? 1 : 0;
        else                m = (((const int*)raw)[i] != 0) ? 1 : 0;
        g_mask[i] = m;
    }
}

// ===========================================================================
// compact: per-b prefix-sum compaction of valid rows
// ===========================================================================
__global__ __launch_bounds__(256) void compact_kernel() {
    __shared__ int ps[256];
    for (int b = 0; b < BB; b++) {
        const int base_n = threadIdx.x * 8;
        int m[8], s = 0;
#pragma unroll
        for (int i = 0; i < 8; i++) { m[i] = g_mask[b * NN + base_n + i]; s += m[i]; }
        ps[threadIdx.x] = s;
        __syncthreads();
        for (int off = 1; off < 256; off <<= 1) {
            int v = ps[threadIdx.x];
            int u = (threadIdx.x >= off) ? ps[threadIdx.x - off] : 0;
            __syncthreads();
            ps[threadIdx.x] = v + u;
            __syncthreads();
        }
        int pos = threadIdx.x ? ps[threadIdx.x - 1] : 0;
#pragma unroll
        for (int i = 0; i < 8; i++) {
            if (m[i]) {
                g_rowmap[b][pos] = base_n + i;
                g_slot[b * NN + base_n + i] = pos;
                pos++;
            } else {
                g_slot[b * NN + base_n + i] = -1;
            }
        }
        if (threadIdx.x == 255) g_validcnt[b] = ps[255];
        __syncthreads();
    }
}

// ===========================================================================
// conv_x / conv_w / conv_wo
// ===========================================================================
__global__ __launch_bounds__(256) void conv_x_kernel(const float* __restrict__ X) {
    int idx = blockIdx.x * 256 + threadIdx.x;
    int m = idx >> 4;
    int k = (idx & 15) * 4;
    float4 v = ((const float4*)X)[idx];
    uint2 hh, ll;
    split4h(v, hh, ll);
    size_t tb = ((size_t)(m >> 7) * 2 + (k >> 5)) * 8192;
    uint32_t so = swz((uint32_t)(m & 127), (uint32_t)(k & 31) * 2);
    *(uint2*)((char*)g_xh + tb + so) = hh;
    *(uint2*)((char*)g_xl + tb + so) = ll;
}

__global__ __launch_bounds__(256) void conv_w_kernel(
    const float* __restrict__ Wq, const float* __restrict__ Wk, const float* __restrict__ Wv)
{
    __shared__ float t[32][33];
    const int n0 = blockIdx.x * 32;
    const int kt = blockIdx.y;
    const float* W = (n0 < 4096) ? Wq : (n0 < 8192) ? Wk : Wv;
    const int nl0 = n0 & 4095;
    const int tx = threadIdx.x & 31, ty8 = threadIdx.x >> 5;
#pragma unroll
    for (int i = 0; i < 4; i++) {
        int kk = ty8 + i * 8;
        t[kk][tx] = W[(size_t)(kt * 32 + kk) * 4096 + nl0 + tx];
    }
    __syncthreads();
    const int nn = threadIdx.x >> 3;
    const int k4 = (threadIdx.x & 7) * 4;
    float4 v = make_float4(t[k4][nn], t[k4+1][nn], t[k4+2][nn], t[k4+3][nn]);
    uint2 hh, ll;
    split4h(v, hh, ll);
    const int gn = n0 + nn;
    const int gk = kt * 32 + k4;
    size_t tb = ((size_t)(gn >> 7) * 2 + (gk >> 5)) * 8192;
    uint32_t so = swz((uint32_t)(gn & 127), (uint32_t)(gk & 31) * 2);
    *(uint2*)((char*)g_wh + tb + so) = hh;
    *(uint2*)((char*)g_wl + tb + so) = ll;
}

__global__ __launch_bounds__(256) void conv_wo_kernel(const float* __restrict__ Wo)
{
    __shared__ float t[64][65];
    const int h = blockIdx.y;
    const int d0 = blockIdx.x * 64;
#pragma unroll
    for (int i = 0; i < 16; i++) {
        int idx = threadIdx.x + i * 256;
        int dl = idx >> 6, dc = idx & 63;
        t[dl][dc] = Wo[(size_t)(h * 512 + d0 + dl) * 64 + dc];
    }
    __syncthreads();
#pragma unroll
    for (int i = 0; i < 4; i++) {
        int j = threadIdx.x + i * 256;
        int dc = j >> 4;
        int d4 = (j & 15) * 4;
        __half2 h01 = __floats2half2_rn(t[d4+0][dc], t[d4+1][dc]);
        __half2 h23 = __floats2half2_rn(t[d4+2][dc], t[d4+3][dc]);
        uint2 hv;
        hv.x = *(uint32_t*)&h01; hv.y = *(uint32_t*)&h23;
        const int d = d0 + d4;
        size_t tb = ((size_t)h * 16 + (d >> 5)) * 4096;
        uint32_t so = swz((uint32_t)dc, (uint32_t)(d & 31) * 2);
        *(uint2*)((char*)g_wo + tb + so) = hv;
    }
}

// ===========================================================================
// proj_mma: C = x @ [Wq|Wk|Wv], 3-term fp16 split, 2-chunk pipelined.
// Q rows stored at COMPACTED slot (masked Q rows dropped). K/V at original n.
// ===========================================================================
#define PROJ_SMEM 65536

__global__ __launch_bounds__(256, 2) void proj_mma()
{
    extern __shared__ char sm[];
    const uint32_t sbase = smem_u32(sm);
    const int tid = threadIdx.x;
    const int wid = tid >> 5, lane = tid & 31;
    const int wm = wid >> 2, wn = wid & 3;
    const int row0 = blockIdx.y * 128;
    const int col0 = blockIdx.x * 128;

    const char* xhB = (const char*)g_xh + (size_t)(blockIdx.y * 2) * 8192;
    const char* xlB = (const char*)g_xl + (size_t)(blockIdx.y * 2) * 8192;
    const char* whB = (const char*)g_wh + (size_t)(blockIdx.x * 2) * 8192;
    const char* wlB = (const char*)g_wl + (size_t)(blockIdx.x * 2) * 8192;

    auto issue = [&](int chk) {
        const uint32_t co = (uint32_t)chk * 8192;
#pragma unroll
        for (int k = 0; k < 2; k++) {
            uint32_t off = (uint32_t)(tid + k * 256) * 16;   // 8KB per region
            CP16(sbase + co + off,          xhB + co + off);
            CP16(sbase + 16384 + co + off,  xlB + co + off);
            CP16(sbase + 32768 + co + off,  whB + co + off);
            CP16(sbase + 49152 + co + off,  wlB + co + off);
        }
    };
    issue(0); CP_COMMIT();
    issue(1); CP_COMMIT();

    float acc[4][4][4];
#pragma unroll
    for (int mf = 0; mf < 4; mf++)
#pragma unroll
        for (int nf = 0; nf < 4; nf++)
#pragma unroll
            for (int r = 0; r < 4; r++) acc[mf][nf][r] = 0.f;

    const uint32_t a_row = (uint32_t)(wm * 64) + (lane & 15);
    const uint32_t a_kb  = ((lane >> 4) & 1) * 16;
    const uint32_t b_row = (uint32_t)(wn * 32) + ((lane >> 4) & 1) * 8 + (lane & 7);
    const uint32_t b_kb  = ((lane >> 3) & 1) * 16;

#pragma unroll
    for (int chk = 0; chk < 2; chk++) {
        if (chk == 0) CP_WAIT1(); else CP_WAIT0();
        __syncthreads();
        const uint32_t AH = sbase + (uint32_t)chk * 8192;
        const uint32_t AL = AH + 16384;
        const uint32_t BH = sbase + 32768 + (uint32_t)chk * 8192;
        const uint32_t BL = BH + 16384;
#pragma unroll
        for (int ks = 0; ks < 2; ks++) {
            const uint32_t kb0 = (uint32_t)ks * 32;
            uint32_t bh[4][2], bl[4][2];
#pragma unroll
            for (int p = 0; p < 2; p++) {
                uint32_t o = swz(b_row + p * 16, kb0 + b_kb);
                uint32_t t4[4];
                ldsm_x4(t4, BH + o);
                bh[2*p][0] = t4[0]; bh[2*p][1] = t4[1];
                bh[2*p+1][0] = t4[2]; bh[2*p+1][1] = t4[3];
                ldsm_x4(t4, BL + o);
                bl[2*p][0] = t4[0]; bl[2*p][1] = t4[1];
                bl[2*p+1][0] = t4[2]; bl[2*p+1][1] = t4[3];
            }
#pragma unroll
            for (int mf = 0; mf < 4; mf++) {
                uint32_t o = swz(a_row + mf * 16, kb0 + a_kb);
                uint32_t ah[4], al[4];
                ldsm_x4(ah, AH + o);
                ldsm_x4(al, AL + o);
#pragma unroll
                for (int nf = 0; nf < 4; nf++) {
                    mma_f16(acc[mf][nf], ah, bh[nf]);
                    mma_f16(acc[mf][nf], ah, bl[nf]);
                    mma_f16(acc[mf][nf], al, bh[nf]);
                }
            }
        }
    }

    // epilogue
    const int wsel = col0 >> 12;           // 0=Q 1=K 2=V
    const int dcol0 = col0 & 4095;
    const int r_lo = row0 + wm * 64 + (lane >> 2);
    const int c_base = wn * 32 + (lane & 3) * 2;
#pragma unroll
    for (int mf = 0; mf < 4; mf++) {
#pragma unroll
        for (int nf = 0; nf < 4; nf++) {
            const int cg = c_base + nf * 8;
            const int col = dcol0 + cg;
            const int h = col >> 9, dd = col & 511;
#pragma unroll
            for (int rr = 0; rr < 2; rr++) {
                float v0 = acc[mf][nf][rr*2+0];
                float v1 = acc[mf][nf][rr*2+1];
                const int m = r_lo + mf * 16 + rr * 8;
                const int b = m >> 11, n = m & 2047;
                int nrow = n;
                if (wsel == 0) {
                    nrow = g_slot[b * NN + n];
                    if (nrow < 0) continue;
                }
                size_t tb = (((size_t)(b*HH+h) * 16 + (nrow >> 7)) * 16 + (dd >> 5)) * 8192;
                uint32_t so = swz((uint32_t)(nrow & 127), (uint32_t)(dd & 31) * 2);
                __half2 hv = __floats2half2_rn(v0, v1);
                if (wsel == 1) {
                    *(uint32_t*)((char*)g_kh + tb + so) = *(uint32_t*)&hv;
                } else {
                    float2 f = __half22float2(hv);
                    __half2 lv = __floats2half2_rn(v0 - f.x, v1 - f.y);
                    if (wsel == 0) {
                        *(uint32_t*)((char*)g_qh + tb + so) = *(uint32_t*)&hv;
                        *(uint32_t*)((char*)g_ql + tb + so) = *(uint32_t*)&lv;
                    } else {
                        *(uint32_t*)((char*)g_vh + tb + so) = *(uint32_t*)&hv;
                        *(uint32_t*)((char*)g_vl + tb + so) = *(uint32_t*)&lv;
                    }
                }
            }
        }
    }
}

// ===========================================================================
// pvw_mma: P[z] = (Vh+Vl) @ Woh^T
// ===========================================================================
#define PVW_STAGE 20480u
#define PVW_SMEM (2 * 20480)

__global__ __launch_bounds__(256, 2) void pvw_mma()
{
    extern __shared__ char sm[];
    const uint32_t sbase = smem_u32(sm);
    const int tid = threadIdx.x;
    const int wid = tid >> 5, lane = tid & 31;
    const int wm = wid >> 1, wn = wid & 1;
    const int z = blockIdx.y, h = z & 7;
    const int nt = blockIdx.x;

    const char* vhB = (const char*)g_vh + (((size_t)z * 16 + nt) * 16) * 8192;
    const char* vlB = (const char*)g_vl + (((size_t)z * 16 + nt) * 16) * 8192;
    const char* woB = (const char*)g_wo + (size_t)(h * 16) * 4096;

    float acc[2][4][4];
#pragma unroll
    for (int mf = 0; mf < 2; mf++)
#pragma unroll
        for (int nf = 0; nf < 4; nf++)
#pragma unroll
            for (int r = 0; r < 4; r++) acc[mf][nf][r] = 0.f;

    auto issue = [&](int ch) {
        const uint32_t ss = sbase + (uint32_t)(ch & 1) * PVW_STAGE;
#pragma unroll
        for (int k = 0; k < 2; k++) {
            uint32_t off = (uint32_t)(tid + k * 256) * 16;
            CP16(ss + off,        vhB + (size_t)ch * 8192 + off);
            CP16(ss + 8192 + off, vlB + (size_t)ch * 8192 + off);
        }
        {
            uint32_t off = (uint32_t)tid * 16;
            CP16(ss + 16384 + off, woB + (size_t)ch * 4096 + off);
        }
    };

    issue(0); CP_COMMIT();

    const uint32_t a_row = (uint32_t)(wm * 32) + (lane & 15);
    const uint32_t a_kb  = ((lane >> 4) & 1) * 16;
    const uint32_t b_row = (uint32_t)(wn * 32) + ((lane >> 4) & 1) * 8 + (lane & 7);
    const uint32_t b_kb  = ((lane >> 3) & 1) * 16;

    for (int ch = 0; ch < 16; ++ch) {
        if (ch + 1 < 16) { issue(ch + 1); CP_COMMIT(); CP_WAIT1(); }
        else CP_WAIT0();
        __syncthreads();
        const uint32_t S = sbase + (uint32_t)(ch & 1) * PVW_STAGE;
        const uint32_t AH = S, AL = S + 8192, BH = S + 16384;
#pragma unroll
        for (int ks = 0; ks < 2; ks++) {
            const uint32_t kb0 = (uint32_t)ks * 32;
            uint32_t bh[4][2];
#pragma unroll
            for (int p = 0; p < 2; p++) {
                uint32_t o = swz(b_row + p * 16, kb0 + b_kb);
                uint32_t t4[4];
                ldsm_x4(t4, BH + o);
                bh[2*p][0] = t4[0]; bh[2*p][1] = t4[1];
                bh[2*p+1][0] = t4[2]; bh[2*p+1][1] = t4[3];
            }
#pragma unroll
            for (int mf = 0; mf < 2; mf++) {
                uint32_t o = swz(a_row + mf * 16, kb0 + a_kb);
                uint32_t ah[4], al[4];
                ldsm_x4(ah, AH + o);
                ldsm_x4(al, AL + o);
#pragma unroll
                for (int nf = 0; nf < 4; nf++) {
                    mma_f16(acc[mf][nf], ah, bh[nf]);
                    mma_f16(acc[mf][nf], al, bh[nf]);
                }
            }
        }
        __syncthreads();
    }

    const int r_lo = nt * 128 + wm * 32 + (lane >> 2);
    const int c_base = wn * 32 + (lane & 3) * 2;
    float* Pz = g_p + (size_t)z * NN * 64;
#pragma unroll
    for (int mf = 0; mf < 2; mf++) {
        int rg0 = r_lo + mf * 16;
#pragma unroll
        for (int nf = 0; nf < 4; nf++) {
            int cg = c_base + nf * 8;
            *(float2*)(Pz + (size_t)rg0 * 64 + cg)       = make_float2(acc[mf][nf][0], acc[mf][nf][1]);
            *(float2*)(Pz + (size_t)(rg0 + 8) * 64 + cg) = make_float2(acc[mf][nf][2], acc[mf][nf][3]);
        }
    }
}

// ===========================================================================
// psum: 2-phase parallel reduction
// ===========================================================================
__global__ __launch_bounds__(256) void psum_part_kernel()
{
    __shared__ float red[4][64];
    const int z = blockIdx.x, seg = blockIdx.y;
    const int d = threadIdx.x & 63, sub = threadIdx.x >> 6;
    const float* p = g_p + ((size_t)z * NN + seg * 256 + sub * 64) * 64 + d;
    float s = 0.f;
#pragma unroll 8
    for (int n = 0; n < 64; n++) s += p[(size_t)n * 64];
    red[sub][d] = s;
    __syncthreads();
    if (threadIdx.x < 64)
        g_psumP[z][seg][d] = red[0][d] + red[1][d] + red[2][d] + red[3][d];
}
__global__ __launch_bounds__(256) void psum_red_kernel()
{
    const int i = blockIdx.x * 256 + threadIdx.x;
    const int z = i >> 6, d = i & 63;
    float s = 0.f;
#pragma unroll
    for (int g = 0; g < 8; g++) s += g_psumP[z][g][d];
    g_psum[z * 64 + d] = s;
}

// ===========================================================================
// fill_pre: masked rows of pre -> MASKV
// ===========================================================================
__global__ __launch_bounds__(256) void fill_pre_kernel(float* __restrict__ pre)
{
    const int row = blockIdx.x;
    const int z = row >> 11, n = row & 2047, b = z >> 3;
    if (g_mask[b * NN + n]) return;
    float4* p = (float4*)(pre + (size_t)row * NN);
    const float4 mv = make_float4(MASKV, MASKV, MASKV, MASKV);
#pragma unroll
    for (int i = 0; i < 2; i++)
        p[threadIdx.x + i * 256] = mv;
}

// ===========================================================================
// dots = scale*(Qh+Ql)@Kh^T (+col mask) on COMPACTED rows -> pre (row-scattered)
// ===========================================================================
#define DSTAGE 24576u
#define DOTS_SMEM (4 * 24576)

__global__ __launch_bounds__(256, 2) void dots_gemm(float* __restrict__ Out)
{
    extern __shared__ char sm[];
    __shared__ int cmask[128];
    const uint32_t sbase = smem_u32(sm);

    const int tid = threadIdx.x;
    const int wid = tid >> 5, lane = tid & 31;
    const int wm = wid >> 2, wn = wid & 3;
    const int z = blockIdx.z, b = z >> 3;
    const int row0 = blockIdx.y * 128, col0 = blockIdx.x * 128;

    const int cnt = g_validcnt[b];
    if (row0 >= cnt) return;

    if (tid < 128) cmask[tid] = g_mask[b * NN + col0 + tid];

    const char* qhB = (const char*)g_qh + (((size_t)z * 16 + blockIdx.y) * 16) * 8192;
    const char* qlB = (const char*)g_ql + (((size_t)z * 16 + blockIdx.y) * 16) * 8192;
    const char* khB = (const char*)g_kh + (((size_t)z * 16 + blockIdx.x) * 16) * 8192;

    float acc[4][4][4];
#pragma unroll
    for (int mf = 0; mf < 4; mf++)
#pragma unroll
        for (int nf = 0; nf < 4; nf++)
#pragma unroll
            for (int r = 0; r < 4; r++) acc[mf][nf][r] = 0.f;

    auto issue = [&](int ch) {
        const uint32_t ss = sbase + (uint32_t)(ch & 3) * DSTAGE;
        const char* q1 = qhB + (size_t)ch * 8192;
        const char* l1 = qlB + (size_t)ch * 8192;
        const char* k1 = khB + (size_t)ch * 8192;
#pragma unroll
        for (int k = 0; k < 2; k++) {
            uint32_t off = (uint32_t)(tid + k * 256) * 16;
            CP16(ss + off,         q1 + off);
            CP16(ss + 8192 + off,  l1 + off);
            CP16(ss + 16384 + off, k1 + off);
        }
    };

    issue(0); CP_COMMIT();
    issue(1); CP_COMMIT();
    issue(2); CP_COMMIT();

    const uint32_t a_row = (uint32_t)(wm * 64) + (lane & 15);
    const uint32_t a_kb  = ((lane >> 4) & 1) * 16;
    const uint32_t b_row = (uint32_t)(wn * 32) + ((lane >> 4) & 1) * 8 + (lane & 7);
    const uint32_t b_kb  = ((lane >> 3) & 1) * 16;

    for (int ch = 0; ch < 16; ++ch) {
        CP_WAIT2();
        __syncthreads();
        const uint32_t S = sbase + (uint32_t)(ch & 3) * DSTAGE;
        const uint32_t AH = S, AL = S + 8192, BH = S + 16384;
#pragma unroll
        for (int ks = 0; ks < 2; ks++) {
            const uint32_t kb0 = (uint32_t)ks * 32;
            uint32_t bh[4][2];
#pragma unroll
            for (int p = 0; p < 2; p++) {
                uint32_t o = swz(b_row + p * 16, kb0 + b_kb);
                uint32_t t4[4];
                ldsm_x4(t4, BH + o);
                bh[2*p][0] = t4[0]; bh[2*p][1] = t4[1];
                bh[2*p+1][0] = t4[2]; bh[2*p+1][1] = t4[3];
            }
#pragma unroll
            for (int mf = 0; mf < 4; mf++) {
                uint32_t o = swz(a_row + mf * 16, kb0 + a_kb);
                uint32_t ah[4], al[4];
                ldsm_x4(ah, AH + o);
                ldsm_x4(al, AL + o);
#pragma unroll
                for (int nf = 0; nf < 4; nf++) {
                    mma_f16(acc[mf][nf], ah, bh[nf]);
                    mma_f16(acc[mf][nf], al, bh[nf]);
                }
            }
        }
        if (ch + 3 < 16) issue(ch + 3);
        CP_COMMIT();
    }

    const int r_lo = row0 + wm * 64 + (lane >> 2);
    const int c_base = wn * 32 + (lane & 3) * 2;
    float* outz = Out + (size_t)z * NN * NN;
#pragma unroll
    for (int mf = 0; mf < 4; mf++) {
#pragma unroll
        for (int rr = 0; rr < 2; rr++) {
            const int cr = r_lo + mf * 16 + rr * 8;
            if (cr >= cnt) continue;
            const int orig = g_rowmap[b][cr];
            float* rowp = outz + (size_t)orig * NN + col0;
#pragma unroll
            for (int nf = 0; nf < 4; nf++) {
                int cg = c_base + nf * 8;
                float2 v;
                v.x = cmask[cg]     ? acc[mf][nf][rr*2+0] * SCALE : MASKV;
                v.y = cmask[cg + 1] ? acc[mf][nf][rr*2+1] * SCALE : MASKV;
                *(float2*)(rowp + cg) = v;
            }
        }
    }
}

// ===========================================================================
// entmax-1.5: one warp per row + compact list; Newton with uniform early-exit
// ===========================================================================
__global__ __launch_bounds__(256) void entmax_kernel(
    const float* __restrict__ pre, float* __restrict__ att)
{
    const int wid = threadIdx.x >> 5, lane = threadIdx.x & 31;
    const size_t row = (size_t)blockIdx.x * 8 + wid;
    const int z = (int)(row >> 11), n = (int)(row & 2047), b = z >> 3;
    float4* o4 = (float4*)(att + row * NN);

    if (!g_mask[b * NN + n]) {
        const float P = 1.0f / 2048.0f;
        float4 u = make_float4(P, P, P, P);
#pragma unroll
        for (int i = 0; i < 16; i++) o4[lane + i * 32] = u;
        if (lane == 0) g_cnt[row] = -1;
        return;
    }

    const float4* p4 = (const float4*)(pre + row * NN);
    float x[64];
    float mx = -3.0e38f;
#pragma unroll
    for (int i = 0; i < 16; i++) {
        float4 v = p4[lane + i * 32];
        x[4*i+0] = 0.5f * v.x; x[4*i+1] = 0.5f * v.y;
        x[4*i+2] = 0.5f * v.z; x[4*i+3] = 0.5f * v.w;
        mx = fmaxf(mx, fmaxf(fmaxf(x[4*i], x[4*i+1]), fmaxf(x[4*i+2], x[4*i+3])));
    }
#pragma unroll
    for (int off = 16; off; off >>= 1)
        mx = fmaxf(mx, __shfl_xor_sync(0xffffffffu, mx, off));
#pragma unroll
    for (int j = 0; j < 64; j++) x[j] -= mx;

    float tau = -1.0f;
#pragma unroll 1
    for (int it = 0; it < 12; ++it) {
        float s1 = 0.f, s2 = 0.f;
#pragma unroll
        for (int j = 0; j < 64; j++) {
            float d = fmaxf(x[j] - tau, 0.f);
            s1 += d;
            s2 = fmaf(d, d, s2);
        }
#pragma unroll
        for (int off = 16; off; off >>= 1) {
            s1 += __shfl_xor_sync(0xffffffffu, s1, off);
            s2 += __shfl_xor_sync(0xffffffffu, s2, off);
        }
        float step = (s1 > 1e-20f) ? (s2 - 1.0f) / (2.0f * s1) : 0.f;
        tau += step;
        if (fabsf(step) < 1e-6f) break;
    }

#pragma unroll
    for (int i = 0; i < 16; i++) {
        float4 w;
        float d;
        d = fmaxf(x[4*i+0] - tau, 0.f); w.x = d * d;
        d = fmaxf(x[4*i+1] - tau, 0.f); w.y = d * d;
        d = fmaxf(x[4*i+2] - tau, 0.f); w.z = d * d;
        d = fmaxf(x[4*i+3] - tau, 0.f); w.w = d * d;
        o4[lane + i * 32] = w;
    }

    int cl = 0;
#pragma unroll
    for (int j = 0; j < 64; j++) cl += (x[j] > tau) ? 1 : 0;
    int v = cl;
#pragma unroll
    for (int d = 1; d < 32; d <<= 1) {
        int t = __shfl_up_sync(0xffffffffu, v, d);
        if (lane >= d) v += t;
    }
    int total = __shfl_sync(0xffffffffu, v, 31);
    int pos = v - cl;
    if (total <= MAXS) {
        int*   si = g_si + row * MAXS;
        float* sw = g_sw + row * MAXS;
#pragma unroll
        for (int i = 0; i < 16; i++)
#pragma unroll
            for (int c = 0; c < 4; c++) {
                int j = 4*i + c;
                if (x[j] > tau) {
                    float d = x[j] - tau;
                    si[pos] = 4*lane + 128*i + c;
                    sw[pos] = d * d;
                    pos++;
                }
            }
        if (lane == 31) g_cnt[row] = total;
    } else if (lane == 31) {
        g_cnt[row] = -2;
    }
}

// ===========================================================================
// Fused sparse attention-out
// ===========================================================================
__global__ __launch_bounds__(256) void af_kernel(
    const float* __restrict__ att, const float* __restrict__ bo, float* __restrict__ out)
{
    const int wid = threadIdx.x >> 5, lane = threadIdx.x & 31;
    const int gw = blockIdx.x * 8 + wid;
    const int b = gw >> 11, n = gw & 2047;
    const int dc = lane * 2;

    float2 acc;
    float2 bb = *(const float2*)(bo + dc);
    acc.x = bb.x; acc.y = bb.y;

#pragma unroll 1
    for (int h = 0; h < HH; h++) {
        const int z = b * HH + h;
        const size_t row = (size_t)z * NN + n;
        const int cnt = g_cnt[row];
        const float* Pz = g_p + (size_t)z * NN * 64;
        if (cnt == -1) {
            const float Pu = 1.0f / 2048.0f;
            float2 s = *(const float2*)(g_psum + z * 64 + dc);
            acc.x = fmaf(Pu, s.x, acc.x);
            acc.y = fmaf(Pu, s.y, acc.y);
        } else if (cnt >= 0) {
            const int*   si = g_si + row * MAXS;
            const float* sw = g_sw + row * MAXS;
            for (int j = 0; j < cnt; j++) {
                int   i0 = si[j];
                float w0 = sw[j];
                float2 v = *(const float2*)(Pz + (size_t)i0 * 64 + dc);
                acc.x = fmaf(w0, v.x, acc.x);
                acc.y = fmaf(w0, v.y, acc.y);
            }
        } else {
            const float* arow = att + row * NN;
            for (int c = 0; c < NN; c++) {
                float p = arow[c];
                if (p != 0.f) {
                    float2 v = *(const float2*)(Pz + (size_t)c * 64 + dc);
                    acc.x = fmaf(p, v.x, acc.x);
                    acc.y = fmaf(p, v.y, acc.y);
                }
            }
        }
    }
    *(float2*)(out + (size_t)gw * 64 + dc) = acc;
}

// ===========================================================================
extern "C" void kernel_launch(void* const* d_in, const int* in_sizes, int n_in,
                              void* d_out, int out_size)
{
    const float* x   = (const float*)d_in[0];
    const unsigned char* mask_raw = (const unsigned char*)d_in[1];
    const float* Wq  = (const float*)d_in[2];
    const float* Wk  = (const float*)d_in[3];
    const float* Wv  = (const float*)d_in[4];
    const float* Wo  = (const float*)d_in[5];
    const float* bo  = (const float*)d_in[6];

    float* out = (float*)d_out;
    float* pre = out + OUT_ELEMS;
    float* att = pre + PRE_ELEMS;

    static int smem_set = 0;
    if (!smem_set) {
        cudaFuncSetAttribute(dots_gemm,
                             cudaFuncAttributeMaxDynamicSharedMemorySize, DOTS_SMEM);
        cudaFuncSetAttribute(proj_mma,
                             cudaFuncAttributeMaxDynamicSharedMemorySize, PROJ_SMEM);
        cudaFuncSetAttribute(pvw_mma,
                             cudaFuncAttributeMaxDynamicSharedMemorySize, PVW_SMEM);
        smem_set = 1;
    }

    prep_mask_kernel<<<1, 256>>>(mask_raw);
    compact_kernel<<<1, 256>>>();

    conv_x_kernel<<<256, 256>>>(x);
    conv_w_kernel<<<dim3(384, 2), 256>>>(Wq, Wk, Wv);
    conv_wo_kernel<<<dim3(8, 8), 256>>>(Wo);

    proj_mma<<<dim3(96, 32), 256, PROJ_SMEM>>>();

    pvw_mma<<<dim3(16, 16), 256, PVW_SMEM>>>();
    psum_part_kernel<<<dim3(16, 8), 256>>>();
    psum_red_kernel<<<4, 256>>>();

    fill_pre_kernel<<<NROWS, 256>>>(pre);

    dots_gemm<<<dim3(16, 16, 16), 256, DOTS_SMEM>>>(pre);

    entmax_kernel<<<BB * HH * NN / 8, 256>>>(pre, att);

    af_kernel<<<BB * NN / 8, 256>>>(att, bo, out);
}

// round 12
// speedup vs baseline: 8.6649x; 1.0096x over previous
#include <cuda_runtime.h>
#include <cuda_bf16.h>
#include <cuda_fp16.h>
#include <cstdint>

// Problem constants
#define BB 2
#define NN 2048
#define DIMX 64
#define HH 8
#define DD 512            // per-head dim
#define INNER 4096
#define SCALE 0.125f
#define MASKV -1e9f

#define OUT_ELEMS   (BB*NN*DIMX)          // 262144
#define PRE_ELEMS   (BB*HH*NN*NN)         // 67108864

#define NROWS (BB*HH*NN)   // 32768
#define NZ    (BB*HH)      // 16
#define MAXS  512

// Scratch
__device__ __half g_qh[BB*HH*NN*DD];
__device__ __half g_ql[BB*HH*NN*DD];
__device__ __half g_kh[BB*HH*NN*DD];
__device__ __half g_vh[BB*HH*NN*DD];
__device__ __half g_vl[BB*HH*NN*DD];
__device__ __half g_xh[4096*64];
__device__ __half g_xl[4096*64];
__device__ __half g_wh[12288*64];
__device__ __half g_wl[12288*64];
__device__ __half g_wo[HH*64*DD];
__device__ float  g_p[(size_t)NZ * NN * 64];
__device__ float  g_psum[NZ * 64];
__device__ float  g_psumP[NZ][8][64];
__device__ int    g_mask[BB*NN];
__device__ int    g_slot[BB*NN];         // n -> compact slot (-1 if masked)
__device__ int    g_rowmap[BB][NN];      // compact slot -> n (valid rows)
__device__ int    g_maskedmap[BB][NN];   // masked slot -> n (masked rows)
__device__ int    g_validcnt[BB];
__device__ int    g_si[(size_t)NROWS * MAXS];
__device__ float  g_sw[(size_t)NROWS * MAXS];
__device__ int    g_cnt[NROWS];

// ===========================================================================
// Helpers
// ===========================================================================
__device__ __forceinline__ uint32_t smem_u32(const void* p) {
    uint32_t r;
    asm("{ .reg .u64 t; cvta.to.shared.u64 t, %1; cvt.u32.u64 %0, t; }" : "=r"(r) : "l"(p));
    return r;
}
__device__ __forceinline__ void ldsm_x4(uint32_t* r, uint32_t addr) {
    asm volatile("ldmatrix.sync.aligned.m8n8.x4.shared.b16 {%0,%1,%2,%3}, [%4];"
        : "=r"(r[0]), "=r"(r[1]), "=r"(r[2]), "=r"(r[3]) : "r"(addr));
}
__device__ __forceinline__ void mma_f16(float* c, const uint32_t* a, const uint32_t* b) {
    asm volatile("mma.sync.aligned.m16n8k16.row.col.f32.f16.f16.f32 "
        "{%0,%1,%2,%3}, {%4,%5,%6,%7}, {%8,%9}, {%0,%1,%2,%3};"
        : "+f"(c[0]), "+f"(c[1]), "+f"(c[2]), "+f"(c[3])
        : "r"(a[0]), "r"(a[1]), "r"(a[2]), "r"(a[3]), "r"(b[0]), "r"(b[1]));
}
#define CP16(saddr, gptr) \
    asm volatile("cp.async.cg.shared.global [%0], [%1], 16;" :: "r"(saddr), "l"(gptr))
#define CP_COMMIT() asm volatile("cp.async.commit_group;")
#define CP_WAIT2()  asm volatile("cp.async.wait_group 2;")
#define CP_WAIT1()  asm volatile("cp.async.wait_group 1;")
#define CP_WAIT0()  asm volatile("cp.async.wait_group 0;")

__device__ __forceinline__ uint32_t swz(uint32_t r, uint32_t kb) {
    uint32_t off = r * 64u + kb;
    return off ^ ((off >> 3) & 0x70u);
}
__device__ __forceinline__ void split4h(float4 v, uint2& hh, uint2& ll) {
    __half2 h01 = __floats2half2_rn(v.x, v.y);
    __half2 h23 = __floats2half2_rn(v.z, v.w);
    float2 f01 = __half22float2(h01);
    float2 f23 = __half22float2(h23);
    __half2 l01 = __floats2half2_rn(v.x - f01.x, v.y - f01.y);
    __half2 l23 = __floats2half2_rn(v.z - f23.x, v.w - f23.y);
    hh.x = *(uint32_t*)&h01; hh.y = *(uint32_t*)&h23;
    ll.x = *(uint32_t*)&l01; ll.y = *(uint32_t*)&l23;
}

// ===========================================================================
// prep_mask + compact merged (single block)
// ===========================================================================
__global__ __launch_bounds__(256) void prep_compact_kernel(const unsigned char* __restrict__ raw) {
    __shared__ int cnt_f32, cnt_gt1;
    __shared__ int ps[256];
    if (threadIdx.x == 0) { cnt_f32 = 0; cnt_gt1 = 0; }
    __syncthreads();
    const unsigned int* u = (const unsigned int*)raw;
    int lf = 0, lg = 0;
    for (int i = threadIdx.x; i < 1024; i += blockDim.x) {
        unsigned int v = u[i];
        if (v == 0x3f800000u) lf++;
        else if (v > 1u) lg++;
    }
    atomicAdd(&cnt_f32, lf);
    atomicAdd(&cnt_gt1, lg);
    __syncthreads();
    int mode;
    if (cnt_f32 > 64) mode = 2;
    else if (cnt_gt1 > 64) mode = 1;
    else mode = 0;
    for (int i = threadIdx.x; i < BB*NN; i += blockDim.x) {
        int m;
        if (mode == 2)      m = (((const unsigned int*)raw)[i] != 0u) ? 1 : 0;
        else if (mode == 1) m = raw[i] ? 1 : 0;
        else                m = (((const int*)raw)[i] != 0) ? 1 : 0;
        g_mask[i] = m;
    }
    __syncthreads();

    for (int b = 0; b < BB; b++) {
        const int base_n = threadIdx.x * 8;
        int m[8], s = 0;
#pragma unroll
        for (int i = 0; i < 8; i++) { m[i] = g_mask[b * NN + base_n + i]; s += m[i]; }
        ps[threadIdx.x] = s;
        __syncthreads();
        for (int off = 1; off < 256; off <<= 1) {
            int v = ps[threadIdx.x];
            int u2 = (threadIdx.x >= off) ? ps[threadIdx.x - off] : 0;
            __syncthreads();
            ps[threadIdx.x] = v + u2;
            __syncthreads();
        }
        int pos = threadIdx.x ? ps[threadIdx.x - 1] : 0;
#pragma unroll
        for (int i = 0; i < 8; i++) {
            int n = base_n + i;
            if (m[i]) {
                g_rowmap[b][pos] = n;
                g_slot[b * NN + n] = pos;
                pos++;
            } else {
                g_maskedmap[b][n - pos] = n;   // masked index = n - (#valid before n)
                g_slot[b * NN + n] = -1;
            }
        }
        if (threadIdx.x == 255) g_validcnt[b] = ps[255];
        __syncthreads();
    }
}

// ===========================================================================
// conv_x / conv_w / conv_wo
// ===========================================================================
__global__ __launch_bounds__(256) void conv_x_kernel(const float* __restrict__ X) {
    int idx = blockIdx.x * 256 + threadIdx.x;
    int m = idx >> 4;
    int k = (idx & 15) * 4;
    float4 v = ((const float4*)X)[idx];
    uint2 hh, ll;
    split4h(v, hh, ll);
    size_t tb = ((size_t)(m >> 7) * 2 + (k >> 5)) * 8192;
    uint32_t so = swz((uint32_t)(m & 127), (uint32_t)(k & 31) * 2);
    *(uint2*)((char*)g_xh + tb + so) = hh;
    *(uint2*)((char*)g_xl + tb + so) = ll;
}

__global__ __launch_bounds__(256) void conv_w_kernel(
    const float* __restrict__ Wq, const float* __restrict__ Wk, const float* __restrict__ Wv)
{
    __shared__ float t[32][33];
    const int n0 = blockIdx.x * 32;
    const int kt = blockIdx.y;
    const float* W = (n0 < 4096) ? Wq : (n0 < 8192) ? Wk : Wv;
    const int nl0 = n0 & 4095;
    const int tx = threadIdx.x & 31, ty8 = threadIdx.x >> 5;
#pragma unroll
    for (int i = 0; i < 4; i++) {
        int kk = ty8 + i * 8;
        t[kk][tx] = W[(size_t)(kt * 32 + kk) * 4096 + nl0 + tx];
    }
    __syncthreads();
    const int nn = threadIdx.x >> 3;
    const int k4 = (threadIdx.x & 7) * 4;
    float4 v = make_float4(t[k4][nn], t[k4+1][nn], t[k4+2][nn], t[k4+3][nn]);
    uint2 hh, ll;
    split4h(v, hh, ll);
    const int gn = n0 + nn;
    const int gk = kt * 32 + k4;
    size_t tb = ((size_t)(gn >> 7) * 2 + (gk >> 5)) * 8192;
    uint32_t so = swz((uint32_t)(gn & 127), (uint32_t)(gk & 31) * 2);
    *(uint2*)((char*)g_wh + tb + so) = hh;
    *(uint2*)((char*)g_wl + tb + so) = ll;
}

__global__ __launch_bounds__(256) void conv_wo_kernel(const float* __restrict__ Wo)
{
    __shared__ float t[64][65];
    const int h = blockIdx.y;
    const int d0 = blockIdx.x * 64;
#pragma unroll
    for (int i = 0; i < 16; i++) {
        int idx = threadIdx.x + i * 256;
        int dl = idx >> 6, dc = idx & 63;
        t[dl][dc] = Wo[(size_t)(h * 512 + d0 + dl) * 64 + dc];
    }
    __syncthreads();
#pragma unroll
    for (int i = 0; i < 4; i++) {
        int j = threadIdx.x + i * 256;
        int dc = j >> 4;
        int d4 = (j & 15) * 4;
        __half2 h01 = __floats2half2_rn(t[d4+0][dc], t[d4+1][dc]);
        __half2 h23 = __floats2half2_rn(t[d4+2][dc], t[d4+3][dc]);
        uint2 hv;
        hv.x = *(uint32_t*)&h01; hv.y = *(uint32_t*)&h23;
        const int d = d0 + d4;
        size_t tb = ((size_t)h * 16 + (d >> 5)) * 4096;
        uint32_t so = swz((uint32_t)dc, (uint32_t)(d & 31) * 2);
        *(uint2*)((char*)g_wo + tb + so) = hv;
    }
}

// ===========================================================================
// proj_mma: C = x @ [Wq|Wk|Wv], 3-term fp16 split, 2-chunk pipelined.
// Epilogue: SMEM repack -> uint4 (16B) stores. Q rows at compact slot.
// SMEM: max(64KB operands, 128x132 fp32 accum = 67584B)
// ===========================================================================
#define PROJ_SMEM 67584

__global__ __launch_bounds__(256, 2) void proj_mma()
{
    extern __shared__ char sm[];
    const uint32_t sbase = smem_u32(sm);
    const int tid = threadIdx.x;
    const int wid = tid >> 5, lane = tid & 31;
    const int wm = wid >> 2, wn = wid & 3;
    const int row0 = blockIdx.y * 128;
    const int col0 = blockIdx.x * 128;

    const char* xhB = (const char*)g_xh + (size_t)(blockIdx.y * 2) * 8192;
    const char* xlB = (const char*)g_xl + (size_t)(blockIdx.y * 2) * 8192;
    const char* whB = (const char*)g_wh + (size_t)(blockIdx.x * 2) * 8192;
    const char* wlB = (const char*)g_wl + (size_t)(blockIdx.x * 2) * 8192;

    auto issue = [&](int chk) {
        const uint32_t co = (uint32_t)chk * 8192;
#pragma unroll
        for (int k = 0; k < 2; k++) {
            uint32_t off = (uint32_t)(tid + k * 256) * 16;
            CP16(sbase + co + off,          xhB + co + off);
            CP16(sbase + 16384 + co + off,  xlB + co + off);
            CP16(sbase + 32768 + co + off,  whB + co + off);
            CP16(sbase + 49152 + co + off,  wlB + co + off);
        }
    };
    issue(0); CP_COMMIT();
    issue(1); CP_COMMIT();

    float acc[4][4][4];
#pragma unroll
    for (int mf = 0; mf < 4; mf++)
#pragma unroll
        for (int nf = 0; nf < 4; nf++)
#pragma unroll
            for (int r = 0; r < 4; r++) acc[mf][nf][r] = 0.f;

    const uint32_t a_row = (uint32_t)(wm * 64) + (lane & 15);
    const uint32_t a_kb  = ((lane >> 4) & 1) * 16;
    const uint32_t b_row = (uint32_t)(wn * 32) + ((lane >> 4) & 1) * 8 + (lane & 7);
    const uint32_t b_kb  = ((lane >> 3) & 1) * 16;

#pragma unroll
    for (int chk = 0; chk < 2; chk++) {
        if (chk == 0) CP_WAIT1(); else CP_WAIT0();
        __syncthreads();
        const uint32_t AH = sbase + (uint32_t)chk * 8192;
        const uint32_t AL = AH + 16384;
        const uint32_t BH = sbase + 32768 + (uint32_t)chk * 8192;
        const uint32_t BL = BH + 16384;
#pragma unroll
        for (int ks = 0; ks < 2; ks++) {
            const uint32_t kb0 = (uint32_t)ks * 32;
            uint32_t bh[4][2], bl[4][2];
#pragma unroll
            for (int p = 0; p < 2; p++) {
                uint32_t o = swz(b_row + p * 16, kb0 + b_kb);
                uint32_t t4[4];
                ldsm_x4(t4, BH + o);
                bh[2*p][0] = t4[0]; bh[2*p][1] = t4[1];
                bh[2*p+1][0] = t4[2]; bh[2*p+1][1] = t4[3];
                ldsm_x4(t4, BL + o);
                bl[2*p][0] = t4[0]; bl[2*p][1] = t4[1];
                bl[2*p+1][0] = t4[2]; bl[2*p+1][1] = t4[3];
            }
#pragma unroll
            for (int mf = 0; mf < 4; mf++) {
                uint32_t o = swz(a_row + mf * 16, kb0 + a_kb);
                uint32_t ah[4], al[4];
                ldsm_x4(ah, AH + o);
                ldsm_x4(al, AL + o);
#pragma unroll
                for (int nf = 0; nf < 4; nf++) {
                    mma_f16(acc[mf][nf], ah, bh[nf]);
                    mma_f16(acc[mf][nf], ah, bl[nf]);
                    mma_f16(acc[mf][nf], al, bh[nf]);
                }
            }
        }
    }

    // ---- repack through SMEM ----
    __syncthreads();
    float* sacc = (float*)sm;   // [128][132]
    {
        const int rb = wm * 64 + (lane >> 2);
        const int cb = wn * 32 + (lane & 3) * 2;
#pragma unroll
        for (int mf = 0; mf < 4; mf++)
#pragma unroll
            for (int nf = 0; nf < 4; nf++)
#pragma unroll
                for (int rr = 0; rr < 2; rr++) {
                    int r = rb + mf * 16 + rr * 8;
                    int c = cb + nf * 8;
                    *(float2*)(sacc + r * 132 + c) =
                        make_float2(acc[mf][nf][rr*2+0], acc[mf][nf][rr*2+1]);
                }
    }
    __syncthreads();

    const int wsel = col0 >> 12;           // 0=Q 1=K 2=V
    const int dcol0 = col0 & 4095;
    const int r = tid >> 1;
    const int cH = (tid & 1) * 64;
    const int m = row0 + r;
    const int b = m >> 11, n = m & 2047;
    int nrow = n;
    if (wsel == 0) nrow = g_slot[b * NN + n];
    if (wsel != 0 || nrow >= 0) {
        const float* rowp = sacc + r * 132 + cH;
#pragma unroll
        for (int g = 0; g < 8; g++) {
            const int cg = cH + g * 8;
            const int col = dcol0 + cg;
            const int h = col >> 9, dd = col & 511;
            float4 e0 = *(const float4*)(rowp + g * 8);
            float4 e1 = *(const float4*)(rowp + g * 8 + 4);
            __half2 h0 = __floats2half2_rn(e0.x, e0.y);
            __half2 h1 = __floats2half2_rn(e0.z, e0.w);
            __half2 h2 = __floats2half2_rn(e1.x, e1.y);
            __half2 h3 = __floats2half2_rn(e1.z, e1.w);
            uint4 hv = make_uint4(*(uint32_t*)&h0, *(uint32_t*)&h1,
                                  *(uint32_t*)&h2, *(uint32_t*)&h3);
            size_t tb = (((size_t)(b*HH+h) * 16 + (nrow >> 7)) * 16 + (dd >> 5)) * 8192;
            uint32_t so = swz((uint32_t)(nrow & 127), (uint32_t)(dd & 31) * 2);
            if (wsel == 1) {
                *(uint4*)((char*)g_kh + tb + so) = hv;
            } else {
                float2 f0 = __half22float2(h0), f1 = __half22float2(h1);
                float2 f2 = __half22float2(h2), f3 = __half22float2(h3);
                __half2 l0 = __floats2half2_rn(e0.x - f0.x, e0.y - f0.y);
                __half2 l1 = __floats2half2_rn(e0.z - f1.x, e0.w - f1.y);
                __half2 l2 = __floats2half2_rn(e1.x - f2.x, e1.y - f2.y);
                __half2 l3 = __floats2half2_rn(e1.z - f3.x, e1.w - f3.y);
                uint4 lv = make_uint4(*(uint32_t*)&l0, *(uint32_t*)&l1,
                                      *(uint32_t*)&l2, *(uint32_t*)&l3);
                if (wsel == 0) {
                    *(uint4*)((char*)g_qh + tb + so) = hv;
                    *(uint4*)((char*)g_ql + tb + so) = lv;
                } else {
                    *(uint4*)((char*)g_vh + tb + so) = hv;
                    *(uint4*)((char*)g_vl + tb + so) = lv;
                }
            }
        }
    }
}

// ===========================================================================
// pvw_mma: P[z] = (Vh+Vl) @ Woh^T
// ===========================================================================
#define PVW_STAGE 20480u
#define PVW_SMEM (2 * 20480)

__global__ __launch_bounds__(256, 2) void pvw_mma()
{
    extern __shared__ char sm[];
    const uint32_t sbase = smem_u32(sm);
    const int tid = threadIdx.x;
    const int wid = tid >> 5, lane = tid & 31;
    const int wm = wid >> 1, wn = wid & 1;
    const int z = blockIdx.y, h = z & 7;
    const int nt = blockIdx.x;

    const char* vhB = (const char*)g_vh + (((size_t)z * 16 + nt) * 16) * 8192;
    const char* vlB = (const char*)g_vl + (((size_t)z * 16 + nt) * 16) * 8192;
    const char* woB = (const char*)g_wo + (size_t)(h * 16) * 4096;

    float acc[2][4][4];
#pragma unroll
    for (int mf = 0; mf < 2; mf++)
#pragma unroll
        for (int nf = 0; nf < 4; nf++)
#pragma unroll
            for (int r = 0; r < 4; r++) acc[mf][nf][r] = 0.f;

    auto issue = [&](int ch) {
        const uint32_t ss = sbase + (uint32_t)(ch & 1) * PVW_STAGE;
#pragma unroll
        for (int k = 0; k < 2; k++) {
            uint32_t off = (uint32_t)(tid + k * 256) * 16;
            CP16(ss + off,        vhB + (size_t)ch * 8192 + off);
            CP16(ss + 8192 + off, vlB + (size_t)ch * 8192 + off);
        }
        {
            uint32_t off = (uint32_t)tid * 16;
            CP16(ss + 16384 + off, woB + (size_t)ch * 4096 + off);
        }
    };

    issue(0); CP_COMMIT();

    const uint32_t a_row = (uint32_t)(wm * 32) + (lane & 15);
    const uint32_t a_kb  = ((lane >> 4) & 1) * 16;
    const uint32_t b_row = (uint32_t)(wn * 32) + ((lane >> 4) & 1) * 8 + (lane & 7);
    const uint32_t b_kb  = ((lane >> 3) & 1) * 16;

    for (int ch = 0; ch < 16; ++ch) {
        if (ch + 1 < 16) { issue(ch + 1); CP_COMMIT(); CP_WAIT1(); }
        else CP_WAIT0();
        __syncthreads();
        const uint32_t S = sbase + (uint32_t)(ch & 1) * PVW_STAGE;
        const uint32_t AH = S, AL = S + 8192, BH = S + 16384;
#pragma unroll
        for (int ks = 0; ks < 2; ks++) {
            const uint32_t kb0 = (uint32_t)ks * 32;
            uint32_t bh[4][2];
#pragma unroll
            for (int p = 0; p < 2; p++) {
                uint32_t o = swz(b_row + p * 16, kb0 + b_kb);
                uint32_t t4[4];
                ldsm_x4(t4, BH + o);
                bh[2*p][0] = t4[0]; bh[2*p][1] = t4[1];
                bh[2*p+1][0] = t4[2]; bh[2*p+1][1] = t4[3];
            }
#pragma unroll
            for (int mf = 0; mf < 2; mf++) {
                uint32_t o = swz(a_row + mf * 16, kb0 + a_kb);
                uint32_t ah[4], al[4];
                ldsm_x4(ah, AH + o);
                ldsm_x4(al, AL + o);
#pragma unroll
                for (int nf = 0; nf < 4; nf++) {
                    mma_f16(acc[mf][nf], ah, bh[nf]);
                    mma_f16(acc[mf][nf], al, bh[nf]);
                }
            }
        }
        __syncthreads();
    }

    const int r_lo = nt * 128 + wm * 32 + (lane >> 2);
    const int c_base = wn * 32 + (lane & 3) * 2;
    float* Pz = g_p + (size_t)z * NN * 64;
#pragma unroll
    for (int mf = 0; mf < 2; mf++) {
        int rg0 = r_lo + mf * 16;
#pragma unroll
        for (int nf = 0; nf < 4; nf++) {
            int cg = c_base + nf * 8;
            *(float2*)(Pz + (size_t)rg0 * 64 + cg)       = make_float2(acc[mf][nf][0], acc[mf][nf][1]);
            *(float2*)(Pz + (size_t)(rg0 + 8) * 64 + cg) = make_float2(acc[mf][nf][2], acc[mf][nf][3]);
        }
    }
}

// ===========================================================================
// psum: 2-phase parallel reduction
// ===========================================================================
__global__ __launch_bounds__(256) void psum_part_kernel()
{
    __shared__ float red[4][64];
    const int z = blockIdx.x, seg = blockIdx.y;
    const int d = threadIdx.x & 63, sub = threadIdx.x >> 6;
    const float* p = g_p + ((size_t)z * NN + seg * 256 + sub * 64) * 64 + d;
    float s = 0.f;
#pragma unroll 8
    for (int n = 0; n < 64; n++) s += p[(size_t)n * 64];
    red[sub][d] = s;
    __syncthreads();
    if (threadIdx.x < 64)
        g_psumP[z][seg][d] = red[0][d] + red[1][d] + red[2][d] + red[3][d];
}
__global__ __launch_bounds__(256) void psum_red_kernel()
{
    const int i = blockIdx.x * 256 + threadIdx.x;
    const int z = i >> 6, d = i & 63;
    float s = 0.f;
#pragma unroll
    for (int g = 0; g < 8; g++) s += g_psumP[z][g][d];
    g_psum[z * 64 + d] = s;
}

// ===========================================================================
// dots = scale*(Qh+Ql)@Kh^T (+col mask) on COMPACTED rows -> pre (row-scattered)
// Tiles beyond validcnt (and tile tails) write MASKV rows via maskedmap.
// ===========================================================================
#define DSTAGE 24576u
#define DOTS_SMEM (4 * 24576)

__global__ __launch_bounds__(256, 2) void dots_gemm(float* __restrict__ Out)
{
    extern __shared__ char sm[];
    __shared__ int cmask[128];
    const uint32_t sbase = smem_u32(sm);

    const int tid = threadIdx.x;
    const int wid = tid >> 5, lane = tid & 31;
    const int wm = wid >> 2, wn = wid & 3;
    const int z = blockIdx.z, b = z >> 3;
    const int row0 = blockIdx.y * 128, col0 = blockIdx.x * 128;

    const int cnt = g_validcnt[b];

    float acc[4][4][4];

    if (row0 < cnt) {
        if (tid < 128) cmask[tid] = g_mask[b * NN + col0 + tid];

        const char* qhB = (const char*)g_qh + (((size_t)z * 16 + blockIdx.y) * 16) * 8192;
        const char* qlB = (const char*)g_ql + (((size_t)z * 16 + blockIdx.y) * 16) * 8192;
        const char* khB = (const char*)g_kh + (((size_t)z * 16 + blockIdx.x) * 16) * 8192;

#pragma unroll
        for (int mf = 0; mf < 4; mf++)
#pragma unroll
            for (int nf = 0; nf < 4; nf++)
#pragma unroll
                for (int r = 0; r < 4; r++) acc[mf][nf][r] = 0.f;

        auto issue = [&](int ch) {
            const uint32_t ss = sbase + (uint32_t)(ch & 3) * DSTAGE;
            const char* q1 = qhB + (size_t)ch * 8192;
            const char* l1 = qlB + (size_t)ch * 8192;
            const char* k1 = khB + (size_t)ch * 8192;
#pragma unroll
            for (int k = 0; k < 2; k++) {
                uint32_t off = (uint32_t)(tid + k * 256) * 16;
                CP16(ss + off,         q1 + off);
                CP16(ss + 8192 + off,  l1 + off);
                CP16(ss + 16384 + off, k1 + off);
            }
        };

        issue(0); CP_COMMIT();
        issue(1); CP_COMMIT();
        issue(2); CP_COMMIT();

        const uint32_t a_row = (uint32_t)(wm * 64) + (lane & 15);
        const uint32_t a_kb  = ((lane >> 4) & 1) * 16;
        const uint32_t b_row = (uint32_t)(wn * 32) + ((lane >> 4) & 1) * 8 + (lane & 7);
        const uint32_t b_kb  = ((lane >> 3) & 1) * 16;

        for (int ch = 0; ch < 16; ++ch) {
            CP_WAIT2();
            __syncthreads();
            const uint32_t S = sbase + (uint32_t)(ch & 3) * DSTAGE;
            const uint32_t AH = S, AL = S + 8192, BH = S + 16384;
#pragma unroll
            for (int ks = 0; ks < 2; ks++) {
                const uint32_t kb0 = (uint32_t)ks * 32;
                uint32_t bh[4][2];
#pragma unroll
                for (int p = 0; p < 2; p++) {
                    uint32_t o = swz(b_row + p * 16, kb0 + b_kb);
                    uint32_t t4[4];
                    ldsm_x4(t4, BH + o);
                    bh[2*p][0] = t4[0]; bh[2*p][1] = t4[1];
                    bh[2*p+1][0] = t4[2]; bh[2*p+1][1] = t4[3];
                }
#pragma unroll
                for (int mf = 0; mf < 4; mf++) {
                    uint32_t o = swz(a_row + mf * 16, kb0 + a_kb);
                    uint32_t ah[4], al[4];
                    ldsm_x4(ah, AH + o);
                    ldsm_x4(al, AL + o);
#pragma unroll
                    for (int nf = 0; nf < 4; nf++) {
                        mma_f16(acc[mf][nf], ah, bh[nf]);
                        mma_f16(acc[mf][nf], al, bh[nf]);
                    }
                }
            }
            if (ch + 3 < 16) issue(ch + 3);
            CP_COMMIT();
        }
    }

    // epilogue: valid rows -> scaled/masked result; rows >= cnt -> MASKV fill
    const int r_lo = row0 + wm * 64 + (lane >> 2);
    const int c_base = wn * 32 + (lane & 3) * 2;
    float* outz = Out + (size_t)z * NN * NN;
#pragma unroll
    for (int mf = 0; mf < 4; mf++) {
#pragma unroll
        for (int rr = 0; rr < 2; rr++) {
            const int cr = r_lo + mf * 16 + rr * 8;
            if (cr < cnt) {
                const int orig = g_rowmap[b][cr];
                float* rowp = outz + (size_t)orig * NN + col0;
#pragma unroll
                for (int nf = 0; nf < 4; nf++) {
                    int cg = c_base + nf * 8;
                    float2 v;
                    v.x = cmask[cg]     ? acc[mf][nf][rr*2+0] * SCALE : MASKV;
                    v.y = cmask[cg + 1] ? acc[mf][nf][rr*2+1] * SCALE : MASKV;
                    *(float2*)(rowp + cg) = v;
                }
            } else {
                const int orig = g_maskedmap[b][cr - cnt];
                float* rowp = outz + (size_t)orig * NN + col0;
                const float2 mv = make_float2(MASKV, MASKV);
#pragma unroll
                for (int nf = 0; nf < 4; nf++)
                    *(float2*)(rowp + c_base + nf * 8) = mv;
            }
        }
    }
}

// ===========================================================================
// entmax-1.5: one warp per row + compact list; Newton with uniform early-exit
// ===========================================================================
__global__ __launch_bounds__(256) void entmax_kernel(
    const float* __restrict__ pre, float* __restrict__ att)
{
    const int wid = threadIdx.x >> 5, lane = threadIdx.x & 31;
    const size_t row = (size_t)blockIdx.x * 8 + wid;
    const int z = (int)(row >> 11), n = (int)(row & 2047), b = z >> 3;
    float4* o4 = (float4*)(att + row * NN);

    if (!g_mask[b * NN + n]) {
        const float P = 1.0f / 2048.0f;
        float4 u = make_float4(P, P, P, P);
#pragma unroll
        for (int i = 0; i < 16; i++) o4[lane + i * 32] = u;
        if (lane == 0) g_cnt[row] = -1;
        return;
    }

    const float4* p4 = (const float4*)(pre + row * NN);
    float x[64];
    float mx = -3.0e38f;
#pragma unroll
    for (int i = 0; i < 16; i++) {
        float4 v = p4[lane + i * 32];
        x[4*i+0] = 0.5f * v.x; x[4*i+1] = 0.5f * v.y;
        x[4*i+2] = 0.5f * v.z; x[4*i+3] = 0.5f * v.w;
        mx = fmaxf(mx, fmaxf(fmaxf(x[4*i], x[4*i+1]), fmaxf(x[4*i+2], x[4*i+3])));
    }
#pragma unroll
    for (int off = 16; off; off >>= 1)
        mx = fmaxf(mx, __shfl_xor_sync(0xffffffffu, mx, off));
#pragma unroll
    for (int j = 0; j < 64; j++) x[j] -= mx;

    float tau = -1.0f;
#pragma unroll 1
    for (int it = 0; it < 12; ++it) {
        float s1 = 0.f, s2 = 0.f;
#pragma unroll
        for (int j = 0; j < 64; j++) {
            float d = fmaxf(x[j] - tau, 0.f);
            s1 += d;
            s2 = fmaf(d, d, s2);
        }
#pragma unroll
        for (int off = 16; off; off >>= 1) {
            s1 += __shfl_xor_sync(0xffffffffu, s1, off);
            s2 += __shfl_xor_sync(0xffffffffu, s2, off);
        }
        float step = (s1 > 1e-20f) ? (s2 - 1.0f) / (2.0f * s1) : 0.f;
        tau += step;
        if (fabsf(step) < 1e-6f) break;
    }

#pragma unroll
    for (int i = 0; i < 16; i++) {
        float4 w;
        float d;
        d = fmaxf(x[4*i+0] - tau, 0.f); w.x = d * d;
        d = fmaxf(x[4*i+1] - tau, 0.f); w.y = d * d;
        d = fmaxf(x[4*i+2] - tau, 0.f); w.z = d * d;
        d = fmaxf(x[4*i+3] - tau, 0.f); w.w = d * d;
        o4[lane + i * 32] = w;
    }

    int cl = 0;
#pragma unroll
    for (int j = 0; j < 64; j++) cl += (x[j] > tau) ? 1 : 0;
    int v = cl;
#pragma unroll
    for (int d = 1; d < 32; d <<= 1) {
        int t = __shfl_up_sync(0xffffffffu, v, d);
        if (lane >= d) v += t;
    }
    int total = __shfl_sync(0xffffffffu, v, 31);
    int pos = v - cl;
    if (total <= MAXS) {
        int*   si = g_si + row * MAXS;
        float* sw = g_sw + row * MAXS;
#pragma unroll
        for (int i = 0; i < 16; i++)
#pragma unroll
            for (int c = 0; c < 4; c++) {
                int j = 4*i + c;
                if (x[j] > tau) {
                    float d = x[j] - tau;
                    si[pos] = 4*lane + 128*i + c;
                    sw[pos] = d * d;
                    pos++;
                }
            }
        if (lane == 31) g_cnt[row] = total;
    } else if (lane == 31) {
        g_cnt[row] = -2;
    }
}

// ===========================================================================
// Fused sparse attention-out
// ===========================================================================
__global__ __launch_bounds__(256) void af_kernel(
    const float* __restrict__ att, const float* __restrict__ bo, float* __restrict__ out)
{
    const int wid = threadIdx.x >> 5, lane = threadIdx.x & 31;
    const int gw = blockIdx.x * 8 + wid;
    const int b = gw >> 11, n = gw & 2047;
    const int dc = lane * 2;

    float2 acc;
    float2 bb = *(const float2*)(bo + dc);
    acc.x = bb.x; acc.y = bb.y;

#pragma unroll 1
    for (int h = 0; h < HH; h++) {
        const int z = b * HH + h;
        const size_t row = (size_t)z * NN + n;
        const int cnt = g_cnt[row];
        const float* Pz = g_p + (size_t)z * NN * 64;
        if (cnt == -1) {
            const float Pu = 1.0f / 2048.0f;
            float2 s = *(const float2*)(g_psum + z * 64 + dc);
            acc.x = fmaf(Pu, s.x, acc.x);
            acc.y = fmaf(Pu, s.y, acc.y);
        } else if (cnt >= 0) {
            const int*   si = g_si + row * MAXS;
            const float* sw = g_sw + row * MAXS;
            for (int j = 0; j < cnt; j++) {
                int   i0 = si[j];
                float w0 = sw[j];
                float2 v = *(const float2*)(Pz + (size_t)i0 * 64 + dc);
                acc.x = fmaf(w0, v.x, acc.x);
                acc.y = fmaf(w0, v.y, acc.y);
            }
        } else {
            const float* arow = att + row * NN;
            for (int c = 0; c < NN; c++) {
                float p = arow[c];
                if (p != 0.f) {
                    float2 v = *(const float2*)(Pz + (size_t)c * 64 + dc);
                    acc.x = fmaf(p, v.x, acc.x);
                    acc.y = fmaf(p, v.y, acc.y);
                }
            }
        }
    }
    *(float2*)(out + (size_t)gw * 64 + dc) = acc;
}

// ===========================================================================
extern "C" void kernel_launch(void* const* d_in, const int* in_sizes, int n_in,
                              void* d_out, int out_size)
{
    const float* x   = (const float*)d_in[0];
    const unsigned char* mask_raw = (const unsigned char*)d_in[1];
    const float* Wq  = (const float*)d_in[2];
    const float* Wk  = (const float*)d_in[3];
    const float* Wv  = (const float*)d_in[4];
    const float* Wo  = (const float*)d_in[5];
    const float* bo  = (const float*)d_in[6];

    float* out = (float*)d_out;
    float* pre = out + OUT_ELEMS;
    float* att = pre + PRE_ELEMS;

    static int smem_set = 0;
    if (!smem_set) {
        cudaFuncSetAttribute(dots_gemm,
                             cudaFuncAttributeMaxDynamicSharedMemorySize, DOTS_SMEM);
        cudaFuncSetAttribute(proj_mma,
                             cudaFuncAttributeMaxDynamicSharedMemorySize, PROJ_SMEM);
        cudaFuncSetAttribute(pvw_mma,
                             cudaFuncAttributeMaxDynamicSharedMemorySize, PVW_SMEM);
        smem_set = 1;
    }

    prep_compact_kernel<<<1, 256>>>(mask_raw);

    conv_x_kernel<<<256, 256>>>(x);
    conv_w_kernel<<<dim3(384, 2), 256>>>(Wq, Wk, Wv);
    conv_wo_kernel<<<dim3(8, 8), 256>>>(Wo);

    proj_mma<<<dim3(96, 32), 256, PROJ_SMEM>>>();

    pvw_mma<<<dim3(16, 16), 256, PVW_SMEM>>>();
    psum_part_kernel<<<dim3(16, 8), 256>>>();
    psum_red_kernel<<<4, 256>>>();

    dots_gemm<<<dim3(16, 16, 16), 256, DOTS_SMEM>>>(pre);

    entmax_kernel<<<BB * HH * NN / 8, 256>>>(pre, att);

    af_kernel<<<BB * NN / 8, 256>>>(att, bo, out);
}

// round 13
// speedup vs baseline: 8.6992x; 1.0040x over previous
#include <cuda_runtime.h>
#include <cuda_bf16.h>
#include <cuda_fp16.h>
#include <cstdint>

// Problem constants
#define BB 2
#define NN 2048
#define DIMX 64
#define HH 8
#define DD 512            // per-head dim
#define INNER 4096
#define SCALE 0.125f
#define MASKV -1e9f

#define OUT_ELEMS   (BB*NN*DIMX)          // 262144
#define PRE_ELEMS   (BB*HH*NN*NN)         // 67108864

#define NROWS (BB*HH*NN)   // 32768
#define NZ    (BB*HH)      // 16
#define MAXS  512

// Scratch
__device__ __half g_qh[BB*HH*NN*DD];
__device__ __half g_ql[BB*HH*NN*DD];
__device__ __half g_kh[BB*HH*NN*DD];
__device__ __half g_vh[BB*HH*NN*DD];
__device__ __half g_vl[BB*HH*NN*DD];
__device__ __half g_xh[4096*64];
__device__ __half g_xl[4096*64];
__device__ __half g_wh[12288*64];
__device__ __half g_wl[12288*64];
__device__ __half g_wo[HH*64*DD];
__device__ float  g_p[(size_t)NZ * NN * 64];
__device__ float  g_psum[NZ * 64];
__device__ float  g_psumP[NZ][8][64];
__device__ int    g_mask[BB*NN];
__device__ int    g_slot[BB*NN];         // n -> compact slot (-1 if masked)
__device__ int    g_rowmap[BB][NN];      // compact slot -> n (valid rows)
__device__ int    g_maskedmap[BB][NN];   // masked slot -> n (masked rows)
__device__ int    g_validcnt[BB];
__device__ int    g_si[(size_t)NROWS * MAXS];
__device__ float  g_sw[(size_t)NROWS * MAXS];
__device__ int    g_cnt[NROWS];

// ===========================================================================
// Helpers
// ===========================================================================
__device__ __forceinline__ uint32_t smem_u32(const void* p) {
    uint32_t r;
    asm("{ .reg .u64 t; cvta.to.shared.u64 t, %1; cvt.u32.u64 %0, t; }" : "=r"(r) : "l"(p));
    return r;
}
__device__ __forceinline__ void ldsm_x4(uint32_t* r, uint32_t addr) {
    asm volatile("ldmatrix.sync.aligned.m8n8.x4.shared.b16 {%0,%1,%2,%3}, [%4];"
        : "=r"(r[0]), "=r"(r[1]), "=r"(r[2]), "=r"(r[3]) : "r"(addr));
}
__device__ __forceinline__ void mma_f16(float* c, const uint32_t* a, const uint32_t* b) {
    asm volatile("mma.sync.aligned.m16n8k16.row.col.f32.f16.f16.f32 "
        "{%0,%1,%2,%3}, {%4,%5,%6,%7}, {%8,%9}, {%0,%1,%2,%3};"
        : "+f"(c[0]), "+f"(c[1]), "+f"(c[2]), "+f"(c[3])
        : "r"(a[0]), "r"(a[1]), "r"(a[2]), "r"(a[3]), "r"(b[0]), "r"(b[1]));
}
#define CP16(saddr, gptr) \
    asm volatile("cp.async.cg.shared.global [%0], [%1], 16;" :: "r"(saddr), "l"(gptr))
#define CP_COMMIT() asm volatile("cp.async.commit_group;")
#define CP_WAIT2()  asm volatile("cp.async.wait_group 2;")
#define CP_WAIT1()  asm volatile("cp.async.wait_group 1;")
#define CP_WAIT0()  asm volatile("cp.async.wait_group 0;")

__device__ __forceinline__ uint32_t swz(uint32_t r, uint32_t kb) {
    uint32_t off = r * 64u + kb;
    return off ^ ((off >> 3) & 0x70u);
}
__device__ __forceinline__ void split4h(float4 v, uint2& hh, uint2& ll) {
    __half2 h01 = __floats2half2_rn(v.x, v.y);
    __half2 h23 = __floats2half2_rn(v.z, v.w);
    float2 f01 = __half22float2(h01);
    float2 f23 = __half22float2(h23);
    __half2 l01 = __floats2half2_rn(v.x - f01.x, v.y - f01.y);
    __half2 l23 = __floats2half2_rn(v.z - f23.x, v.w - f23.y);
    hh.x = *(uint32_t*)&h01; hh.y = *(uint32_t*)&h23;
    ll.x = *(uint32_t*)&l01; ll.y = *(uint32_t*)&l23;
}

// ===========================================================================
// prep_mask + compact merged (single block)
// ===========================================================================
__global__ __launch_bounds__(256) void prep_compact_kernel(const unsigned char* __restrict__ raw) {
    __shared__ int cnt_f32, cnt_gt1;
    __shared__ int ps[256];
    if (threadIdx.x == 0) { cnt_f32 = 0; cnt_gt1 = 0; }
    __syncthreads();
    const unsigned int* u = (const unsigned int*)raw;
    int lf = 0, lg = 0;
    for (int i = threadIdx.x; i < 1024; i += blockDim.x) {
        unsigned int v = u[i];
        if (v == 0x3f800000u) lf++;
        else if (v > 1u) lg++;
    }
    atomicAdd(&cnt_f32, lf);
    atomicAdd(&cnt_gt1, lg);
    __syncthreads();
    int mode;
    if (cnt_f32 > 64) mode = 2;
    else if (cnt_gt1 > 64) mode = 1;
    else mode = 0;
    for (int i = threadIdx.x; i < BB*NN; i += blockDim.x) {
        int m;
        if (mode == 2)      m = (((const unsigned int*)raw)[i] != 0u) ? 1 : 0;
        else if (mode == 1) m = raw[i] ? 1 : 0;
        else                m = (((const int*)raw)[i] != 0) ? 1 : 0;
        g_mask[i] = m;
    }
    __syncthreads();

    for (int b = 0; b < BB; b++) {
        const int base_n = threadIdx.x * 8;
        int m[8], s = 0;
#pragma unroll
        for (int i = 0; i < 8; i++) { m[i] = g_mask[b * NN + base_n + i]; s += m[i]; }
        ps[threadIdx.x] = s;
        __syncthreads();
        for (int off = 1; off < 256; off <<= 1) {
            int v = ps[threadIdx.x];
            int u2 = (threadIdx.x >= off) ? ps[threadIdx.x - off] : 0;
            __syncthreads();
            ps[threadIdx.x] = v + u2;
            __syncthreads();
        }
        int pos = threadIdx.x ? ps[threadIdx.x - 1] : 0;
#pragma unroll
        for (int i = 0; i < 8; i++) {
            int n = base_n + i;
            if (m[i]) {
                g_rowmap[b][pos] = n;
                g_slot[b * NN + n] = pos;
                pos++;
            } else {
                g_maskedmap[b][n - pos] = n;
                g_slot[b * NN + n] = -1;
            }
        }
        if (threadIdx.x == 255) g_validcnt[b] = ps[255];
        __syncthreads();
    }
}

// ===========================================================================
// conv_all: fused conv_x (blocks 0..255), conv_w (256..1023), conv_wo (1024..1087)
// ===========================================================================
__global__ __launch_bounds__(256) void conv_all_kernel(
    const float* __restrict__ X,
    const float* __restrict__ Wq, const float* __restrict__ Wk, const float* __restrict__ Wv,
    const float* __restrict__ Wo)
{
    __shared__ float sh[64 * 65];
    const int bx = blockIdx.x;
    if (bx < 256) {
        // conv_x
        int idx = bx * 256 + threadIdx.x;
        int m = idx >> 4;
        int k = (idx & 15) * 4;
        float4 v = ((const float4*)X)[idx];
        uint2 hh, ll;
        split4h(v, hh, ll);
        size_t tb = ((size_t)(m >> 7) * 2 + (k >> 5)) * 8192;
        uint32_t so = swz((uint32_t)(m & 127), (uint32_t)(k & 31) * 2);
        *(uint2*)((char*)g_xh + tb + so) = hh;
        *(uint2*)((char*)g_xl + tb + so) = ll;
    } else if (bx < 1024) {
        // conv_w
        float (*t)[33] = (float(*)[33])sh;
        const int i = bx - 256;
        const int kt = i / 384;
        const int n0 = (i % 384) * 32;
        const float* W = (n0 < 4096) ? Wq : (n0 < 8192) ? Wk : Wv;
        const int nl0 = n0 & 4095;
        const int tx = threadIdx.x & 31, ty8 = threadIdx.x >> 5;
#pragma unroll
        for (int j = 0; j < 4; j++) {
            int kk = ty8 + j * 8;
            t[kk][tx] = W[(size_t)(kt * 32 + kk) * 4096 + nl0 + tx];
        }
        __syncthreads();
        const int nn = threadIdx.x >> 3;
        const int k4 = (threadIdx.x & 7) * 4;
        float4 v = make_float4(t[k4][nn], t[k4+1][nn], t[k4+2][nn], t[k4+3][nn]);
        uint2 hh, ll;
        split4h(v, hh, ll);
        const int gn = n0 + nn;
        const int gk = kt * 32 + k4;
        size_t tb = ((size_t)(gn >> 7) * 2 + (gk >> 5)) * 8192;
        uint32_t so = swz((uint32_t)(gn & 127), (uint32_t)(gk & 31) * 2);
        *(uint2*)((char*)g_wh + tb + so) = hh;
        *(uint2*)((char*)g_wl + tb + so) = ll;
    } else {
        // conv_wo
        float (*t)[65] = (float(*)[65])sh;
        const int i = bx - 1024;
        const int h = i >> 3;
        const int d0 = (i & 7) * 64;
#pragma unroll
        for (int j = 0; j < 16; j++) {
            int idx = threadIdx.x + j * 256;
            int dl = idx >> 6, dc = idx & 63;
            t[dl][dc] = Wo[(size_t)(h * 512 + d0 + dl) * 64 + dc];
        }
        __syncthreads();
#pragma unroll
        for (int j = 0; j < 4; j++) {
            int jj = threadIdx.x + j * 256;
            int dc = jj >> 4;
            int d4 = (jj & 15) * 4;
            __half2 h01 = __floats2half2_rn(t[d4+0][dc], t[d4+1][dc]);
            __half2 h23 = __floats2half2_rn(t[d4+2][dc], t[d4+3][dc]);
            uint2 hv;
            hv.x = *(uint32_t*)&h01; hv.y = *(uint32_t*)&h23;
            const int d = d0 + d4;
            size_t tb = ((size_t)h * 16 + (d >> 5)) * 4096;
            uint32_t so = swz((uint32_t)dc, (uint32_t)(d & 31) * 2);
            *(uint2*)((char*)g_wo + tb + so) = hv;
        }
    }
}

// ===========================================================================
// proj_mma: C = x @ [Wq|Wk|Wv], 3-term fp16 split, 2-chunk pipelined.
// Epilogue: SMEM repack -> uint4 stores. Q rows at compact slot.
// ===========================================================================
#define PROJ_SMEM 67584

__global__ __launch_bounds__(256, 2) void proj_mma()
{
    extern __shared__ char sm[];
    const uint32_t sbase = smem_u32(sm);
    const int tid = threadIdx.x;
    const int wid = tid >> 5, lane = tid & 31;
    const int wm = wid >> 2, wn = wid & 3;
    const int row0 = blockIdx.y * 128;
    const int col0 = blockIdx.x * 128;

    const char* xhB = (const char*)g_xh + (size_t)(blockIdx.y * 2) * 8192;
    const char* xlB = (const char*)g_xl + (size_t)(blockIdx.y * 2) * 8192;
    const char* whB = (const char*)g_wh + (size_t)(blockIdx.x * 2) * 8192;
    const char* wlB = (const char*)g_wl + (size_t)(blockIdx.x * 2) * 8192;

    auto issue = [&](int chk) {
        const uint32_t co = (uint32_t)chk * 8192;
#pragma unroll
        for (int k = 0; k < 2; k++) {
            uint32_t off = (uint32_t)(tid + k * 256) * 16;
            CP16(sbase + co + off,          xhB + co + off);
            CP16(sbase + 16384 + co + off,  xlB + co + off);
            CP16(sbase + 32768 + co + off,  whB + co + off);
            CP16(sbase + 49152 + co + off,  wlB + co + off);
        }
    };
    issue(0); CP_COMMIT();
    issue(1); CP_COMMIT();

    float acc[4][4][4];
#pragma unroll
    for (int mf = 0; mf < 4; mf++)
#pragma unroll
        for (int nf = 0; nf < 4; nf++)
#pragma unroll
            for (int r = 0; r < 4; r++) acc[mf][nf][r] = 0.f;

    const uint32_t a_row = (uint32_t)(wm * 64) + (lane & 15);
    const uint32_t a_kb  = ((lane >> 4) & 1) * 16;
    const uint32_t b_row = (uint32_t)(wn * 32) + ((lane >> 4) & 1) * 8 + (lane & 7);
    const uint32_t b_kb  = ((lane >> 3) & 1) * 16;

#pragma unroll
    for (int chk = 0; chk < 2; chk++) {
        if (chk == 0) CP_WAIT1(); else CP_WAIT0();
        __syncthreads();
        const uint32_t AH = sbase + (uint32_t)chk * 8192;
        const uint32_t AL = AH + 16384;
        const uint32_t BH = sbase + 32768 + (uint32_t)chk * 8192;
        const uint32_t BL = BH + 16384;
#pragma unroll
        for (int ks = 0; ks < 2; ks++) {
            const uint32_t kb0 = (uint32_t)ks * 32;
            uint32_t bh[4][2], bl[4][2];
#pragma unroll
            for (int p = 0; p < 2; p++) {
                uint32_t o = swz(b_row + p * 16, kb0 + b_kb);
                uint32_t t4[4];
                ldsm_x4(t4, BH + o);
                bh[2*p][0] = t4[0]; bh[2*p][1] = t4[1];
                bh[2*p+1][0] = t4[2]; bh[2*p+1][1] = t4[3];
                ldsm_x4(t4, BL + o);
                bl[2*p][0] = t4[0]; bl[2*p][1] = t4[1];
                bl[2*p+1][0] = t4[2]; bl[2*p+1][1] = t4[3];
            }
#pragma unroll
            for (int mf = 0; mf < 4; mf++) {
                uint32_t o = swz(a_row + mf * 16, kb0 + a_kb);
                uint32_t ah[4], al[4];
                ldsm_x4(ah, AH + o);
                ldsm_x4(al, AL + o);
#pragma unroll
                for (int nf = 0; nf < 4; nf++) {
                    mma_f16(acc[mf][nf], ah, bh[nf]);
                    mma_f16(acc[mf][nf], ah, bl[nf]);
                    mma_f16(acc[mf][nf], al, bh[nf]);
                }
            }
        }
    }

    // repack through SMEM
    __syncthreads();
    float* sacc = (float*)sm;   // [128][132]
    {
        const int rb = wm * 64 + (lane >> 2);
        const int cb = wn * 32 + (lane & 3) * 2;
#pragma unroll
        for (int mf = 0; mf < 4; mf++)
#pragma unroll
            for (int nf = 0; nf < 4; nf++)
#pragma unroll
                for (int rr = 0; rr < 2; rr++) {
                    int r = rb + mf * 16 + rr * 8;
                    int c = cb + nf * 8;
                    *(float2*)(sacc + r * 132 + c) =
                        make_float2(acc[mf][nf][rr*2+0], acc[mf][nf][rr*2+1]);
                }
    }
    __syncthreads();

    const int wsel = col0 >> 12;           // 0=Q 1=K 2=V
    const int dcol0 = col0 & 4095;
    const int r = tid >> 1;
    const int cH = (tid & 1) * 64;
    const int m = row0 + r;
    const int b = m >> 11, n = m & 2047;
    int nrow = n;
    if (wsel == 0) nrow = g_slot[b * NN + n];
    if (wsel != 0 || nrow >= 0) {
        const float* rowp = sacc + r * 132 + cH;
#pragma unroll
        for (int g = 0; g < 8; g++) {
            const int cg = cH + g * 8;
            const int col = dcol0 + cg;
            const int h = col >> 9, dd = col & 511;
            float4 e0 = *(const float4*)(rowp + g * 8);
            float4 e1 = *(const float4*)(rowp + g * 8 + 4);
            __half2 h0 = __floats2half2_rn(e0.x, e0.y);
            __half2 h1 = __floats2half2_rn(e0.z, e0.w);
            __half2 h2 = __floats2half2_rn(e1.x, e1.y);
            __half2 h3 = __floats2half2_rn(e1.z, e1.w);
            uint4 hv = make_uint4(*(uint32_t*)&h0, *(uint32_t*)&h1,
                                  *(uint32_t*)&h2, *(uint32_t*)&h3);
            size_t tb = (((size_t)(b*HH+h) * 16 + (nrow >> 7)) * 16 + (dd >> 5)) * 8192;
            uint32_t so = swz((uint32_t)(nrow & 127), (uint32_t)(dd & 31) * 2);
            if (wsel == 1) {
                *(uint4*)((char*)g_kh + tb + so) = hv;
            } else {
                float2 f0 = __half22float2(h0), f1 = __half22float2(h1);
                float2 f2 = __half22float2(h2), f3 = __half22float2(h3);
                __half2 l0 = __floats2half2_rn(e0.x - f0.x, e0.y - f0.y);
                __half2 l1 = __floats2half2_rn(e0.z - f1.x, e0.w - f1.y);
                __half2 l2 = __floats2half2_rn(e1.x - f2.x, e1.y - f2.y);
                __half2 l3 = __floats2half2_rn(e1.z - f3.x, e1.w - f3.y);
                uint4 lv = make_uint4(*(uint32_t*)&l0, *(uint32_t*)&l1,
                                      *(uint32_t*)&l2, *(uint32_t*)&l3);
                if (wsel == 0) {
                    *(uint4*)((char*)g_qh + tb + so) = hv;
                    *(uint4*)((char*)g_ql + tb + so) = lv;
                } else {
                    *(uint4*)((char*)g_vh + tb + so) = hv;
                    *(uint4*)((char*)g_vl + tb + so) = lv;
                }
            }
        }
    }
}

// ===========================================================================
// pvw_mma: P[z] = (Vh+Vl) @ Woh^T
// ===========================================================================
#define PVW_STAGE 20480u
#define PVW_SMEM (2 * 20480)

__global__ __launch_bounds__(256, 2) void pvw_mma()
{
    extern __shared__ char sm[];
    const uint32_t sbase = smem_u32(sm);
    const int tid = threadIdx.x;
    const int wid = tid >> 5, lane = tid & 31;
    const int wm = wid >> 1, wn = wid & 1;
    const int z = blockIdx.y, h = z & 7;
    const int nt = blockIdx.x;

    const char* vhB = (const char*)g_vh + (((size_t)z * 16 + nt) * 16) * 8192;
    const char* vlB = (const char*)g_vl + (((size_t)z * 16 + nt) * 16) * 8192;
    const char* woB = (const char*)g_wo + (size_t)(h * 16) * 4096;

    float acc[2][4][4];
#pragma unroll
    for (int mf = 0; mf < 2; mf++)
#pragma unroll
        for (int nf = 0; nf < 4; nf++)
#pragma unroll
            for (int r = 0; r < 4; r++) acc[mf][nf][r] = 0.f;

    auto issue = [&](int ch) {
        const uint32_t ss = sbase + (uint32_t)(ch & 1) * PVW_STAGE;
#pragma unroll
        for (int k = 0; k < 2; k++) {
            uint32_t off = (uint32_t)(tid + k * 256) * 16;
            CP16(ss + off,        vhB + (size_t)ch * 8192 + off);
            CP16(ss + 8192 + off, vlB + (size_t)ch * 8192 + off);
        }
        {
            uint32_t off = (uint32_t)tid * 16;
            CP16(ss + 16384 + off, woB + (size_t)ch * 4096 + off);
        }
    };

    issue(0); CP_COMMIT();

    const uint32_t a_row = (uint32_t)(wm * 32) + (lane & 15);
    const uint32_t a_kb  = ((lane >> 4) & 1) * 16;
    const uint32_t b_row = (uint32_t)(wn * 32) + ((lane >> 4) & 1) * 8 + (lane & 7);
    const uint32_t b_kb  = ((lane >> 3) & 1) * 16;

    for (int ch = 0; ch < 16; ++ch) {
        if (ch + 1 < 16) { issue(ch + 1); CP_COMMIT(); CP_WAIT1(); }
        else CP_WAIT0();
        __syncthreads();
        const uint32_t S = sbase + (uint32_t)(ch & 1) * PVW_STAGE;
        const uint32_t AH = S, AL = S + 8192, BH = S + 16384;
#pragma unroll
        for (int ks = 0; ks < 2; ks++) {
            const uint32_t kb0 = (uint32_t)ks * 32;
            uint32_t bh[4][2];
#pragma unroll
            for (int p = 0; p < 2; p++) {
                uint32_t o = swz(b_row + p * 16, kb0 + b_kb);
                uint32_t t4[4];
                ldsm_x4(t4, BH + o);
                bh[2*p][0] = t4[0]; bh[2*p][1] = t4[1];
                bh[2*p+1][0] = t4[2]; bh[2*p+1][1] = t4[3];
            }
#pragma unroll
            for (int mf = 0; mf < 2; mf++) {
                uint32_t o = swz(a_row + mf * 16, kb0 + a_kb);
                uint32_t ah[4], al[4];
                ldsm_x4(ah, AH + o);
                ldsm_x4(al, AL + o);
#pragma unroll
                for (int nf = 0; nf < 4; nf++) {
                    mma_f16(acc[mf][nf], ah, bh[nf]);
                    mma_f16(acc[mf][nf], al, bh[nf]);
                }
            }
        }
        __syncthreads();
    }

    const int r_lo = nt * 128 + wm * 32 + (lane >> 2);
    const int c_base = wn * 32 + (lane & 3) * 2;
    float* Pz = g_p + (size_t)z * NN * 64;
#pragma unroll
    for (int mf = 0; mf < 2; mf++) {
        int rg0 = r_lo + mf * 16;
#pragma unroll
        for (int nf = 0; nf < 4; nf++) {
            int cg = c_base + nf * 8;
            *(float2*)(Pz + (size_t)rg0 * 64 + cg)       = make_float2(acc[mf][nf][0], acc[mf][nf][1]);
            *(float2*)(Pz + (size_t)(rg0 + 8) * 64 + cg) = make_float2(acc[mf][nf][2], acc[mf][nf][3]);
        }
    }
}

// ===========================================================================
// psum: 2-phase parallel reduction
// ===========================================================================
__global__ __launch_bounds__(256) void psum_part_kernel()
{
    __shared__ float red[4][64];
    const int z = blockIdx.x, seg = blockIdx.y;
    const int d = threadIdx.x & 63, sub = threadIdx.x >> 6;
    const float* p = g_p + ((size_t)z * NN + seg * 256 + sub * 64) * 64 + d;
    float s = 0.f;
#pragma unroll 8
    for (int n = 0; n < 64; n++) s += p[(size_t)n * 64];
    red[sub][d] = s;
    __syncthreads();
    if (threadIdx.x < 64)
        g_psumP[z][seg][d] = red[0][d] + red[1][d] + red[2][d] + red[3][d];
}
__global__ __launch_bounds__(256) void psum_red_kernel()
{
    const int i = blockIdx.x * 256 + threadIdx.x;
    const int z = i >> 6, d = i & 63;
    float s = 0.f;
#pragma unroll
    for (int g = 0; g < 8; g++) s += g_psumP[z][g][d];
    g_psum[z * 64 + d] = s;
}

// ===========================================================================
// dots = scale*(Qh+Ql)@Kh^T (+col mask) on COMPACTED rows -> pre (row-scattered)
// Streaming stores (evict-first) keep K tiles / g_p resident in L2.
// ===========================================================================
#define DSTAGE 24576u
#define DOTS_SMEM (4 * 24576)

__global__ __launch_bounds__(256, 2) void dots_gemm(float* __restrict__ Out)
{
    extern __shared__ char sm[];
    __shared__ int cmask[128];
    const uint32_t sbase = smem_u32(sm);

    const int tid = threadIdx.x;
    const int wid = tid >> 5, lane = tid & 31;
    const int wm = wid >> 2, wn = wid & 3;
    const int z = blockIdx.z, b = z >> 3;
    const int row0 = blockIdx.y * 128, col0 = blockIdx.x * 128;

    const int cnt = g_validcnt[b];

    float acc[4][4][4];

    if (row0 < cnt) {
        if (tid < 128) cmask[tid] = g_mask[b * NN + col0 + tid];

        const char* qhB = (const char*)g_qh + (((size_t)z * 16 + blockIdx.y) * 16) * 8192;
        const char* qlB = (const char*)g_ql + (((size_t)z * 16 + blockIdx.y) * 16) * 8192;
        const char* khB = (const char*)g_kh + (((size_t)z * 16 + blockIdx.x) * 16) * 8192;

#pragma unroll
        for (int mf = 0; mf < 4; mf++)
#pragma unroll
            for (int nf = 0; nf < 4; nf++)
#pragma unroll
                for (int r = 0; r < 4; r++) acc[mf][nf][r] = 0.f;

        auto issue = [&](int ch) {
            const uint32_t ss = sbase + (uint32_t)(ch & 3) * DSTAGE;
            const char* q1 = qhB + (size_t)ch * 8192;
            const char* l1 = qlB + (size_t)ch * 8192;
            const char* k1 = khB + (size_t)ch * 8192;
#pragma unroll
            for (int k = 0; k < 2; k++) {
                uint32_t off = (uint32_t)(tid + k * 256) * 16;
                CP16(ss + off,         q1 + off);
                CP16(ss + 8192 + off,  l1 + off);
                CP16(ss + 16384 + off, k1 + off);
            }
        };

        issue(0); CP_COMMIT();
        issue(1); CP_COMMIT();
        issue(2); CP_COMMIT();

        const uint32_t a_row = (uint32_t)(wm * 64) + (lane & 15);
        const uint32_t a_kb  = ((lane >> 4) & 1) * 16;
        const uint32_t b_row = (uint32_t)(wn * 32) + ((lane >> 4) & 1) * 8 + (lane & 7);
        const uint32_t b_kb  = ((lane >> 3) & 1) * 16;

        for (int ch = 0; ch < 16; ++ch) {
            CP_WAIT2();
            __syncthreads();
            const uint32_t S = sbase + (uint32_t)(ch & 3) * DSTAGE;
            const uint32_t AH = S, AL = S + 8192, BH = S + 16384;
#pragma unroll
            for (int ks = 0; ks < 2; ks++) {
                const uint32_t kb0 = (uint32_t)ks * 32;
                uint32_t bh[4][2];
#pragma unroll
                for (int p = 0; p < 2; p++) {
                    uint32_t o = swz(b_row + p * 16, kb0 + b_kb);
                    uint32_t t4[4];
                    ldsm_x4(t4, BH + o);
                    bh[2*p][0] = t4[0]; bh[2*p][1] = t4[1];
                    bh[2*p+1][0] = t4[2]; bh[2*p+1][1] = t4[3];
                }
#pragma unroll
                for (int mf = 0; mf < 4; mf++) {
                    uint32_t o = swz(a_row + mf * 16, kb0 + a_kb);
                    uint32_t ah[4], al[4];
                    ldsm_x4(ah, AH + o);
                    ldsm_x4(al, AL + o);
#pragma unroll
                    for (int nf = 0; nf < 4; nf++) {
                        mma_f16(acc[mf][nf], ah, bh[nf]);
                        mma_f16(acc[mf][nf], al, bh[nf]);
                    }
                }
            }
            if (ch + 3 < 16) issue(ch + 3);
            CP_COMMIT();
        }
    }

    // epilogue: valid rows -> scaled/masked result; rows >= cnt -> MASKV fill
    const int r_lo = row0 + wm * 64 + (lane >> 2);
    const int c_base = wn * 32 + (lane & 3) * 2;
    float* outz = Out + (size_t)z * NN * NN;
#pragma unroll
    for (int mf = 0; mf < 4; mf++) {
#pragma unroll
        for (int rr = 0; rr < 2; rr++) {
            const int cr = r_lo + mf * 16 + rr * 8;
            if (cr < cnt) {
                const int orig = g_rowmap[b][cr];
                float* rowp = outz + (size_t)orig * NN + col0;
#pragma unroll
                for (int nf = 0; nf < 4; nf++) {
                    int cg = c_base + nf * 8;
                    float2 v;
                    v.x = cmask[cg]     ? acc[mf][nf][rr*2+0] * SCALE : MASKV;
                    v.y = cmask[cg + 1] ? acc[mf][nf][rr*2+1] * SCALE : MASKV;
                    __stcs((float2*)(rowp + cg), v);
                }
            } else {
                const int orig = g_maskedmap[b][cr - cnt];
                float* rowp = outz + (size_t)orig * NN + col0;
                const float2 mv = make_float2(MASKV, MASKV);
#pragma unroll
                for (int nf = 0; nf < 4; nf++)
                    __stcs((float2*)(rowp + c_base + nf * 8), mv);
            }
        }
    }
}

// ===========================================================================
// entmax-1.5: streaming loads/stores; Newton with uniform early-exit
// ===========================================================================
__global__ __launch_bounds__(256) void entmax_kernel(
    const float* __restrict__ pre, float* __restrict__ att)
{
    const int wid = threadIdx.x >> 5, lane = threadIdx.x & 31;
    const size_t row = (size_t)blockIdx.x * 8 + wid;
    const int z = (int)(row >> 11), n = (int)(row & 2047), b = z >> 3;
    float4* o4 = (float4*)(att + row * NN);

    if (!g_mask[b * NN + n]) {
        const float P = 1.0f / 2048.0f;
        float4 u = make_float4(P, P, P, P);
#pragma unroll
        for (int i = 0; i < 16; i++) __stcs(&o4[lane + i * 32], u);
        if (lane == 0) g_cnt[row] = -1;
        return;
    }

    const float4* p4 = (const float4*)(pre + row * NN);
    float x[64];
    float mx = -3.0e38f;
#pragma unroll
    for (int i = 0; i < 16; i++) {
        float4 v = __ldcs(&p4[lane + i * 32]);
        x[4*i+0] = 0.5f * v.x; x[4*i+1] = 0.5f * v.y;
        x[4*i+2] = 0.5f * v.z; x[4*i+3] = 0.5f * v.w;
        mx = fmaxf(mx, fmaxf(fmaxf(x[4*i], x[4*i+1]), fmaxf(x[4*i+2], x[4*i+3])));
    }
#pragma unroll
    for (int off = 16; off; off >>= 1)
        mx = fmaxf(mx, __shfl_xor_sync(0xffffffffu, mx, off));
#pragma unroll
    for (int j = 0; j < 64; j++) x[j] -= mx;

    float tau = -1.0f;
#pragma unroll 1
    for (int it = 0; it < 12; ++it) {
        float s1 = 0.f, s2 = 0.f;
#pragma unroll
        for (int j = 0; j < 64; j++) {
            float d = fmaxf(x[j] - tau, 0.f);
            s1 += d;
            s2 = fmaf(d, d, s2);
        }
#pragma unroll
        for (int off = 16; off; off >>= 1) {
            s1 += __shfl_xor_sync(0xffffffffu, s1, off);
            s2 += __shfl_xor_sync(0xffffffffu, s2, off);
        }
        float step = (s1 > 1e-20f) ? (s2 - 1.0f) / (2.0f * s1) : 0.f;
        tau += step;
        if (fabsf(step) < 1e-6f) break;
    }

#pragma unroll
    for (int i = 0; i < 16; i++) {
        float4 w;
        float d;
        d = fmaxf(x[4*i+0] - tau, 0.f); w.x = d * d;
        d = fmaxf(x[4*i+1] - tau, 0.f); w.y = d * d;
        d = fmaxf(x[4*i+2] - tau, 0.f); w.z = d * d;
        d = fmaxf(x[4*i+3] - tau, 0.f); w.w = d * d;
        __stcs(&o4[lane + i * 32], w);
    }

    int cl = 0;
#pragma unroll
    for (int j = 0; j < 64; j++) cl += (x[j] > tau) ? 1 : 0;
    int v = cl;
#pragma unroll
    for (int d = 1; d < 32; d <<= 1) {
        int t = __shfl_up_sync(0xffffffffu, v, d);
        if (lane >= d) v += t;
    }
    int total = __shfl_sync(0xffffffffu, v, 31);
    int pos = v - cl;
    if (total <= MAXS) {
        int*   si = g_si + row * MAXS;
        float* sw = g_sw + row * MAXS;
#pragma unroll
        for (int i = 0; i < 16; i++)
#pragma unroll
            for (int c = 0; c < 4; c++) {
                int j = 4*i + c;
                if (x[j] > tau) {
                    float d = x[j] - tau;
                    si[pos] = 4*lane + 128*i + c;
                    sw[pos] = d * d;
                    pos++;
                }
            }
        if (lane == 31) g_cnt[row] = total;
    } else if (lane == 31) {
        g_cnt[row] = -2;
    }
}

// ===========================================================================
// Fused sparse attention-out
// ===========================================================================
__global__ __launch_bounds__(256) void af_kernel(
    const float* __restrict__ att, const float* __restrict__ bo, float* __restrict__ out)
{
    const int wid = threadIdx.x >> 5, lane = threadIdx.x & 31;
    const int gw = blockIdx.x * 8 + wid;
    const int b = gw >> 11, n = gw & 2047;
    const int dc = lane * 2;

    float2 acc;
    float2 bb = *(const float2*)(bo + dc);
    acc.x = bb.x; acc.y = bb.y;

#pragma unroll 1
    for (int h = 0; h < HH; h++) {
        const int z = b * HH + h;
        const size_t row = (size_t)z * NN + n;
        const int cnt = g_cnt[row];
        const float* Pz = g_p + (size_t)z * NN * 64;
        if (cnt == -1) {
            const float Pu = 1.0f / 2048.0f;
            float2 s = *(const float2*)(g_psum + z * 64 + dc);
            acc.x = fmaf(Pu, s.x, acc.x);
            acc.y = fmaf(Pu, s.y, acc.y);
        } else if (cnt >= 0) {
            const int*   si = g_si + row * MAXS;
            const float* sw = g_sw + row * MAXS;
            for (int j = 0; j < cnt; j++) {
                int   i0 = si[j];
                float w0 = sw[j];
                float2 v = *(const float2*)(Pz + (size_t)i0 * 64 + dc);
                acc.x = fmaf(w0, v.x, acc.x);
                acc.y = fmaf(w0, v.y, acc.y);
            }
        } else {
            const float* arow = att + row * NN;
            for (int c = 0; c < NN; c++) {
                float p = __ldcs(arow + c);
                if (p != 0.f) {
                    float2 v = *(const float2*)(Pz + (size_t)c * 64 + dc);
                    acc.x = fmaf(p, v.x, acc.x);
                    acc.y = fmaf(p, v.y, acc.y);
                }
            }
        }
    }
    *(float2*)(out + (size_t)gw * 64 + dc) = acc;
}

// ===========================================================================
extern "C" void kernel_launch(void* const* d_in, const int* in_sizes, int n_in,
                              void* d_out, int out_size)
{
    const float* x   = (const float*)d_in[0];
    const unsigned char* mask_raw = (const unsigned char*)d_in[1];
    const float* Wq  = (const float*)d_in[2];
    const float* Wk  = (const float*)d_in[3];
    const float* Wv  = (const float*)d_in[4];
    const float* Wo  = (const float*)d_in[5];
    const float* bo  = (const float*)d_in[6];

    float* out = (float*)d_out;
    float* pre = out + OUT_ELEMS;
    float* att = pre + PRE_ELEMS;

    static int smem_set = 0;
    if (!smem_set) {
        cudaFuncSetAttribute(dots_gemm,
                             cudaFuncAttributeMaxDynamicSharedMemorySize, DOTS_SMEM);
        cudaFuncSetAttribute(proj_mma,
                             cudaFuncAttributeMaxDynamicSharedMemorySize, PROJ_SMEM);
        cudaFuncSetAttribute(pvw_mma,
                             cudaFuncAttributeMaxDynamicSharedMemorySize, PVW_SMEM);
        smem_set = 1;
    }

    prep_compact_kernel<<<1, 256>>>(mask_raw);

    conv_all_kernel<<<1088, 256>>>(x, Wq, Wk, Wv, Wo);

    proj_mma<<<dim3(96, 32), 256, PROJ_SMEM>>>();

    pvw_mma<<<dim3(16, 16), 256, PVW_SMEM>>>();
    psum_part_kernel<<<dim3(16, 8), 256>>>();
    psum_red_kernel<<<4, 256>>>();

    dots_gemm<<<dim3(16, 16, 16), 256, DOTS_SMEM>>>(pre);

    entmax_kernel<<<BB * HH * NN / 8, 256>>>(pre, att);

    af_kernel<<<BB * NN / 8, 256>>>(att, bo, out);
}